// round 4
// baseline (speedup 1.0000x reference)
#include <cuda_runtime.h>
#include <math.h>

#define BB 4
#define TT 512
#define SS 1536           // S = 3*T
#define SDIM 64
#define ADIM 32
#define HDIM 512
#define NH 8
#define DH 64
#define NBLK 6
#define DFF 2048
#define MROWS (BB*SS)     // 6144

enum { EP_BIAS = 0, EP_BIAS_RES = 1, EP_BIAS_GELU = 2 };

// ---------------- scratch (static device globals; no runtime allocs) ----------
__device__ float g_h   [MROWS * HDIM];
__device__ float g_q   [MROWS * HDIM];
__device__ float g_k   [MROWS * HDIM];
__device__ float g_v   [MROWS * HDIM];
__device__ float g_ctx [MROWS * HDIM];
__device__ float g_xa  [MROWS * HDIM];
__device__ float g_ln1 [MROWS * HDIM];
__device__ float g_pre2[MROWS * HDIM];
__device__ float g_mlp [MROWS * DFF];
__device__ float g_sc  [(size_t)BB * NH * SS * SS];   // 302 MB scores

// ---------------- tf32 helpers ----------------
__device__ __forceinline__ unsigned f2tf(float x) {
    unsigned r; asm("cvt.rna.tf32.f32 %0, %1;" : "=r"(r) : "f"(x)); return r;
}
__device__ __forceinline__ uint2 split2(float x) {
    unsigned hi = f2tf(x);
    unsigned lo = f2tf(x - __uint_as_float(hi));
    return make_uint2(hi, lo);
}
__device__ __forceinline__ void mma8(float c[4],
    unsigned a0, unsigned a1, unsigned a2, unsigned a3,
    unsigned b0, unsigned b1)
{
    asm volatile(
      "mma.sync.aligned.m16n8k8.row.col.f32.tf32.tf32.f32 "
      "{%0,%1,%2,%3},{%4,%5,%6,%7},{%8,%9},{%0,%1,%2,%3};"
      : "+f"(c[0]), "+f"(c[1]), "+f"(c[2]), "+f"(c[3])
      : "r"(a0), "r"(a1), "r"(a2), "r"(a3), "r"(b0), "r"(b1));
}

// ---------------- reductions ----------------
__device__ __forceinline__ float blockReduceSum(float v, float* sm) {
    int lane = threadIdx.x & 31, wid = threadIdx.x >> 5;
    #pragma unroll
    for (int o = 16; o; o >>= 1) v += __shfl_down_sync(0xffffffffu, v, o);
    if (lane == 0) sm[wid] = v;
    __syncthreads();
    float r = 0.f;
    if (wid == 0) {
        r = (lane < 8) ? sm[lane] : 0.f;
        #pragma unroll
        for (int o = 4; o; o >>= 1) r += __shfl_down_sync(0xffffffffu, r, o);
        if (lane == 0) sm[0] = r;
    }
    __syncthreads();
    r = sm[0];
    __syncthreads();
    return r;
}

__device__ __forceinline__ float blockReduceMax(float v, float* sm) {
    int lane = threadIdx.x & 31, wid = threadIdx.x >> 5;
    #pragma unroll
    for (int o = 16; o; o >>= 1) v = fmaxf(v, __shfl_down_sync(0xffffffffu, v, o));
    if (lane == 0) sm[wid] = v;
    __syncthreads();
    float r = -1e30f;
    if (wid == 0) {
        r = (lane < 8) ? sm[lane] : -1e30f;
        #pragma unroll
        for (int o = 4; o; o >>= 1) r = fmaxf(r, __shfl_down_sync(0xffffffffu, r, o));
        if (lane == 0) sm[0] = r;
    }
    __syncthreads();
    r = sm[0];
    __syncthreads();
    return r;
}

// ---------------- embedding + eLN (one block per sequence row) ----------------
__global__ __launch_bounds__(256) void embed_kernel(
    const int* __restrict__ timesteps, const float* __restrict__ s0,
    const float* __restrict__ s1, const float* __restrict__ act,
    const float* __restrict__ temb,
    const float* __restrict__ Ws, const float* __restrict__ bs,
    const float* __restrict__ Wa, const float* __restrict__ ba,
    const float* __restrict__ eg, const float* __restrict__ eb,
    float* __restrict__ out)
{
    int s = blockIdx.x;
    int b = s / SS, sr = s % SS;
    int t = sr / 3, r = sr % 3;

    __shared__ float sIn[SDIM];
    __shared__ float red[32];

    const float* inp; const float* W; const float* bias; int Kin;
    if (r == 0)      { inp = s0  + (size_t)(b*TT + t)*SDIM; W = Ws; bias = bs; Kin = SDIM; }
    else if (r == 1) { inp = s1  + (size_t)(b*TT + t)*SDIM; W = Ws; bias = bs; Kin = SDIM; }
    else             { inp = act + (size_t)(b*TT + t)*ADIM; W = Wa; bias = ba; Kin = ADIM; }

    int tid = threadIdx.x;
    if (tid < Kin) sIn[tid] = inp[tid];
    __syncthreads();

    int tsv = timesteps[b*TT + t];
    const float* te = temb + (size_t)tsv * HDIM;

    float v0, v1;
    {
        int c = tid;
        float a = bias[c] + te[c];
        for (int k = 0; k < Kin; k++) a = fmaf(sIn[k], W[(size_t)k*HDIM + c], a);
        v0 = a;
        c = tid + 256;
        a = bias[c] + te[c];
        for (int k = 0; k < Kin; k++) a = fmaf(sIn[k], W[(size_t)k*HDIM + c], a);
        v1 = a;
    }
    float sum = blockReduceSum(v0 + v1, red);
    float m = sum * (1.0f / HDIM);
    float d0 = v0 - m, d1 = v1 - m;
    float ssq = blockReduceSum(d0*d0 + d1*d1, red);
    float rstd = rsqrtf(ssq * (1.0f / HDIM) + 1e-5f);
    out[(size_t)s*HDIM + tid      ] = d0 * rstd * eg[tid]       + eb[tid];
    out[(size_t)s*HDIM + tid + 256] = d1 * rstd * eg[tid + 256] + eb[tid + 256];
}

// ============ tensor-core GEMM: C[M,N] = A[M,K] @ B[K,N] (3xTF32) ==============
// 256 threads, tile 128xBN, BK=16. Warp grid 2(m) x 4(n). Register-staged
// prefetch pipelines global loads of tile t+1 behind the mma of tile t.
template<int BN>
__device__ __forceinline__ void tgemm_body(
    const float* __restrict__ A, const float* __restrict__ B,
    const float* __restrict__ bias, const float* __restrict__ res,
    float* __restrict__ C, int M, int N, int K, int ep)
{
    constexpr int TNF = BN / 32;          // n-fragments per warp (8 wide each)
    __shared__ uint2 As2[16][136];
    __shared__ uint2 Bs2[16][BN + 8];
    const int tid  = threadIdx.x, lane = tid & 31, warp = tid >> 5;
    const int g    = lane >> 2,  tg   = lane & 3;
    const int wm0  = (warp >> 2) * 64, wn0 = (warp & 3) * (BN / 4);
    const int m0   = blockIdx.y * 128, n0 = blockIdx.x * BN;
    const int ar   = tid >> 2,  ac = (tid & 3) * 4;
    // B loaders
    const int br1  = tid >> 5,  bc1 = (tid & 31) * 4;   // BN=128: rows br1, br1+8
    const int br2  = tid >> 4,  bc2 = (tid & 15) * 4;   // BN=64 : single row

    float acc[4][TNF][4];
    #pragma unroll
    for (int i = 0; i < 4; i++)
        #pragma unroll
        for (int j = 0; j < TNF; j++)
            #pragma unroll
            for (int l = 0; l < 4; l++) acc[i][j][l] = 0.f;

    // prologue: stage k-tile 0
    float4 a0r = *(const float4*)(A + (size_t)(m0 + ar)*K      + ac);
    float4 a1r = *(const float4*)(A + (size_t)(m0 + ar + 64)*K + ac);
    float4 b0r, b1r;
    if (BN == 128) {
        b0r = *(const float4*)(B + (size_t)br1*N       + n0 + bc1);
        b1r = *(const float4*)(B + (size_t)(br1 + 8)*N + n0 + bc1);
    } else {
        b0r = *(const float4*)(B + (size_t)br2*N + n0 + bc2);
    }

    for (int k0 = 0; k0 < K; k0 += 16) {
        // commit staged registers to smem (split hi/lo once)
        As2[ac+0][ar] = split2(a0r.x); As2[ac+1][ar] = split2(a0r.y);
        As2[ac+2][ar] = split2(a0r.z); As2[ac+3][ar] = split2(a0r.w);
        As2[ac+0][ar+64] = split2(a1r.x); As2[ac+1][ar+64] = split2(a1r.y);
        As2[ac+2][ar+64] = split2(a1r.z); As2[ac+3][ar+64] = split2(a1r.w);
        if (BN == 128) {
            Bs2[br1][bc1+0] = split2(b0r.x); Bs2[br1][bc1+1] = split2(b0r.y);
            Bs2[br1][bc1+2] = split2(b0r.z); Bs2[br1][bc1+3] = split2(b0r.w);
            Bs2[br1+8][bc1+0] = split2(b1r.x); Bs2[br1+8][bc1+1] = split2(b1r.y);
            Bs2[br1+8][bc1+2] = split2(b1r.z); Bs2[br1+8][bc1+3] = split2(b1r.w);
        } else {
            Bs2[br2][bc2+0] = split2(b0r.x); Bs2[br2][bc2+1] = split2(b0r.y);
            Bs2[br2][bc2+2] = split2(b0r.z); Bs2[br2][bc2+3] = split2(b0r.w);
        }
        __syncthreads();

        // prefetch k-tile t+1 (latency hidden by the mma below)
        if (k0 + 16 < K) {
            a0r = *(const float4*)(A + (size_t)(m0 + ar)*K      + k0 + 16 + ac);
            a1r = *(const float4*)(A + (size_t)(m0 + ar + 64)*K + k0 + 16 + ac);
            if (BN == 128) {
                b0r = *(const float4*)(B + (size_t)(k0 + 16 + br1)*N     + n0 + bc1);
                b1r = *(const float4*)(B + (size_t)(k0 + 16 + br1 + 8)*N + n0 + bc1);
            } else {
                b0r = *(const float4*)(B + (size_t)(k0 + 16 + br2)*N + n0 + bc2);
            }
        }

        #pragma unroll
        for (int ks = 0; ks < 16; ks += 8) {
            uint2 bf[TNF][2];
            #pragma unroll
            for (int tn = 0; tn < TNF; tn++) {
                int n = wn0 + tn*8 + g;
                bf[tn][0] = Bs2[ks+tg][n];
                bf[tn][1] = Bs2[ks+tg+4][n];
            }
            #pragma unroll
            for (int tm = 0; tm < 4; tm++) {
                int m = wm0 + tm*16 + g;
                uint2 a0 = As2[ks+tg][m],   a1 = As2[ks+tg][m+8];
                uint2 a2 = As2[ks+tg+4][m], a3 = As2[ks+tg+4][m+8];
                #pragma unroll
                for (int tn = 0; tn < TNF; tn++) {
                    mma8(acc[tm][tn], a0.x,a1.x,a2.x,a3.x, bf[tn][0].x, bf[tn][1].x);
                    mma8(acc[tm][tn], a0.y,a1.y,a2.y,a3.y, bf[tn][0].x, bf[tn][1].x);
                    mma8(acc[tm][tn], a0.x,a1.x,a2.x,a3.x, bf[tn][0].y, bf[tn][1].y);
                }
            }
        }
        __syncthreads();
    }

    #pragma unroll
    for (int tm = 0; tm < 4; tm++) {
        #pragma unroll
        for (int tn = 0; tn < TNF; tn++) {
            int row = m0 + wm0 + tm*16 + g;
            int col = n0 + wn0 + tn*8 + tg*2;
            float b0v = bias[col], b1v = bias[col+1];
            float v00 = acc[tm][tn][0] + b0v, v01 = acc[tm][tn][1] + b1v;
            float v10 = acc[tm][tn][2] + b0v, v11 = acc[tm][tn][3] + b1v;
            if (ep == EP_BIAS_RES) {
                v00 += res[(size_t)row*N + col];     v01 += res[(size_t)row*N + col + 1];
                v10 += res[(size_t)(row+8)*N + col]; v11 += res[(size_t)(row+8)*N + col + 1];
            } else if (ep == EP_BIAS_GELU) {
                v00 = 0.5f*v00*(1.0f + erff(v00*0.70710678118654752f));
                v01 = 0.5f*v01*(1.0f + erff(v01*0.70710678118654752f));
                v10 = 0.5f*v10*(1.0f + erff(v10*0.70710678118654752f));
                v11 = 0.5f*v11*(1.0f + erff(v11*0.70710678118654752f));
            }
            *(float2*)(C + (size_t)row*N + col)     = make_float2(v00, v01);
            *(float2*)(C + (size_t)(row+8)*N + col) = make_float2(v10, v11);
        }
    }
}

template<int BN>
__global__ __launch_bounds__(256) void tgemm_kernel(
    const float* __restrict__ A, const float* __restrict__ B,
    const float* __restrict__ bias, const float* __restrict__ res,
    float* __restrict__ C, int M, int N, int K, int ep)
{
    tgemm_body<BN>(A, B, bias, res, C, M, N, K, ep);
}

// fused QKV: blockIdx.z selects the projection
__global__ __launch_bounds__(256) void qkv_kernel(
    const float* __restrict__ h,
    const float* __restrict__ Wq, const float* __restrict__ Wk, const float* __restrict__ Wv,
    const float* __restrict__ bq, const float* __restrict__ bk, const float* __restrict__ bv,
    float* __restrict__ q, float* __restrict__ k, float* __restrict__ v)
{
    const float* W; const float* bias; float* out;
    if      (blockIdx.z == 0) { W = Wq; bias = bq; out = q; }
    else if (blockIdx.z == 1) { W = Wk; bias = bk; out = k; }
    else                      { W = Wv; bias = bv; out = v; }
    tgemm_body<128>(h, W, bias, nullptr, out, MROWS, HDIM, HDIM, EP_BIAS);
}

// ---------- scores = Q @ K^T (NT), lower-triangle 128x128 tiles, 3xTF32 -------
__global__ __launch_bounds__(256) void tscores_kernel(
    const float* __restrict__ q, const float* __restrict__ k, float* __restrict__ sc)
{
    int jt = blockIdx.x, it = blockIdx.y;
    if (jt > it) return;
    int bh = blockIdx.z, b = bh >> 3, h = bh & 7;
    const float* qb = q + (size_t)b*SS*HDIM + h*DH;
    const float* kb = k + (size_t)b*SS*HDIM + h*DH;
    float* cb = sc + (size_t)bh * SS * SS;
    int i0 = it * 128, j0 = jt * 128;

    __shared__ uint2 Qs2[16][136];
    __shared__ uint2 Ks2[128][20];
    const int tid  = threadIdx.x, lane = tid & 31, warp = tid >> 5;
    const int g    = lane >> 2,  tg   = lane & 3;
    const int wm0  = (warp >> 2) * 64, wn0 = (warp & 3) * 32;
    const int ar   = tid >> 2,  ac = (tid & 3) * 4;

    float acc[4][4][4];
    #pragma unroll
    for (int i = 0; i < 4; i++)
        #pragma unroll
        for (int j = 0; j < 4; j++)
            #pragma unroll
            for (int l = 0; l < 4; l++) acc[i][j][l] = 0.f;

    float4 q0r = *(const float4*)(qb + (size_t)(i0 + ar)*HDIM      + ac);
    float4 q1r = *(const float4*)(qb + (size_t)(i0 + ar + 64)*HDIM + ac);
    float4 k0r = *(const float4*)(kb + (size_t)(j0 + ar)*HDIM      + ac);
    float4 k1r = *(const float4*)(kb + (size_t)(j0 + ar + 64)*HDIM + ac);

    for (int k0 = 0; k0 < DH; k0 += 16) {
        Qs2[ac+0][ar] = split2(q0r.x); Qs2[ac+1][ar] = split2(q0r.y);
        Qs2[ac+2][ar] = split2(q0r.z); Qs2[ac+3][ar] = split2(q0r.w);
        Qs2[ac+0][ar+64] = split2(q1r.x); Qs2[ac+1][ar+64] = split2(q1r.y);
        Qs2[ac+2][ar+64] = split2(q1r.z); Qs2[ac+3][ar+64] = split2(q1r.w);
        Ks2[ar][ac+0] = split2(k0r.x); Ks2[ar][ac+1] = split2(k0r.y);
        Ks2[ar][ac+2] = split2(k0r.z); Ks2[ar][ac+3] = split2(k0r.w);
        Ks2[ar+64][ac+0] = split2(k1r.x); Ks2[ar+64][ac+1] = split2(k1r.y);
        Ks2[ar+64][ac+2] = split2(k1r.z); Ks2[ar+64][ac+3] = split2(k1r.w);
        __syncthreads();

        if (k0 + 16 < DH) {
            q0r = *(const float4*)(qb + (size_t)(i0 + ar)*HDIM      + k0 + 16 + ac);
            q1r = *(const float4*)(qb + (size_t)(i0 + ar + 64)*HDIM + k0 + 16 + ac);
            k0r = *(const float4*)(kb + (size_t)(j0 + ar)*HDIM      + k0 + 16 + ac);
            k1r = *(const float4*)(kb + (size_t)(j0 + ar + 64)*HDIM + k0 + 16 + ac);
        }

        #pragma unroll
        for (int ks = 0; ks < 16; ks += 8) {
            uint2 bf[4][2];
            #pragma unroll
            for (int tn = 0; tn < 4; tn++) {
                int n = wn0 + tn*8 + g;
                bf[tn][0] = Ks2[n][ks+tg];
                bf[tn][1] = Ks2[n][ks+tg+4];
            }
            #pragma unroll
            for (int tm = 0; tm < 4; tm++) {
                int m = wm0 + tm*16 + g;
                uint2 a0 = Qs2[ks+tg][m],   a1 = Qs2[ks+tg][m+8];
                uint2 a2 = Qs2[ks+tg+4][m], a3 = Qs2[ks+tg+4][m+8];
                #pragma unroll
                for (int tn = 0; tn < 4; tn++) {
                    mma8(acc[tm][tn], a0.x,a1.x,a2.x,a3.x, bf[tn][0].x, bf[tn][1].x);
                    mma8(acc[tm][tn], a0.y,a1.y,a2.y,a3.y, bf[tn][0].x, bf[tn][1].x);
                    mma8(acc[tm][tn], a0.x,a1.x,a2.x,a3.x, bf[tn][0].y, bf[tn][1].y);
                }
            }
        }
        __syncthreads();
    }
    const float scale = 0.125f;
    #pragma unroll
    for (int tm = 0; tm < 4; tm++)
        #pragma unroll
        for (int tn = 0; tn < 4; tn++) {
            int row = i0 + wm0 + tm*16 + g;
            int col = j0 + wn0 + tn*8 + tg*2;
            *(float2*)(cb + (size_t)row*SS + col) =
                make_float2(acc[tm][tn][0]*scale, acc[tm][tn][1]*scale);
            *(float2*)(cb + (size_t)(row+8)*SS + col) =
                make_float2(acc[tm][tn][2]*scale, acc[tm][tn][3]*scale);
        }
}

// ------------- causal row softmax, vectorized single read/write ---------------
__global__ __launch_bounds__(256) void softmax_kernel(float* __restrict__ sc)
{
    size_t rid = blockIdx.x;            // bh*S + i
    int i = (int)(rid % SS);
    float* row = sc + rid * (size_t)SS;
    int n = i + 1;
    int nf = (n + 3) >> 2;              // float4 count covering valid region
    int endf = (((i >> 7) + 1) << 7) >> 2;  // 128-tile boundary in float4 units
    __shared__ float red[32];
    int tid = threadIdx.x;

    float4 vals[2];
    int cnt = 0;
    float mx = -1e30f;
    for (int f = tid; f < nf; f += 256) {
        float4 x = *(const float4*)(row + 4*(size_t)f);
        int b4 = 4*f;
        if (b4 + 1 >= n) x.y = -1e30f;
        if (b4 + 2 >= n) x.z = -1e30f;
        if (b4 + 3 >= n) x.w = -1e30f;
        vals[cnt++] = x;
        mx = fmaxf(fmaxf(mx, fmaxf(x.x, x.y)), fmaxf(x.z, x.w));
    }
    mx = blockReduceMax(mx, red);

    float sum = 0.f;
    #pragma unroll
    for (int l = 0; l < 2; l++)
        if (l < cnt) {
            float4& x = vals[l];
            x.x = __expf(x.x - mx); x.y = __expf(x.y - mx);
            x.z = __expf(x.z - mx); x.w = __expf(x.w - mx);
            sum += (x.x + x.y) + (x.z + x.w);
        }
    sum = blockReduceSum(sum, red);
    float inv = 1.0f / sum;

    cnt = 0;
    for (int f = tid; f < nf; f += 256) {
        float4 x = vals[cnt++];
        x.x *= inv; x.y *= inv; x.z *= inv; x.w *= inv;
        *(float4*)(row + 4*(size_t)f) = x;
    }
    for (int f = nf + tid; f < endf; f += 256)
        *(float4*)(row + 4*(size_t)f) = make_float4(0.f, 0.f, 0.f, 0.f);
}

// ---- ctx = attn @ V (NN), tile 128x64, causal K-limit, pipelined 3xTF32 ------
__global__ __launch_bounds__(256) void tctx_kernel(
    const float* __restrict__ at, const float* __restrict__ v, float* __restrict__ ctx)
{
    int it = blockIdx.x, bh = blockIdx.y, b = bh >> 3, h = bh & 7;
    const float* ab = at + (size_t)bh * SS * SS;
    const float* vb = v   + (size_t)b*SS*HDIM + h*DH;
    float* cb       = ctx + (size_t)b*SS*HDIM + h*DH;
    int i0 = it * 128;
    int kmax = (it + 1) * 128;

    __shared__ uint2 As2[16][136];
    __shared__ uint2 Bs2[16][72];
    const int tid  = threadIdx.x, lane = tid & 31, warp = tid >> 5;
    const int g    = lane >> 2,  tg   = lane & 3;
    const int wm0  = (warp >> 2) * 64, wn0 = (warp & 3) * 16;
    const int ar   = tid >> 2,  ac = (tid & 3) * 4;
    const int brr  = tid >> 4,  bcc = (tid & 15) * 4;

    float acc[4][2][4];
    #pragma unroll
    for (int i = 0; i < 4; i++)
        #pragma unroll
        for (int j = 0; j < 2; j++)
            #pragma unroll
            for (int l = 0; l < 4; l++) acc[i][j][l] = 0.f;

    float4 a0r = *(const float4*)(ab + (size_t)(i0 + ar)*SS      + ac);
    float4 a1r = *(const float4*)(ab + (size_t)(i0 + ar + 64)*SS + ac);
    float4 b0r = *(const float4*)(vb + (size_t)brr*HDIM + bcc);

    for (int k0 = 0; k0 < kmax; k0 += 16) {
        As2[ac+0][ar] = split2(a0r.x); As2[ac+1][ar] = split2(a0r.y);
        As2[ac+2][ar] = split2(a0r.z); As2[ac+3][ar] = split2(a0r.w);
        As2[ac+0][ar+64] = split2(a1r.x); As2[ac+1][ar+64] = split2(a1r.y);
        As2[ac+2][ar+64] = split2(a1r.z); As2[ac+3][ar+64] = split2(a1r.w);
        Bs2[brr][bcc+0] = split2(b0r.x); Bs2[brr][bcc+1] = split2(b0r.y);
        Bs2[brr][bcc+2] = split2(b0r.z); Bs2[brr][bcc+3] = split2(b0r.w);
        __syncthreads();

        if (k0 + 16 < kmax) {
            a0r = *(const float4*)(ab + (size_t)(i0 + ar)*SS      + k0 + 16 + ac);
            a1r = *(const float4*)(ab + (size_t)(i0 + ar + 64)*SS + k0 + 16 + ac);
            b0r = *(const float4*)(vb + (size_t)(k0 + 16 + brr)*HDIM + bcc);
        }

        #pragma unroll
        for (int ks = 0; ks < 16; ks += 8) {
            uint2 bf[2][2];
            #pragma unroll
            for (int tn = 0; tn < 2; tn++) {
                int n = wn0 + tn*8 + g;
                bf[tn][0] = Bs2[ks+tg][n];
                bf[tn][1] = Bs2[ks+tg+4][n];
            }
            #pragma unroll
            for (int tm = 0; tm < 4; tm++) {
                int m = wm0 + tm*16 + g;
                uint2 a0 = As2[ks+tg][m],   a1 = As2[ks+tg][m+8];
                uint2 a2 = As2[ks+tg+4][m], a3 = As2[ks+tg+4][m+8];
                #pragma unroll
                for (int tn = 0; tn < 2; tn++) {
                    mma8(acc[tm][tn], a0.x,a1.x,a2.x,a3.x, bf[tn][0].x, bf[tn][1].x);
                    mma8(acc[tm][tn], a0.y,a1.y,a2.y,a3.y, bf[tn][0].x, bf[tn][1].x);
                    mma8(acc[tm][tn], a0.x,a1.x,a2.x,a3.x, bf[tn][0].y, bf[tn][1].y);
                }
            }
        }
        __syncthreads();
    }
    #pragma unroll
    for (int tm = 0; tm < 4; tm++)
        #pragma unroll
        for (int tn = 0; tn < 2; tn++) {
            int row = i0 + wm0 + tm*16 + g;
            int col = wn0 + tn*8 + tg*2;
            *(float2*)(cb + (size_t)row*HDIM + col) =
                make_float2(acc[tm][tn][0], acc[tm][tn][1]);
            *(float2*)(cb + (size_t)(row+8)*HDIM + col) =
                make_float2(acc[tm][tn][2], acc[tm][tn][3]);
        }
}

// ---------------- plain layernorm over HDIM ----------------
__global__ __launch_bounds__(256) void ln_kernel(
    const float* __restrict__ x, const float* __restrict__ g,
    const float* __restrict__ b, float* __restrict__ out)
{
    int row = blockIdx.x;
    __shared__ float red[32];
    int tid = threadIdx.x;
    float v0 = x[(size_t)row*HDIM + tid];
    float v1 = x[(size_t)row*HDIM + tid + 256];
    float sum = blockReduceSum(v0 + v1, red);
    float m = sum * (1.0f / HDIM);
    float d0 = v0 - m, d1 = v1 - m;
    float ssq = blockReduceSum(d0*d0 + d1*d1, red);
    float rstd = rsqrtf(ssq * (1.0f / HDIM) + 1e-5f);
    out[(size_t)row*HDIM + tid      ] = d0 * rstd * g[tid]       + b[tid];
    out[(size_t)row*HDIM + tid + 256] = d1 * rstd * g[tid + 256] + b[tid + 256];
}

// ---------------- final projection: out = h[:, :, 1] @ Wp + bp ----------------
__global__ __launch_bounds__(256) void final_kernel(
    const float* __restrict__ h, const float* __restrict__ Wp,
    const float* __restrict__ bp, float* __restrict__ out)
{
    int bt = blockIdx.x;                 // b*T + t
    int b = bt / TT, t = bt % TT;
    const float* row = h + ((size_t)b*SS + 3*t + 1) * HDIM;
    __shared__ float sRow[HDIM];
    __shared__ float part[8][ADIM];
    int tid = threadIdx.x;
    sRow[tid] = row[tid];
    sRow[tid + 256] = row[tid + 256];
    __syncthreads();
    int c = tid & 31, g = tid >> 5;
    float a = 0.f;
    for (int k = g*64; k < (g+1)*64; k++) a = fmaf(sRow[k], Wp[(size_t)k*ADIM + c], a);
    part[g][c] = a;
    __syncthreads();
    if (tid < ADIM) {
        float s = bp[tid];
        #pragma unroll
        for (int g2 = 0; g2 < 8; g2++) s += part[g2][tid];
        out[(size_t)bt*ADIM + tid] = s;
    }
}

// ---------------- driver ----------------
extern "C" void kernel_launch(void* const* d_in, const int* in_sizes, int n_in,
                              void* d_out, int out_size)
{
    const int*   timesteps = (const int*)  d_in[0];
    const float* state_0   = (const float*)d_in[1];
    const float* state_1   = (const float*)d_in[2];
    const float* actions   = (const float*)d_in[3];
    const float* time_emb  = (const float*)d_in[4];
    const float* Ws  = (const float*)d_in[5];
    const float* bs  = (const float*)d_in[6];
    const float* Wa  = (const float*)d_in[7];
    const float* ba  = (const float*)d_in[8];
    const float* Wq  = (const float*)d_in[9];
    const float* bq  = (const float*)d_in[10];
    const float* Wk  = (const float*)d_in[11];
    const float* bk  = (const float*)d_in[12];
    const float* Wv  = (const float*)d_in[13];
    const float* bv  = (const float*)d_in[14];
    const float* Wo  = (const float*)d_in[15];
    const float* bo  = (const float*)d_in[16];
    const float* W1  = (const float*)d_in[17];
    const float* b1  = (const float*)d_in[18];
    const float* W2  = (const float*)d_in[19];
    const float* b2  = (const float*)d_in[20];
    const float* ln1_g = (const float*)d_in[21];
    const float* ln1_b = (const float*)d_in[22];
    const float* ln2_g = (const float*)d_in[23];
    const float* ln2_b = (const float*)d_in[24];
    const float* eln_g = (const float*)d_in[25];
    const float* eln_b = (const float*)d_in[26];
    const float* Wp  = (const float*)d_in[27];
    const float* bp  = (const float*)d_in[28];

    float *h, *q, *k, *v, *ctx, *xa, *ln1o, *pre2, *mlp, *sc;
    cudaGetSymbolAddress((void**)&h,    g_h);
    cudaGetSymbolAddress((void**)&q,    g_q);
    cudaGetSymbolAddress((void**)&k,    g_k);
    cudaGetSymbolAddress((void**)&v,    g_v);
    cudaGetSymbolAddress((void**)&ctx,  g_ctx);
    cudaGetSymbolAddress((void**)&xa,   g_xa);
    cudaGetSymbolAddress((void**)&ln1o, g_ln1);
    cudaGetSymbolAddress((void**)&pre2, g_pre2);
    cudaGetSymbolAddress((void**)&mlp,  g_mlp);
    cudaGetSymbolAddress((void**)&sc,   g_sc);

    embed_kernel<<<BB*SS, 256>>>(timesteps, state_0, state_1, actions, time_emb,
                                 Ws, bs, Wa, ba, eln_g, eln_b, h);

    dim3 gQKV(HDIM/128, MROWS/128, 3);   // (4, 48, 3)
    dim3 gH64(HDIM/64,  MROWS/128);      // (8, 48)
    dim3 gF  (DFF /128, MROWS/128);      // (16, 48)
    dim3 gS  (SS/128, SS/128, BB*NH);    // (12, 12, 32)
    dim3 gC  (SS/128, BB*NH);            // (12, 32)

    for (int blk = 0; blk < NBLK; blk++) {
        const float* Wq_ = Wq + (size_t)blk*HDIM*HDIM;
        const float* Wk_ = Wk + (size_t)blk*HDIM*HDIM;
        const float* Wv_ = Wv + (size_t)blk*HDIM*HDIM;
        const float* Wo_ = Wo + (size_t)blk*HDIM*HDIM;
        const float* W1_ = W1 + (size_t)blk*HDIM*DFF;
        const float* W2_ = W2 + (size_t)blk*DFF*HDIM;
        const float* bq_ = bq + (size_t)blk*HDIM;
        const float* bk_ = bk + (size_t)blk*HDIM;
        const float* bv_ = bv + (size_t)blk*HDIM;
        const float* bo_ = bo + (size_t)blk*HDIM;
        const float* b1_ = b1 + (size_t)blk*DFF;
        const float* b2_ = b2 + (size_t)blk*HDIM;
        const float* g1_ = ln1_g + (size_t)blk*HDIM;
        const float* e1_ = ln1_b + (size_t)blk*HDIM;
        const float* g2_ = ln2_g + (size_t)blk*HDIM;
        const float* e2_ = ln2_b + (size_t)blk*HDIM;

        qkv_kernel<<<gQKV, 256>>>(h, Wq_, Wk_, Wv_, bq_, bk_, bv_, q, k, v);

        tscores_kernel<<<gS, 256>>>(q, k, sc);
        softmax_kernel<<<BB*NH*SS, 256>>>(sc);
        tctx_kernel   <<<gC, 256>>>(sc, v, ctx);

        tgemm_kernel<64> <<<gH64, 256>>>(ctx, Wo_, bo_, h, xa, MROWS, HDIM, HDIM, EP_BIAS_RES);
        ln_kernel   <<<MROWS, 256>>>(xa, g1_, e1_, ln1o);
        tgemm_kernel<128><<<gF, 256>>>(ln1o, W1_, b1_, nullptr, mlp, MROWS, DFF, HDIM, EP_BIAS_GELU);
        tgemm_kernel<64> <<<gH64, 256>>>(mlp, W2_, b2_, ln1o, pre2, MROWS, HDIM, DFF, EP_BIAS_RES);
        ln_kernel   <<<MROWS, 256>>>(pre2, g2_, e2_, h);
    }

    final_kernel<<<BB*TT, 256>>>(h, Wp, bp, (float*)d_out);
}

// round 5
// speedup vs baseline: 1.7343x; 1.7343x over previous
#include <cuda_runtime.h>
#include <cuda_bf16.h>
#include <math.h>

#define BB 4
#define TT 512
#define SS 1536           // S = 3*T
#define SDIM 64
#define ADIM 32
#define HDIM 512
#define NH 8
#define DH 64
#define NBLK 6
#define DFF 2048
#define MROWS (BB*SS)     // 6144

enum { EP_BIAS = 0, EP_BIAS_RES = 1, EP_BIAS_GELU = 2 };

// ---------------- scratch (static device globals; no runtime allocs) ----------
__device__ float g_h   [MROWS * HDIM];
__device__ float g_q   [MROWS * HDIM];
__device__ float g_k   [MROWS * HDIM];
__device__ float g_v   [MROWS * HDIM];
__device__ float g_ctx [MROWS * HDIM];
__device__ float g_xa  [MROWS * HDIM];
__device__ float g_ln1 [MROWS * HDIM];
__device__ float g_pre2[MROWS * HDIM];
__device__ float g_mlp [MROWS * DFF];
__device__ float g_sc  [(size_t)BB * NH * SS * SS];   // 302 MB scores

// ---------------- bf16 split helpers ----------------
// pack two consecutive-k elements into (hi-pair, lo-pair) bf16x2 words.
__device__ __forceinline__ uint2 split2bf(float x0, float x1) {
    __nv_bfloat162 h = __floats2bfloat162_rn(x0, x1);   // .x = bf16(x0) (low half)
    float r0 = x0 - __bfloat162float(h.x);
    float r1 = x1 - __bfloat162float(h.y);
    __nv_bfloat162 l = __floats2bfloat162_rn(r0, r1);
    uint2 out;
    out.x = *reinterpret_cast<unsigned*>(&h);
    out.y = *reinterpret_cast<unsigned*>(&l);
    return out;
}

__device__ __forceinline__ void mma16(float c[4],
    unsigned a0, unsigned a1, unsigned a2, unsigned a3,
    unsigned b0, unsigned b1)
{
    asm volatile(
      "mma.sync.aligned.m16n8k16.row.col.f32.bf16.bf16.f32 "
      "{%0,%1,%2,%3},{%4,%5,%6,%7},{%8,%9},{%0,%1,%2,%3};"
      : "+f"(c[0]), "+f"(c[1]), "+f"(c[2]), "+f"(c[3])
      : "r"(a0), "r"(a1), "r"(a2), "r"(a3), "r"(b0), "r"(b1));
}

// ---------------- reductions ----------------
__device__ __forceinline__ float blockReduceSum(float v, float* sm) {
    int lane = threadIdx.x & 31, wid = threadIdx.x >> 5;
    #pragma unroll
    for (int o = 16; o; o >>= 1) v += __shfl_down_sync(0xffffffffu, v, o);
    if (lane == 0) sm[wid] = v;
    __syncthreads();
    float r = 0.f;
    if (wid == 0) {
        r = (lane < 8) ? sm[lane] : 0.f;
        #pragma unroll
        for (int o = 4; o; o >>= 1) r += __shfl_down_sync(0xffffffffu, r, o);
        if (lane == 0) sm[0] = r;
    }
    __syncthreads();
    r = sm[0];
    __syncthreads();
    return r;
}

__device__ __forceinline__ float blockReduceMax(float v, float* sm) {
    int lane = threadIdx.x & 31, wid = threadIdx.x >> 5;
    #pragma unroll
    for (int o = 16; o; o >>= 1) v = fmaxf(v, __shfl_down_sync(0xffffffffu, v, o));
    if (lane == 0) sm[wid] = v;
    __syncthreads();
    float r = -1e30f;
    if (wid == 0) {
        r = (lane < 8) ? sm[lane] : -1e30f;
        #pragma unroll
        for (int o = 4; o; o >>= 1) r = fmaxf(r, __shfl_down_sync(0xffffffffu, r, o));
        if (lane == 0) sm[0] = r;
    }
    __syncthreads();
    r = sm[0];
    __syncthreads();
    return r;
}

// ---------------- embedding + eLN (one block per sequence row) ----------------
__global__ __launch_bounds__(256) void embed_kernel(
    const int* __restrict__ timesteps, const float* __restrict__ s0,
    const float* __restrict__ s1, const float* __restrict__ act,
    const float* __restrict__ temb,
    const float* __restrict__ Ws, const float* __restrict__ bs,
    const float* __restrict__ Wa, const float* __restrict__ ba,
    const float* __restrict__ eg, const float* __restrict__ eb,
    float* __restrict__ out)
{
    int s = blockIdx.x;
    int b = s / SS, sr = s % SS;
    int t = sr / 3, r = sr % 3;

    __shared__ float sIn[SDIM];
    __shared__ float red[32];

    const float* inp; const float* W; const float* bias; int Kin;
    if (r == 0)      { inp = s0  + (size_t)(b*TT + t)*SDIM; W = Ws; bias = bs; Kin = SDIM; }
    else if (r == 1) { inp = s1  + (size_t)(b*TT + t)*SDIM; W = Ws; bias = bs; Kin = SDIM; }
    else             { inp = act + (size_t)(b*TT + t)*ADIM; W = Wa; bias = ba; Kin = ADIM; }

    int tid = threadIdx.x;
    if (tid < Kin) sIn[tid] = inp[tid];
    __syncthreads();

    int tsv = timesteps[b*TT + t];
    const float* te = temb + (size_t)tsv * HDIM;

    float v0, v1;
    {
        int c = tid;
        float a = bias[c] + te[c];
        for (int k = 0; k < Kin; k++) a = fmaf(sIn[k], W[(size_t)k*HDIM + c], a);
        v0 = a;
        c = tid + 256;
        a = bias[c] + te[c];
        for (int k = 0; k < Kin; k++) a = fmaf(sIn[k], W[(size_t)k*HDIM + c], a);
        v1 = a;
    }
    float sum = blockReduceSum(v0 + v1, red);
    float m = sum * (1.0f / HDIM);
    float d0 = v0 - m, d1 = v1 - m;
    float ssq = blockReduceSum(d0*d0 + d1*d1, red);
    float rstd = rsqrtf(ssq * (1.0f / HDIM) + 1e-5f);
    out[(size_t)s*HDIM + tid      ] = d0 * rstd * eg[tid]       + eb[tid];
    out[(size_t)s*HDIM + tid + 256] = d1 * rstd * eg[tid + 256] + eb[tid + 256];
}

// ============ tensor-core GEMM: C[M,N] = A[M,K] @ B[K,N] (bf16x3) ==============
// 256 threads, tile 128xBN, BK=16 (8 k-pairs). Warp grid 2(m) x 4(n).
// Shared tiles hold (hi, lo) bf16x2 pairs; inner loop = LDS.64 + mma.m16n8k16.
template<int BN>
__device__ __forceinline__ void tgemm_body(
    const float* __restrict__ A, const float* __restrict__ B,
    const float* __restrict__ bias, const float* __restrict__ res,
    float* __restrict__ C, int M, int N, int K, int ep)
{
    constexpr int TNF = BN / 32;            // n-fragments per warp
    __shared__ uint2 As2[8][136];           // [k-pair][m]
    __shared__ uint2 Bs2[8][BN + 8];        // [k-pair][n]
    const int tid  = threadIdx.x, lane = tid & 31, warp = tid >> 5;
    const int g    = lane >> 2,  tg   = lane & 3;
    const int wm0  = (warp >> 2) * 64, wn0 = (warp & 3) * (BN / 4);
    const int m0   = blockIdx.y * 128, n0 = blockIdx.x * BN;
    const int ar   = tid >> 2,  akp = (tid & 3) * 2;    // A: k-pairs akp, akp+1
    // B loaders (pair two adjacent k rows)
    const int bkp1 = tid >> 5,  bc1 = (tid & 31) * 4;   // BN=128
    const int bkp2 = tid >> 4,  bc2 = (tid & 15) * 4;   // BN=64 (tid < 128 active)

    float acc[4][TNF][4];
    #pragma unroll
    for (int i = 0; i < 4; i++)
        #pragma unroll
        for (int j = 0; j < TNF; j++)
            #pragma unroll
            for (int l = 0; l < 4; l++) acc[i][j][l] = 0.f;

    for (int k0 = 0; k0 < K; k0 += 16) {
        float4 av0 = *(const float4*)(A + (size_t)(m0 + ar)*K      + k0 + akp*2);
        float4 av1 = *(const float4*)(A + (size_t)(m0 + ar + 64)*K + k0 + akp*2);
        As2[akp+0][ar]    = split2bf(av0.x, av0.y);
        As2[akp+1][ar]    = split2bf(av0.z, av0.w);
        As2[akp+0][ar+64] = split2bf(av1.x, av1.y);
        As2[akp+1][ar+64] = split2bf(av1.z, av1.w);
        if (BN == 128) {
            float4 r0 = *(const float4*)(B + (size_t)(k0 + 2*bkp1)*N     + n0 + bc1);
            float4 r1 = *(const float4*)(B + (size_t)(k0 + 2*bkp1 + 1)*N + n0 + bc1);
            Bs2[bkp1][bc1+0] = split2bf(r0.x, r1.x);
            Bs2[bkp1][bc1+1] = split2bf(r0.y, r1.y);
            Bs2[bkp1][bc1+2] = split2bf(r0.z, r1.z);
            Bs2[bkp1][bc1+3] = split2bf(r0.w, r1.w);
        } else if (tid < 128) {
            float4 r0 = *(const float4*)(B + (size_t)(k0 + 2*bkp2)*N     + n0 + bc2);
            float4 r1 = *(const float4*)(B + (size_t)(k0 + 2*bkp2 + 1)*N + n0 + bc2);
            Bs2[bkp2][bc2+0] = split2bf(r0.x, r1.x);
            Bs2[bkp2][bc2+1] = split2bf(r0.y, r1.y);
            Bs2[bkp2][bc2+2] = split2bf(r0.z, r1.z);
            Bs2[bkp2][bc2+3] = split2bf(r0.w, r1.w);
        }
        __syncthreads();

        uint2 bf[TNF][2];
        #pragma unroll
        for (int tn = 0; tn < TNF; tn++) {
            int n = wn0 + tn*8 + g;
            bf[tn][0] = Bs2[tg][n];
            bf[tn][1] = Bs2[tg+4][n];
        }
        #pragma unroll
        for (int tm = 0; tm < 4; tm++) {
            int m = wm0 + tm*16 + g;
            uint2 a0 = As2[tg][m],   a1 = As2[tg][m+8];
            uint2 a2 = As2[tg+4][m], a3 = As2[tg+4][m+8];
            #pragma unroll
            for (int tn = 0; tn < TNF; tn++) {
                mma16(acc[tm][tn], a0.x,a1.x,a2.x,a3.x, bf[tn][0].x, bf[tn][1].x);
                mma16(acc[tm][tn], a0.y,a1.y,a2.y,a3.y, bf[tn][0].x, bf[tn][1].x);
                mma16(acc[tm][tn], a0.x,a1.x,a2.x,a3.x, bf[tn][0].y, bf[tn][1].y);
            }
        }
        __syncthreads();
    }

    #pragma unroll
    for (int tm = 0; tm < 4; tm++) {
        #pragma unroll
        for (int tn = 0; tn < TNF; tn++) {
            int row = m0 + wm0 + tm*16 + g;
            int col = n0 + wn0 + tn*8 + tg*2;
            float b0v = bias[col], b1v = bias[col+1];
            float v00 = acc[tm][tn][0] + b0v, v01 = acc[tm][tn][1] + b1v;
            float v10 = acc[tm][tn][2] + b0v, v11 = acc[tm][tn][3] + b1v;
            if (ep == EP_BIAS_RES) {
                v00 += res[(size_t)row*N + col];     v01 += res[(size_t)row*N + col + 1];
                v10 += res[(size_t)(row+8)*N + col]; v11 += res[(size_t)(row+8)*N + col + 1];
            } else if (ep == EP_BIAS_GELU) {
                v00 = 0.5f*v00*(1.0f + erff(v00*0.70710678118654752f));
                v01 = 0.5f*v01*(1.0f + erff(v01*0.70710678118654752f));
                v10 = 0.5f*v10*(1.0f + erff(v10*0.70710678118654752f));
                v11 = 0.5f*v11*(1.0f + erff(v11*0.70710678118654752f));
            }
            *(float2*)(C + (size_t)row*N + col)     = make_float2(v00, v01);
            *(float2*)(C + (size_t)(row+8)*N + col) = make_float2(v10, v11);
        }
    }
}

template<int BN>
__global__ __launch_bounds__(256) void tgemm_kernel(
    const float* __restrict__ A, const float* __restrict__ B,
    const float* __restrict__ bias, const float* __restrict__ res,
    float* __restrict__ C, int M, int N, int K, int ep)
{
    tgemm_body<BN>(A, B, bias, res, C, M, N, K, ep);
}

// fused QKV: blockIdx.z selects the projection
__global__ __launch_bounds__(256) void qkv_kernel(
    const float* __restrict__ h,
    const float* __restrict__ Wq, const float* __restrict__ Wk, const float* __restrict__ Wv,
    const float* __restrict__ bq, const float* __restrict__ bk, const float* __restrict__ bv,
    float* __restrict__ q, float* __restrict__ k, float* __restrict__ v)
{
    const float* W; const float* bias; float* out;
    if      (blockIdx.z == 0) { W = Wq; bias = bq; out = q; }
    else if (blockIdx.z == 1) { W = Wk; bias = bk; out = k; }
    else                      { W = Wv; bias = bv; out = v; }
    tgemm_body<128>(h, W, bias, nullptr, out, MROWS, HDIM, HDIM, EP_BIAS);
}

// ---------- scores = Q @ K^T (NT), lower-triangle 128x128 tiles, bf16x3 -------
__global__ __launch_bounds__(256) void tscores_kernel(
    const float* __restrict__ q, const float* __restrict__ k, float* __restrict__ sc)
{
    int jt = blockIdx.x, it = blockIdx.y;
    if (jt > it) return;
    int bh = blockIdx.z, b = bh >> 3, h = bh & 7;
    const float* qb = q + (size_t)b*SS*HDIM + h*DH;
    const float* kb = k + (size_t)b*SS*HDIM + h*DH;
    float* cb = sc + (size_t)bh * SS * SS;
    int i0 = it * 128, j0 = jt * 128;

    __shared__ uint2 Qs2[8][136];     // [k-pair][m]
    __shared__ uint2 Ks2[128][10];    // [n(=j)][k-pair]
    const int tid  = threadIdx.x, lane = tid & 31, warp = tid >> 5;
    const int g    = lane >> 2,  tg   = lane & 3;
    const int wm0  = (warp >> 2) * 64, wn0 = (warp & 3) * 32;
    const int ar   = tid >> 2,  akp = (tid & 3) * 2;

    float acc[4][4][4];
    #pragma unroll
    for (int i = 0; i < 4; i++)
        #pragma unroll
        for (int j = 0; j < 4; j++)
            #pragma unroll
            for (int l = 0; l < 4; l++) acc[i][j][l] = 0.f;

    for (int k0 = 0; k0 < DH; k0 += 16) {
        float4 q0 = *(const float4*)(qb + (size_t)(i0 + ar)*HDIM      + k0 + akp*2);
        float4 q1 = *(const float4*)(qb + (size_t)(i0 + ar + 64)*HDIM + k0 + akp*2);
        float4 kv0 = *(const float4*)(kb + (size_t)(j0 + ar)*HDIM      + k0 + akp*2);
        float4 kv1 = *(const float4*)(kb + (size_t)(j0 + ar + 64)*HDIM + k0 + akp*2);
        Qs2[akp+0][ar]    = split2bf(q0.x, q0.y);
        Qs2[akp+1][ar]    = split2bf(q0.z, q0.w);
        Qs2[akp+0][ar+64] = split2bf(q1.x, q1.y);
        Qs2[akp+1][ar+64] = split2bf(q1.z, q1.w);
        Ks2[ar][akp+0]    = split2bf(kv0.x, kv0.y);
        Ks2[ar][akp+1]    = split2bf(kv0.z, kv0.w);
        Ks2[ar+64][akp+0] = split2bf(kv1.x, kv1.y);
        Ks2[ar+64][akp+1] = split2bf(kv1.z, kv1.w);
        __syncthreads();

        uint2 bf[4][2];
        #pragma unroll
        for (int tn = 0; tn < 4; tn++) {
            int n = wn0 + tn*8 + g;
            bf[tn][0] = Ks2[n][tg];
            bf[tn][1] = Ks2[n][tg+4];
        }
        #pragma unroll
        for (int tm = 0; tm < 4; tm++) {
            int m = wm0 + tm*16 + g;
            uint2 a0 = Qs2[tg][m],   a1 = Qs2[tg][m+8];
            uint2 a2 = Qs2[tg+4][m], a3 = Qs2[tg+4][m+8];
            #pragma unroll
            for (int tn = 0; tn < 4; tn++) {
                mma16(acc[tm][tn], a0.x,a1.x,a2.x,a3.x, bf[tn][0].x, bf[tn][1].x);
                mma16(acc[tm][tn], a0.y,a1.y,a2.y,a3.y, bf[tn][0].x, bf[tn][1].x);
                mma16(acc[tm][tn], a0.x,a1.x,a2.x,a3.x, bf[tn][0].y, bf[tn][1].y);
            }
        }
        __syncthreads();
    }
    const float scale = 0.125f;
    #pragma unroll
    for (int tm = 0; tm < 4; tm++)
        #pragma unroll
        for (int tn = 0; tn < 4; tn++) {
            int row = i0 + wm0 + tm*16 + g;
            int col = j0 + wn0 + tn*8 + tg*2;
            *(float2*)(cb + (size_t)row*SS + col) =
                make_float2(acc[tm][tn][0]*scale, acc[tm][tn][1]*scale);
            *(float2*)(cb + (size_t)(row+8)*SS + col) =
                make_float2(acc[tm][tn][2]*scale, acc[tm][tn][3]*scale);
        }
}

// ------------- causal row softmax, vectorized single read/write ---------------
__global__ __launch_bounds__(256) void softmax_kernel(float* __restrict__ sc)
{
    size_t rid = blockIdx.x;            // bh*S + i
    int i = (int)(rid % SS);
    float* row = sc + rid * (size_t)SS;
    int n = i + 1;
    int nf = (n + 3) >> 2;              // float4 count covering valid region
    int endf = (((i >> 7) + 1) << 7) >> 2;  // 128-tile boundary in float4 units
    __shared__ float red[32];
    int tid = threadIdx.x;

    float4 vals[2];
    int cnt = 0;
    float mx = -1e30f;
    for (int f = tid; f < nf; f += 256) {
        float4 x = *(const float4*)(row + 4*(size_t)f);
        int b4 = 4*f;
        if (b4 + 1 >= n) x.y = -1e30f;
        if (b4 + 2 >= n) x.z = -1e30f;
        if (b4 + 3 >= n) x.w = -1e30f;
        vals[cnt++] = x;
        mx = fmaxf(fmaxf(mx, fmaxf(x.x, x.y)), fmaxf(x.z, x.w));
    }
    mx = blockReduceMax(mx, red);

    float sum = 0.f;
    #pragma unroll
    for (int l = 0; l < 2; l++)
        if (l < cnt) {
            float4& x = vals[l];
            x.x = __expf(x.x - mx); x.y = __expf(x.y - mx);
            x.z = __expf(x.z - mx); x.w = __expf(x.w - mx);
            sum += (x.x + x.y) + (x.z + x.w);
        }
    sum = blockReduceSum(sum, red);
    float inv = 1.0f / sum;

    cnt = 0;
    for (int f = tid; f < nf; f += 256) {
        float4 x = vals[cnt++];
        x.x *= inv; x.y *= inv; x.z *= inv; x.w *= inv;
        *(float4*)(row + 4*(size_t)f) = x;
    }
    for (int f = nf + tid; f < endf; f += 256)
        *(float4*)(row + 4*(size_t)f) = make_float4(0.f, 0.f, 0.f, 0.f);
}

// ---- ctx = attn @ V (NN), tile 128x64, causal K-limit, bf16x3 ----------------
__global__ __launch_bounds__(256) void tctx_kernel(
    const float* __restrict__ at, const float* __restrict__ v, float* __restrict__ ctx)
{
    int it = blockIdx.x, bh = blockIdx.y, b = bh >> 3, h = bh & 7;
    const float* ab = at + (size_t)bh * SS * SS;
    const float* vb = v   + (size_t)b*SS*HDIM + h*DH;
    float* cb       = ctx + (size_t)b*SS*HDIM + h*DH;
    int i0 = it * 128;
    int kmax = (it + 1) * 128;

    __shared__ uint2 As2[8][136];
    __shared__ uint2 Bs2[8][72];
    const int tid  = threadIdx.x, lane = tid & 31, warp = tid >> 5;
    const int g    = lane >> 2,  tg   = lane & 3;
    const int wm0  = (warp >> 2) * 64, wn0 = (warp & 3) * 16;
    const int ar   = tid >> 2,  akp = (tid & 3) * 2;
    const int bkp  = tid >> 4,  bcc = (tid & 15) * 4;   // tid < 128 active

    float acc[4][2][4];
    #pragma unroll
    for (int i = 0; i < 4; i++)
        #pragma unroll
        for (int j = 0; j < 2; j++)
            #pragma unroll
            for (int l = 0; l < 4; l++) acc[i][j][l] = 0.f;

    for (int k0 = 0; k0 < kmax; k0 += 16) {
        float4 a0v = *(const float4*)(ab + (size_t)(i0 + ar)*SS      + k0 + akp*2);
        float4 a1v = *(const float4*)(ab + (size_t)(i0 + ar + 64)*SS + k0 + akp*2);
        As2[akp+0][ar]    = split2bf(a0v.x, a0v.y);
        As2[akp+1][ar]    = split2bf(a0v.z, a0v.w);
        As2[akp+0][ar+64] = split2bf(a1v.x, a1v.y);
        As2[akp+1][ar+64] = split2bf(a1v.z, a1v.w);
        if (tid < 128) {
            float4 r0 = *(const float4*)(vb + (size_t)(k0 + 2*bkp)*HDIM     + bcc);
            float4 r1 = *(const float4*)(vb + (size_t)(k0 + 2*bkp + 1)*HDIM + bcc);
            Bs2[bkp][bcc+0] = split2bf(r0.x, r1.x);
            Bs2[bkp][bcc+1] = split2bf(r0.y, r1.y);
            Bs2[bkp][bcc+2] = split2bf(r0.z, r1.z);
            Bs2[bkp][bcc+3] = split2bf(r0.w, r1.w);
        }
        __syncthreads();

        uint2 bf[2][2];
        #pragma unroll
        for (int tn = 0; tn < 2; tn++) {
            int n = wn0 + tn*8 + g;
            bf[tn][0] = Bs2[tg][n];
            bf[tn][1] = Bs2[tg+4][n];
        }
        #pragma unroll
        for (int tm = 0; tm < 4; tm++) {
            int m = wm0 + tm*16 + g;
            uint2 a0 = As2[tg][m],   a1 = As2[tg][m+8];
            uint2 a2 = As2[tg+4][m], a3 = As2[tg+4][m+8];
            #pragma unroll
            for (int tn = 0; tn < 2; tn++) {
                mma16(acc[tm][tn], a0.x,a1.x,a2.x,a3.x, bf[tn][0].x, bf[tn][1].x);
                mma16(acc[tm][tn], a0.y,a1.y,a2.y,a3.y, bf[tn][0].x, bf[tn][1].x);
                mma16(acc[tm][tn], a0.x,a1.x,a2.x,a3.x, bf[tn][0].y, bf[tn][1].y);
            }
        }
        __syncthreads();
    }
    #pragma unroll
    for (int tm = 0; tm < 4; tm++)
        #pragma unroll
        for (int tn = 0; tn < 2; tn++) {
            int row = i0 + wm0 + tm*16 + g;
            int col = wn0 + tn*8 + tg*2;
            *(float2*)(cb + (size_t)row*HDIM + col) =
                make_float2(acc[tm][tn][0], acc[tm][tn][1]);
            *(float2*)(cb + (size_t)(row+8)*HDIM + col) =
                make_float2(acc[tm][tn][2], acc[tm][tn][3]);
        }
}

// ---------------- plain layernorm over HDIM ----------------
__global__ __launch_bounds__(256) void ln_kernel(
    const float* __restrict__ x, const float* __restrict__ g,
    const float* __restrict__ b, float* __restrict__ out)
{
    int row = blockIdx.x;
    __shared__ float red[32];
    int tid = threadIdx.x;
    float v0 = x[(size_t)row*HDIM + tid];
    float v1 = x[(size_t)row*HDIM + tid + 256];
    float sum = blockReduceSum(v0 + v1, red);
    float m = sum * (1.0f / HDIM);
    float d0 = v0 - m, d1 = v1 - m;
    float ssq = blockReduceSum(d0*d0 + d1*d1, red);
    float rstd = rsqrtf(ssq * (1.0f / HDIM) + 1e-5f);
    out[(size_t)row*HDIM + tid      ] = d0 * rstd * g[tid]       + b[tid];
    out[(size_t)row*HDIM + tid + 256] = d1 * rstd * g[tid + 256] + b[tid + 256];
}

// ---------------- final projection: out = h[:, :, 1] @ Wp + bp ----------------
__global__ __launch_bounds__(256) void final_kernel(
    const float* __restrict__ h, const float* __restrict__ Wp,
    const float* __restrict__ bp, float* __restrict__ out)
{
    int bt = blockIdx.x;                 // b*T + t
    int b = bt / TT, t = bt % TT;
    const float* row = h + ((size_t)b*SS + 3*t + 1) * HDIM;
    __shared__ float sRow[HDIM];
    __shared__ float part[8][ADIM];
    int tid = threadIdx.x;
    sRow[tid] = row[tid];
    sRow[tid + 256] = row[tid + 256];
    __syncthreads();
    int c = tid & 31, g = tid >> 5;
    float a = 0.f;
    for (int k = g*64; k < (g+1)*64; k++) a = fmaf(sRow[k], Wp[(size_t)k*ADIM + c], a);
    part[g][c] = a;
    __syncthreads();
    if (tid < ADIM) {
        float s = bp[tid];
        #pragma unroll
        for (int g2 = 0; g2 < 8; g2++) s += part[g2][tid];
        out[(size_t)bt*ADIM + tid] = s;
    }
}

// ---------------- driver ----------------
extern "C" void kernel_launch(void* const* d_in, const int* in_sizes, int n_in,
                              void* d_out, int out_size)
{
    const int*   timesteps = (const int*)  d_in[0];
    const float* state_0   = (const float*)d_in[1];
    const float* state_1   = (const float*)d_in[2];
    const float* actions   = (const float*)d_in[3];
    const float* time_emb  = (const float*)d_in[4];
    const float* Ws  = (const float*)d_in[5];
    const float* bs  = (const float*)d_in[6];
    const float* Wa  = (const float*)d_in[7];
    const float* ba  = (const float*)d_in[8];
    const float* Wq  = (const float*)d_in[9];
    const float* bq  = (const float*)d_in[10];
    const float* Wk  = (const float*)d_in[11];
    const float* bk  = (const float*)d_in[12];
    const float* Wv  = (const float*)d_in[13];
    const float* bv  = (const float*)d_in[14];
    const float* Wo  = (const float*)d_in[15];
    const float* bo  = (const float*)d_in[16];
    const float* W1  = (const float*)d_in[17];
    const float* b1  = (const float*)d_in[18];
    const float* W2  = (const float*)d_in[19];
    const float* b2  = (const float*)d_in[20];
    const float* ln1_g = (const float*)d_in[21];
    const float* ln1_b = (const float*)d_in[22];
    const float* ln2_g = (const float*)d_in[23];
    const float* ln2_b = (const float*)d_in[24];
    const float* eln_g = (const float*)d_in[25];
    const float* eln_b = (const float*)d_in[26];
    const float* Wp  = (const float*)d_in[27];
    const float* bp  = (const float*)d_in[28];

    float *h, *q, *k, *v, *ctx, *xa, *ln1o, *pre2, *mlp, *sc;
    cudaGetSymbolAddress((void**)&h,    g_h);
    cudaGetSymbolAddress((void**)&q,    g_q);
    cudaGetSymbolAddress((void**)&k,    g_k);
    cudaGetSymbolAddress((void**)&v,    g_v);
    cudaGetSymbolAddress((void**)&ctx,  g_ctx);
    cudaGetSymbolAddress((void**)&xa,   g_xa);
    cudaGetSymbolAddress((void**)&ln1o, g_ln1);
    cudaGetSymbolAddress((void**)&pre2, g_pre2);
    cudaGetSymbolAddress((void**)&mlp,  g_mlp);
    cudaGetSymbolAddress((void**)&sc,   g_sc);

    embed_kernel<<<BB*SS, 256>>>(timesteps, state_0, state_1, actions, time_emb,
                                 Ws, bs, Wa, ba, eln_g, eln_b, h);

    dim3 gQKV(HDIM/128, MROWS/128, 3);   // (4, 48, 3)
    dim3 gH64(HDIM/64,  MROWS/128);      // (8, 48)
    dim3 gF  (DFF /128, MROWS/128);      // (16, 48)
    dim3 gS  (SS/128, SS/128, BB*NH);    // (12, 12, 32)
    dim3 gC  (SS/128, BB*NH);            // (12, 32)

    for (int blk = 0; blk < NBLK; blk++) {
        const float* Wq_ = Wq + (size_t)blk*HDIM*HDIM;
        const float* Wk_ = Wk + (size_t)blk*HDIM*HDIM;
        const float* Wv_ = Wv + (size_t)blk*HDIM*HDIM;
        const float* Wo_ = Wo + (size_t)blk*HDIM*HDIM;
        const float* W1_ = W1 + (size_t)blk*HDIM*DFF;
        const float* W2_ = W2 + (size_t)blk*DFF*HDIM;
        const float* bq_ = bq + (size_t)blk*HDIM;
        const float* bk_ = bk + (size_t)blk*HDIM;
        const float* bv_ = bv + (size_t)blk*HDIM;
        const float* bo_ = bo + (size_t)blk*HDIM;
        const float* b1_ = b1 + (size_t)blk*DFF;
        const float* b2_ = b2 + (size_t)blk*HDIM;
        const float* g1_ = ln1_g + (size_t)blk*HDIM;
        const float* e1_ = ln1_b + (size_t)blk*HDIM;
        const float* g2_ = ln2_g + (size_t)blk*HDIM;
        const float* e2_ = ln2_b + (size_t)blk*HDIM;

        qkv_kernel<<<gQKV, 256>>>(h, Wq_, Wk_, Wv_, bq_, bk_, bv_, q, k, v);

        tscores_kernel<<<gS, 256>>>(q, k, sc);
        softmax_kernel<<<BB*NH*SS, 256>>>(sc);
        tctx_kernel   <<<gC, 256>>>(sc, v, ctx);

        tgemm_kernel<64> <<<gH64, 256>>>(ctx, Wo_, bo_, h, xa, MROWS, HDIM, HDIM, EP_BIAS_RES);
        ln_kernel   <<<MROWS, 256>>>(xa, g1_, e1_, ln1o);
        tgemm_kernel<128><<<gF, 256>>>(ln1o, W1_, b1_, nullptr, mlp, MROWS, DFF, HDIM, EP_BIAS_GELU);
        tgemm_kernel<64> <<<gH64, 256>>>(mlp, W2_, b2_, ln1o, pre2, MROWS, HDIM, DFF, EP_BIAS_RES);
        ln_kernel   <<<MROWS, 256>>>(pre2, g2_, e2_, h);
    }

    final_kernel<<<BB*TT, 256>>>(h, Wp, bp, (float*)d_out);
}

// round 6
// speedup vs baseline: 2.1165x; 1.2204x over previous
#include <cuda_runtime.h>
#include <cuda_bf16.h>
#include <math.h>

#define BB 4
#define TT 512
#define SS 1536           // S = 3*T
#define SDIM 64
#define ADIM 32
#define HDIM 512
#define NH 8
#define DH 64
#define NBLK 6
#define DFF 2048
#define MROWS (BB*SS)     // 6144

enum { EP_BIAS = 0, EP_BIAS_RES = 1, EP_BIAS_GELU = 2 };

// ---------------- scratch (static device globals; no runtime allocs) ----------
__device__ float g_h   [MROWS * HDIM];
__device__ float g_q   [MROWS * HDIM];
__device__ float g_k   [MROWS * HDIM];
__device__ float g_v   [MROWS * HDIM];
__device__ float g_ctx [MROWS * HDIM];
__device__ float g_xa  [MROWS * HDIM];
__device__ float g_ln1 [MROWS * HDIM];
__device__ float g_pre2[MROWS * HDIM];
__device__ float g_mlp [MROWS * DFF];

// ---------------- bf16 split helpers ----------------
// pack two elements into (hi-pair, lo-pair) bf16x2 words.
__device__ __forceinline__ uint2 split2bf(float x0, float x1) {
    __nv_bfloat162 h = __floats2bfloat162_rn(x0, x1);
    float r0 = x0 - __bfloat162float(h.x);
    float r1 = x1 - __bfloat162float(h.y);
    __nv_bfloat162 l = __floats2bfloat162_rn(r0, r1);
    uint2 out;
    out.x = *reinterpret_cast<unsigned*>(&h);
    out.y = *reinterpret_cast<unsigned*>(&l);
    return out;
}

__device__ __forceinline__ void mma16(float c[4],
    unsigned a0, unsigned a1, unsigned a2, unsigned a3,
    unsigned b0, unsigned b1)
{
    asm volatile(
      "mma.sync.aligned.m16n8k16.row.col.f32.bf16.bf16.f32 "
      "{%0,%1,%2,%3},{%4,%5,%6,%7},{%8,%9},{%0,%1,%2,%3};"
      : "+f"(c[0]), "+f"(c[1]), "+f"(c[2]), "+f"(c[3])
      : "r"(a0), "r"(a1), "r"(a2), "r"(a3), "r"(b0), "r"(b1));
}

// ---------------- reductions ----------------
__device__ __forceinline__ float blockReduceSum(float v, float* sm) {
    int lane = threadIdx.x & 31, wid = threadIdx.x >> 5;
    #pragma unroll
    for (int o = 16; o; o >>= 1) v += __shfl_down_sync(0xffffffffu, v, o);
    if (lane == 0) sm[wid] = v;
    __syncthreads();
    float r = 0.f;
    if (wid == 0) {
        r = (lane < 8) ? sm[lane] : 0.f;
        #pragma unroll
        for (int o = 4; o; o >>= 1) r += __shfl_down_sync(0xffffffffu, r, o);
        if (lane == 0) sm[0] = r;
    }
    __syncthreads();
    r = sm[0];
    __syncthreads();
    return r;
}

// ---------------- embedding + eLN (one block per sequence row) ----------------
__global__ __launch_bounds__(256) void embed_kernel(
    const int* __restrict__ timesteps, const float* __restrict__ s0,
    const float* __restrict__ s1, const float* __restrict__ act,
    const float* __restrict__ temb,
    const float* __restrict__ Ws, const float* __restrict__ bs,
    const float* __restrict__ Wa, const float* __restrict__ ba,
    const float* __restrict__ eg, const float* __restrict__ eb,
    float* __restrict__ out)
{
    int s = blockIdx.x;
    int b = s / SS, sr = s % SS;
    int t = sr / 3, r = sr % 3;

    __shared__ float sIn[SDIM];
    __shared__ float red[32];

    const float* inp; const float* W; const float* bias; int Kin;
    if (r == 0)      { inp = s0  + (size_t)(b*TT + t)*SDIM; W = Ws; bias = bs; Kin = SDIM; }
    else if (r == 1) { inp = s1  + (size_t)(b*TT + t)*SDIM; W = Ws; bias = bs; Kin = SDIM; }
    else             { inp = act + (size_t)(b*TT + t)*ADIM; W = Wa; bias = ba; Kin = ADIM; }

    int tid = threadIdx.x;
    if (tid < Kin) sIn[tid] = inp[tid];
    __syncthreads();

    int tsv = timesteps[b*TT + t];
    const float* te = temb + (size_t)tsv * HDIM;

    float v0, v1;
    {
        int c = tid;
        float a = bias[c] + te[c];
        for (int k = 0; k < Kin; k++) a = fmaf(sIn[k], W[(size_t)k*HDIM + c], a);
        v0 = a;
        c = tid + 256;
        a = bias[c] + te[c];
        for (int k = 0; k < Kin; k++) a = fmaf(sIn[k], W[(size_t)k*HDIM + c], a);
        v1 = a;
    }
    float sum = blockReduceSum(v0 + v1, red);
    float m = sum * (1.0f / HDIM);
    float d0 = v0 - m, d1 = v1 - m;
    float ssq = blockReduceSum(d0*d0 + d1*d1, red);
    float rstd = rsqrtf(ssq * (1.0f / HDIM) + 1e-5f);
    out[(size_t)s*HDIM + tid      ] = d0 * rstd * eg[tid]       + eb[tid];
    out[(size_t)s*HDIM + tid + 256] = d1 * rstd * eg[tid + 256] + eb[tid + 256];
}

// ============ tensor-core GEMM: C[M,N] = A[M,K] @ B[K,N] (bf16x3) ==============
template<int BN>
__device__ __forceinline__ void tgemm_body(
    const float* __restrict__ A, const float* __restrict__ B,
    const float* __restrict__ bias, const float* __restrict__ res,
    float* __restrict__ C, int M, int N, int K, int ep)
{
    constexpr int TNF = BN / 32;
    __shared__ uint2 As2[8][136];
    __shared__ uint2 Bs2[8][BN + 8];
    const int tid  = threadIdx.x, lane = tid & 31, warp = tid >> 5;
    const int g    = lane >> 2,  tg   = lane & 3;
    const int wm0  = (warp >> 2) * 64, wn0 = (warp & 3) * (BN / 4);
    const int m0   = blockIdx.y * 128, n0 = blockIdx.x * BN;
    const int ar   = tid >> 2,  akp = (tid & 3) * 2;
    const int bkp1 = tid >> 5,  bc1 = (tid & 31) * 4;
    const int bkp2 = tid >> 4,  bc2 = (tid & 15) * 4;

    float acc[4][TNF][4];
    #pragma unroll
    for (int i = 0; i < 4; i++)
        #pragma unroll
        for (int j = 0; j < TNF; j++)
            #pragma unroll
            for (int l = 0; l < 4; l++) acc[i][j][l] = 0.f;

    for (int k0 = 0; k0 < K; k0 += 16) {
        float4 av0 = *(const float4*)(A + (size_t)(m0 + ar)*K      + k0 + akp*2);
        float4 av1 = *(const float4*)(A + (size_t)(m0 + ar + 64)*K + k0 + akp*2);
        As2[akp+0][ar]    = split2bf(av0.x, av0.y);
        As2[akp+1][ar]    = split2bf(av0.z, av0.w);
        As2[akp+0][ar+64] = split2bf(av1.x, av1.y);
        As2[akp+1][ar+64] = split2bf(av1.z, av1.w);
        if (BN == 128) {
            float4 r0 = *(const float4*)(B + (size_t)(k0 + 2*bkp1)*N     + n0 + bc1);
            float4 r1 = *(const float4*)(B + (size_t)(k0 + 2*bkp1 + 1)*N + n0 + bc1);
            Bs2[bkp1][bc1+0] = split2bf(r0.x, r1.x);
            Bs2[bkp1][bc1+1] = split2bf(r0.y, r1.y);
            Bs2[bkp1][bc1+2] = split2bf(r0.z, r1.z);
            Bs2[bkp1][bc1+3] = split2bf(r0.w, r1.w);
        } else if (tid < 128) {
            float4 r0 = *(const float4*)(B + (size_t)(k0 + 2*bkp2)*N     + n0 + bc2);
            float4 r1 = *(const float4*)(B + (size_t)(k0 + 2*bkp2 + 1)*N + n0 + bc2);
            Bs2[bkp2][bc2+0] = split2bf(r0.x, r1.x);
            Bs2[bkp2][bc2+1] = split2bf(r0.y, r1.y);
            Bs2[bkp2][bc2+2] = split2bf(r0.z, r1.z);
            Bs2[bkp2][bc2+3] = split2bf(r0.w, r1.w);
        }
        __syncthreads();

        uint2 bf[TNF][2];
        #pragma unroll
        for (int tn = 0; tn < TNF; tn++) {
            int n = wn0 + tn*8 + g;
            bf[tn][0] = Bs2[tg][n];
            bf[tn][1] = Bs2[tg+4][n];
        }
        #pragma unroll
        for (int tm = 0; tm < 4; tm++) {
            int m = wm0 + tm*16 + g;
            uint2 a0 = As2[tg][m],   a1 = As2[tg][m+8];
            uint2 a2 = As2[tg+4][m], a3 = As2[tg+4][m+8];
            #pragma unroll
            for (int tn = 0; tn < TNF; tn++) {
                mma16(acc[tm][tn], a0.x,a1.x,a2.x,a3.x, bf[tn][0].x, bf[tn][1].x);
                mma16(acc[tm][tn], a0.y,a1.y,a2.y,a3.y, bf[tn][0].x, bf[tn][1].x);
                mma16(acc[tm][tn], a0.x,a1.x,a2.x,a3.x, bf[tn][0].y, bf[tn][1].y);
            }
        }
        __syncthreads();
    }

    #pragma unroll
    for (int tm = 0; tm < 4; tm++) {
        #pragma unroll
        for (int tn = 0; tn < TNF; tn++) {
            int row = m0 + wm0 + tm*16 + g;
            int col = n0 + wn0 + tn*8 + tg*2;
            float b0v = bias[col], b1v = bias[col+1];
            float v00 = acc[tm][tn][0] + b0v, v01 = acc[tm][tn][1] + b1v;
            float v10 = acc[tm][tn][2] + b0v, v11 = acc[tm][tn][3] + b1v;
            if (ep == EP_BIAS_RES) {
                v00 += res[(size_t)row*N + col];     v01 += res[(size_t)row*N + col + 1];
                v10 += res[(size_t)(row+8)*N + col]; v11 += res[(size_t)(row+8)*N + col + 1];
            } else if (ep == EP_BIAS_GELU) {
                v00 = 0.5f*v00*(1.0f + erff(v00*0.70710678118654752f));
                v01 = 0.5f*v01*(1.0f + erff(v01*0.70710678118654752f));
                v10 = 0.5f*v10*(1.0f + erff(v10*0.70710678118654752f));
                v11 = 0.5f*v11*(1.0f + erff(v11*0.70710678118654752f));
            }
            *(float2*)(C + (size_t)row*N + col)     = make_float2(v00, v01);
            *(float2*)(C + (size_t)(row+8)*N + col) = make_float2(v10, v11);
        }
    }
}

template<int BN>
__global__ __launch_bounds__(256) void tgemm_kernel(
    const float* __restrict__ A, const float* __restrict__ B,
    const float* __restrict__ bias, const float* __restrict__ res,
    float* __restrict__ C, int M, int N, int K, int ep)
{
    tgemm_body<BN>(A, B, bias, res, C, M, N, K, ep);
}

// fused QKV: blockIdx.z selects the projection
__global__ __launch_bounds__(256) void qkv_kernel(
    const float* __restrict__ h,
    const float* __restrict__ Wq, const float* __restrict__ Wk, const float* __restrict__ Wv,
    const float* __restrict__ bq, const float* __restrict__ bk, const float* __restrict__ bv,
    float* __restrict__ q, float* __restrict__ k, float* __restrict__ v)
{
    const float* W; const float* bias; float* out;
    if      (blockIdx.z == 0) { W = Wq; bias = bq; out = q; }
    else if (blockIdx.z == 1) { W = Wk; bias = bk; out = k; }
    else                      { W = Wv; bias = bv; out = v; }
    tgemm_body<128>(h, W, bias, nullptr, out, MROWS, HDIM, HDIM, EP_BIAS);
}

// ================= flash attention: fused scores+softmax+ctx ==================
// Grid (12 i-tiles, 32 bh), 256 threads (8 warps). Warp owns 16 rows x full
// 128-col S tile in registers; row softmax stats stay intra-quad (shfl 1,2).
// P fragments feed P@V directly from S accumulator registers. bf16x3 both mmas.
#define FLASH_KPAD 132
#define FLASH_VPAD 68
#define FLASH_SMEM ((32*FLASH_KPAD + 64*FLASH_VPAD) * (int)sizeof(uint2))

__global__ __launch_bounds__(256) void flash_kernel(
    const float* __restrict__ q, const float* __restrict__ k,
    const float* __restrict__ v, float* __restrict__ ctx)
{
    extern __shared__ uint2 dsmem[];
    uint2 (*Ks)[FLASH_KPAD] = reinterpret_cast<uint2(*)[FLASH_KPAD]>(dsmem);
    uint2 (*Vs)[FLASH_VPAD] = reinterpret_cast<uint2(*)[FLASH_VPAD]>(dsmem + 32*FLASH_KPAD);

    const int it = (int)(gridDim.x - 1 - blockIdx.x);   // big tiles first
    const int bh = blockIdx.y, b = bh >> 3, h = bh & 7;
    const float* qb = q + (size_t)b*SS*HDIM + h*DH;
    const float* kb = k + (size_t)b*SS*HDIM + h*DH;
    const float* vb = v + (size_t)b*SS*HDIM + h*DH;
    float* cb       = ctx + (size_t)b*SS*HDIM + h*DH;

    const int tid  = threadIdx.x, lane = tid & 31, warp = tid >> 5;
    const int g    = lane >> 2,  tg   = lane & 3;
    const int i0   = it * 128;
    const int rowg = i0 + warp*16 + g;     // + 8 for second row

    // ---- Q fragments in registers (K = 64 => 4 mma-k steps) ----
    uint2 qf[4][4];
    {
        const float* qrg = qb + (size_t)rowg*HDIM;
        const float* qr8 = qrg + 8*HDIM;
        #pragma unroll
        for (int kk = 0; kk < 4; kk++) {
            float2 f;
            f = *(const float2*)(qrg + kk*16 + 2*tg);     qf[kk][0] = split2bf(f.x, f.y);
            f = *(const float2*)(qr8 + kk*16 + 2*tg);     qf[kk][1] = split2bf(f.x, f.y);
            f = *(const float2*)(qrg + kk*16 + 8 + 2*tg); qf[kk][2] = split2bf(f.x, f.y);
            f = *(const float2*)(qr8 + kk*16 + 8 + 2*tg); qf[kk][3] = split2bf(f.x, f.y);
        }
    }

    float m0 = -1e30f, m1 = -1e30f, l0 = 0.f, l1 = 0.f;
    float o[8][4];
    #pragma unroll
    for (int nf = 0; nf < 8; nf++)
        #pragma unroll
        for (int l = 0; l < 4; l++) o[nf][l] = 0.f;

    const int kjr = tid >> 1, kcb = (tid & 1)*32;   // K loader: row, col base
    const int vjp = tid >> 2, vcb = (tid & 3)*16;   // V loader: row pair, col base

    for (int jt = 0; jt <= it; jt++) {
        const int j0 = jt * 128;
        // ---- load K tile [128 x 64] as Ks[kp=dh/2][j] ----
        {
            const float* krow = kb + (size_t)(j0 + kjr)*HDIM + kcb;
            #pragma unroll
            for (int u = 0; u < 8; u++) {
                float4 f = *(const float4*)(krow + u*4);
                int kp = (kcb + u*4) >> 1;
                Ks[kp][kjr]   = split2bf(f.x, f.y);
                Ks[kp+1][kjr] = split2bf(f.z, f.w);
            }
        }
        // ---- load V tile [128 x 64] as Vs[jp=j/2][n] ----
        {
            const float* vr0 = vb + (size_t)(j0 + 2*vjp)*HDIM + vcb;
            const float* vr1 = vr0 + HDIM;
            #pragma unroll
            for (int u = 0; u < 4; u++) {
                float4 f0 = *(const float4*)(vr0 + u*4);
                float4 f1 = *(const float4*)(vr1 + u*4);
                Vs[vjp][vcb + u*4 + 0] = split2bf(f0.x, f1.x);
                Vs[vjp][vcb + u*4 + 1] = split2bf(f0.y, f1.y);
                Vs[vjp][vcb + u*4 + 2] = split2bf(f0.z, f1.z);
                Vs[vjp][vcb + u*4 + 3] = split2bf(f0.w, f1.w);
            }
        }
        __syncthreads();

        // ---- S = Q @ K^T (128 cols -> 16 n-frags per warp) ----
        float s[16][4];
        #pragma unroll
        for (int jf = 0; jf < 16; jf++)
            #pragma unroll
            for (int l = 0; l < 4; l++) s[jf][l] = 0.f;

        #pragma unroll
        for (int kk = 0; kk < 4; kk++) {
            uint2 a0 = qf[kk][0], a1 = qf[kk][1], a2 = qf[kk][2], a3 = qf[kk][3];
            #pragma unroll
            for (int jf = 0; jf < 16; jf++) {
                uint2 b0 = Ks[kk*8 + tg][jf*8 + g];
                uint2 b1 = Ks[kk*8 + tg + 4][jf*8 + g];
                mma16(s[jf], a0.x,a1.x,a2.x,a3.x, b0.x, b1.x);
                mma16(s[jf], a0.y,a1.y,a2.y,a3.y, b0.x, b1.x);
                mma16(s[jf], a0.x,a1.x,a2.x,a3.x, b0.y, b1.y);
            }
        }

        // ---- scale + causal mask (diagonal tile only) ----
        const float scale = 0.125f;
        if (jt == it) {
            const int r0 = warp*16 + g, r1 = r0 + 8;
            #pragma unroll
            for (int jf = 0; jf < 16; jf++) {
                int c0 = jf*8 + 2*tg;
                s[jf][0] = (c0     <= r0) ? s[jf][0]*scale : -1e30f;
                s[jf][1] = (c0 + 1 <= r0) ? s[jf][1]*scale : -1e30f;
                s[jf][2] = (c0     <= r1) ? s[jf][2]*scale : -1e30f;
                s[jf][3] = (c0 + 1 <= r1) ? s[jf][3]*scale : -1e30f;
            }
        } else {
            #pragma unroll
            for (int jf = 0; jf < 16; jf++) {
                s[jf][0] *= scale; s[jf][1] *= scale;
                s[jf][2] *= scale; s[jf][3] *= scale;
            }
        }

        // ---- online softmax (row stats within quad: shfl_xor 1,2) ----
        float tm0 = -1e30f, tm1 = -1e30f;
        #pragma unroll
        for (int jf = 0; jf < 16; jf++) {
            tm0 = fmaxf(tm0, fmaxf(s[jf][0], s[jf][1]));
            tm1 = fmaxf(tm1, fmaxf(s[jf][2], s[jf][3]));
        }
        tm0 = fmaxf(tm0, __shfl_xor_sync(0xffffffffu, tm0, 1));
        tm0 = fmaxf(tm0, __shfl_xor_sync(0xffffffffu, tm0, 2));
        tm1 = fmaxf(tm1, __shfl_xor_sync(0xffffffffu, tm1, 1));
        tm1 = fmaxf(tm1, __shfl_xor_sync(0xffffffffu, tm1, 2));

        float nm0 = fmaxf(m0, tm0), nm1 = fmaxf(m1, tm1);
        float al0 = __expf(m0 - nm0), al1 = __expf(m1 - nm1);
        m0 = nm0; m1 = nm1;

        float rs0 = 0.f, rs1 = 0.f;
        #pragma unroll
        for (int jf = 0; jf < 16; jf++) {
            s[jf][0] = __expf(s[jf][0] - nm0);
            s[jf][1] = __expf(s[jf][1] - nm0);
            s[jf][2] = __expf(s[jf][2] - nm1);
            s[jf][3] = __expf(s[jf][3] - nm1);
            rs0 += s[jf][0] + s[jf][1];
            rs1 += s[jf][2] + s[jf][3];
        }
        rs0 += __shfl_xor_sync(0xffffffffu, rs0, 1);
        rs0 += __shfl_xor_sync(0xffffffffu, rs0, 2);
        rs1 += __shfl_xor_sync(0xffffffffu, rs1, 1);
        rs1 += __shfl_xor_sync(0xffffffffu, rs1, 2);
        l0 = l0*al0 + rs0;
        l1 = l1*al1 + rs1;

        #pragma unroll
        for (int nf = 0; nf < 8; nf++) {
            o[nf][0] *= al0; o[nf][1] *= al0;
            o[nf][2] *= al1; o[nf][3] *= al1;
        }

        // ---- O += P @ V (P fragments straight from S registers) ----
        #pragma unroll
        for (int kk = 0; kk < 8; kk++) {
            uint2 A0 = split2bf(s[2*kk][0],   s[2*kk][1]);
            uint2 A1 = split2bf(s[2*kk][2],   s[2*kk][3]);
            uint2 A2 = split2bf(s[2*kk+1][0], s[2*kk+1][1]);
            uint2 A3 = split2bf(s[2*kk+1][2], s[2*kk+1][3]);
            #pragma unroll
            for (int nf = 0; nf < 8; nf++) {
                uint2 b0 = Vs[kk*8 + tg][nf*8 + g];
                uint2 b1 = Vs[kk*8 + tg + 4][nf*8 + g];
                mma16(o[nf], A0.x,A1.x,A2.x,A3.x, b0.x, b1.x);
                mma16(o[nf], A0.y,A1.y,A2.y,A3.y, b0.x, b1.x);
                mma16(o[nf], A0.x,A1.x,A2.x,A3.x, b0.y, b1.y);
            }
        }
        __syncthreads();
    }

    // ---- epilogue: O /= l ----
    float inv0 = 1.0f / l0, inv1 = 1.0f / l1;
    float* crow0 = cb + (size_t)rowg*HDIM;
    float* crow1 = crow0 + 8*HDIM;
    #pragma unroll
    for (int nf = 0; nf < 8; nf++) {
        *(float2*)(crow0 + nf*8 + 2*tg) = make_float2(o[nf][0]*inv0, o[nf][1]*inv0);
        *(float2*)(crow1 + nf*8 + 2*tg) = make_float2(o[nf][2]*inv1, o[nf][3]*inv1);
    }
}

// ---------------- plain layernorm over HDIM ----------------
__global__ __launch_bounds__(256) void ln_kernel(
    const float* __restrict__ x, const float* __restrict__ g,
    const float* __restrict__ b, float* __restrict__ out)
{
    int row = blockIdx.x;
    __shared__ float red[32];
    int tid = threadIdx.x;
    float v0 = x[(size_t)row*HDIM + tid];
    float v1 = x[(size_t)row*HDIM + tid + 256];
    float sum = blockReduceSum(v0 + v1, red);
    float m = sum * (1.0f / HDIM);
    float d0 = v0 - m, d1 = v1 - m;
    float ssq = blockReduceSum(d0*d0 + d1*d1, red);
    float rstd = rsqrtf(ssq * (1.0f / HDIM) + 1e-5f);
    out[(size_t)row*HDIM + tid      ] = d0 * rstd * g[tid]       + b[tid];
    out[(size_t)row*HDIM + tid + 256] = d1 * rstd * g[tid + 256] + b[tid + 256];
}

// ---------------- final projection: out = h[:, :, 1] @ Wp + bp ----------------
__global__ __launch_bounds__(256) void final_kernel(
    const float* __restrict__ h, const float* __restrict__ Wp,
    const float* __restrict__ bp, float* __restrict__ out)
{
    int bt = blockIdx.x;
    int b = bt / TT, t = bt % TT;
    const float* row = h + ((size_t)b*SS + 3*t + 1) * HDIM;
    __shared__ float sRow[HDIM];
    __shared__ float part[8][ADIM];
    int tid = threadIdx.x;
    sRow[tid] = row[tid];
    sRow[tid + 256] = row[tid + 256];
    __syncthreads();
    int c = tid & 31, g = tid >> 5;
    float a = 0.f;
    for (int k = g*64; k < (g+1)*64; k++) a = fmaf(sRow[k], Wp[(size_t)k*ADIM + c], a);
    part[g][c] = a;
    __syncthreads();
    if (tid < ADIM) {
        float s = bp[tid];
        #pragma unroll
        for (int g2 = 0; g2 < 8; g2++) s += part[g2][tid];
        out[(size_t)bt*ADIM + tid] = s;
    }
}

// ---------------- driver ----------------
extern "C" void kernel_launch(void* const* d_in, const int* in_sizes, int n_in,
                              void* d_out, int out_size)
{
    const int*   timesteps = (const int*)  d_in[0];
    const float* state_0   = (const float*)d_in[1];
    const float* state_1   = (const float*)d_in[2];
    const float* actions   = (const float*)d_in[3];
    const float* time_emb  = (const float*)d_in[4];
    const float* Ws  = (const float*)d_in[5];
    const float* bs  = (const float*)d_in[6];
    const float* Wa  = (const float*)d_in[7];
    const float* ba  = (const float*)d_in[8];
    const float* Wq  = (const float*)d_in[9];
    const float* bq  = (const float*)d_in[10];
    const float* Wk  = (const float*)d_in[11];
    const float* bk  = (const float*)d_in[12];
    const float* Wv  = (const float*)d_in[13];
    const float* bv  = (const float*)d_in[14];
    const float* Wo  = (const float*)d_in[15];
    const float* bo  = (const float*)d_in[16];
    const float* W1  = (const float*)d_in[17];
    const float* b1  = (const float*)d_in[18];
    const float* W2  = (const float*)d_in[19];
    const float* b2  = (const float*)d_in[20];
    const float* ln1_g = (const float*)d_in[21];
    const float* ln1_b = (const float*)d_in[22];
    const float* ln2_g = (const float*)d_in[23];
    const float* ln2_b = (const float*)d_in[24];
    const float* eln_g = (const float*)d_in[25];
    const float* eln_b = (const float*)d_in[26];
    const float* Wp  = (const float*)d_in[27];
    const float* bp  = (const float*)d_in[28];

    float *h, *q, *k, *v, *ctx, *xa, *ln1o, *pre2, *mlp;
    cudaGetSymbolAddress((void**)&h,    g_h);
    cudaGetSymbolAddress((void**)&q,    g_q);
    cudaGetSymbolAddress((void**)&k,    g_k);
    cudaGetSymbolAddress((void**)&v,    g_v);
    cudaGetSymbolAddress((void**)&ctx,  g_ctx);
    cudaGetSymbolAddress((void**)&xa,   g_xa);
    cudaGetSymbolAddress((void**)&ln1o, g_ln1);
    cudaGetSymbolAddress((void**)&pre2, g_pre2);
    cudaGetSymbolAddress((void**)&mlp,  g_mlp);

    cudaFuncSetAttribute(flash_kernel,
                         cudaFuncAttributeMaxDynamicSharedMemorySize, FLASH_SMEM);

    embed_kernel<<<BB*SS, 256>>>(timesteps, state_0, state_1, actions, time_emb,
                                 Ws, bs, Wa, ba, eln_g, eln_b, h);

    dim3 gQKV(HDIM/128, MROWS/128, 3);   // (4, 48, 3)
    dim3 gH64(HDIM/64,  MROWS/128);      // (8, 48)
    dim3 gF  (DFF /128, MROWS/128);      // (16, 48)
    dim3 gFl (SS/128, BB*NH);            // (12, 32)

    for (int blk = 0; blk < NBLK; blk++) {
        const float* Wq_ = Wq + (size_t)blk*HDIM*HDIM;
        const float* Wk_ = Wk + (size_t)blk*HDIM*HDIM;
        const float* Wv_ = Wv + (size_t)blk*HDIM*HDIM;
        const float* Wo_ = Wo + (size_t)blk*HDIM*HDIM;
        const float* W1_ = W1 + (size_t)blk*HDIM*DFF;
        const float* W2_ = W2 + (size_t)blk*DFF*HDIM;
        const float* bq_ = bq + (size_t)blk*HDIM;
        const float* bk_ = bk + (size_t)blk*HDIM;
        const float* bv_ = bv + (size_t)blk*HDIM;
        const float* bo_ = bo + (size_t)blk*HDIM;
        const float* b1_ = b1 + (size_t)blk*DFF;
        const float* b2_ = b2 + (size_t)blk*HDIM;
        const float* g1_ = ln1_g + (size_t)blk*HDIM;
        const float* e1_ = ln1_b + (size_t)blk*HDIM;
        const float* g2_ = ln2_g + (size_t)blk*HDIM;
        const float* e2_ = ln2_b + (size_t)blk*HDIM;

        qkv_kernel<<<gQKV, 256>>>(h, Wq_, Wk_, Wv_, bq_, bk_, bv_, q, k, v);

        flash_kernel<<<gFl, 256, FLASH_SMEM>>>(q, k, v, ctx);

        tgemm_kernel<64> <<<gH64, 256>>>(ctx, Wo_, bo_, h, xa, MROWS, HDIM, HDIM, EP_BIAS_RES);
        ln_kernel   <<<MROWS, 256>>>(xa, g1_, e1_, ln1o);
        tgemm_kernel<128><<<gF, 256>>>(ln1o, W1_, b1_, nullptr, mlp, MROWS, DFF, HDIM, EP_BIAS_GELU);
        tgemm_kernel<64> <<<gH64, 256>>>(mlp, W2_, b2_, ln1o, pre2, MROWS, HDIM, DFF, EP_BIAS_RES);
        ln_kernel   <<<MROWS, 256>>>(pre2, g2_, e2_, h);
    }

    final_kernel<<<BB*TT, 256>>>(h, Wp, bp, (float*)d_out);
}

// round 7
// speedup vs baseline: 2.4827x; 1.1730x over previous
#include <cuda_runtime.h>
#include <cuda_bf16.h>
#include <math.h>

#define BB 4
#define TT 512
#define SS 1536           // S = 3*T
#define SDIM 64
#define ADIM 32
#define HDIM 512
#define HPH 256           // HDIM/2 (uint2 per row)
#define NH 8
#define DH 64
#define NBLK 6
#define DFF 2048
#define DFFH 1024
#define MROWS (BB*SS)     // 6144

enum { EP_BIAS = 0, EP_BIAS_RES = 1, EP_GELU_SPLIT = 2, EP_BIAS_SPLIT = 3 };

// ---------------- scratch (static device globals; no runtime allocs) ----------
__device__ float g_h   [MROWS * HDIM];
__device__ float g_v   [MROWS * HDIM];
__device__ float g_xa  [MROWS * HDIM];
__device__ float g_ln1 [MROWS * HDIM];
__device__ float g_pre2[MROWS * HDIM];

__device__ uint2 g_hs  [MROWS * HPH];
__device__ uint2 g_qs  [MROWS * HPH];
__device__ uint2 g_ks  [MROWS * HPH];
__device__ uint2 g_ctxs[MROWS * HPH];
__device__ uint2 g_ln1s[MROWS * HPH];
__device__ uint2 g_mlps[MROWS * DFFH];

// split weights: Wq,Wk,Wv,Wo (6 x 256x512), W1 (6 x 256x2048), W2 (6 x 1024x512)
#define WQ0 0
#define WK0 786432
#define WV0 1572864
#define WO0 2359296
#define W10 3145728
#define W20 6291456
__device__ uint2 g_ws[9437184];

// ---------------- bf16 split helpers ----------------
__device__ __forceinline__ uint2 split2bf(float x0, float x1) {
    __nv_bfloat162 h = __floats2bfloat162_rn(x0, x1);
    float r0 = x0 - __bfloat162float(h.x);
    float r1 = x1 - __bfloat162float(h.y);
    __nv_bfloat162 l = __floats2bfloat162_rn(r0, r1);
    uint2 out;
    out.x = *reinterpret_cast<unsigned*>(&h);
    out.y = *reinterpret_cast<unsigned*>(&l);
    return out;
}

__device__ __forceinline__ void mma16(float c[4],
    unsigned a0, unsigned a1, unsigned a2, unsigned a3,
    unsigned b0, unsigned b1)
{
    asm volatile(
      "mma.sync.aligned.m16n8k16.row.col.f32.bf16.bf16.f32 "
      "{%0,%1,%2,%3},{%4,%5,%6,%7},{%8,%9},{%0,%1,%2,%3};"
      : "+f"(c[0]), "+f"(c[1]), "+f"(c[2]), "+f"(c[3])
      : "r"(a0), "r"(a1), "r"(a2), "r"(a3), "r"(b0), "r"(b1));
}

// ---------------- cp.async helpers ----------------
__device__ __forceinline__ void cpa16(void* smem, const void* gmem) {
    unsigned saddr = (unsigned)__cvta_generic_to_shared(smem);
    asm volatile("cp.async.cg.shared.global [%0], [%1], 16;" :: "r"(saddr), "l"(gmem));
}
#define CP_COMMIT() asm volatile("cp.async.commit_group;")
#define CP_WAIT0()  asm volatile("cp.async.wait_group 0;")

// ---------------- reductions ----------------
__device__ __forceinline__ float blockReduceSum(float v, float* sm) {
    int lane = threadIdx.x & 31, wid = threadIdx.x >> 5;
    #pragma unroll
    for (int o = 16; o; o >>= 1) v += __shfl_down_sync(0xffffffffu, v, o);
    if (lane == 0) sm[wid] = v;
    __syncthreads();
    float r = 0.f;
    if (wid == 0) {
        r = (lane < 8) ? sm[lane] : 0.f;
        #pragma unroll
        for (int o = 4; o; o >>= 1) r += __shfl_down_sync(0xffffffffu, r, o);
        if (lane == 0) sm[0] = r;
    }
    __syncthreads();
    r = sm[0];
    __syncthreads();
    return r;
}

// ---------------- weight split: W[k][n] -> Ws[k/2][n] ----------------
__global__ __launch_bounds__(256) void wsplit_kernel(
    const float* __restrict__ src, uint2* __restrict__ dst, int N)
{
    int n  = blockIdx.x * 256 + threadIdx.x;
    int kp = blockIdx.y;
    dst[(size_t)kp * N + n] =
        split2bf(src[(size_t)(2*kp) * N + n], src[(size_t)(2*kp + 1) * N + n]);
}

// ---------------- embedding + eLN ----------------
__global__ __launch_bounds__(256) void embed_kernel(
    const int* __restrict__ timesteps, const float* __restrict__ s0,
    const float* __restrict__ s1, const float* __restrict__ act,
    const float* __restrict__ temb,
    const float* __restrict__ Ws, const float* __restrict__ bs,
    const float* __restrict__ Wa, const float* __restrict__ ba,
    const float* __restrict__ eg, const float* __restrict__ eb,
    float* __restrict__ out, uint2* __restrict__ outs)
{
    int s = blockIdx.x;
    int b = s / SS, sr = s % SS;
    int t = sr / 3, r = sr % 3;

    __shared__ float sIn[SDIM];
    __shared__ float red[32];

    const float* inp; const float* W; const float* bias; int Kin;
    if (r == 0)      { inp = s0  + (size_t)(b*TT + t)*SDIM; W = Ws; bias = bs; Kin = SDIM; }
    else if (r == 1) { inp = s1  + (size_t)(b*TT + t)*SDIM; W = Ws; bias = bs; Kin = SDIM; }
    else             { inp = act + (size_t)(b*TT + t)*ADIM; W = Wa; bias = ba; Kin = ADIM; }

    int tid = threadIdx.x;
    if (tid < Kin) sIn[tid] = inp[tid];
    __syncthreads();

    int tsv = timesteps[b*TT + t];
    const float* te = temb + (size_t)tsv * HDIM;

    int c0 = 2*tid;
    float a0 = bias[c0] + te[c0], a1 = bias[c0+1] + te[c0+1];
    for (int k = 0; k < Kin; k++) {
        float x = sIn[k];
        a0 = fmaf(x, W[(size_t)k*HDIM + c0],     a0);
        a1 = fmaf(x, W[(size_t)k*HDIM + c0 + 1], a1);
    }
    float sum = blockReduceSum(a0 + a1, red);
    float m = sum * (1.0f / HDIM);
    float d0 = a0 - m, d1 = a1 - m;
    float ssq = blockReduceSum(d0*d0 + d1*d1, red);
    float rstd = rsqrtf(ssq * (1.0f / HDIM) + 1e-5f);
    float o0 = d0 * rstd * eg[c0]     + eb[c0];
    float o1 = d1 * rstd * eg[c0 + 1] + eb[c0 + 1];
    *(float2*)(out + (size_t)s*HDIM + c0) = make_float2(o0, o1);
    outs[(size_t)s*HPH + tid] = split2bf(o0, o1);
}

// ============ tensor-core GEMM (bf16x3, split operands, cp.async pipeline) =====
// A: [M][K/2] uint2 (hi,lo pairs along k). B: [K/2][N] uint2.
// 256 threads, tile 128xBN, BK=16 (8 kp), 2-stage smem double buffer.
template<int BN>
__device__ __forceinline__ void tgemm_body(
    const uint2* __restrict__ A, const uint2* __restrict__ B,
    const float* __restrict__ bias, const float* __restrict__ res,
    float* __restrict__ C, uint2* __restrict__ Cs,
    int M, int N, int K, int ep)
{
    constexpr int TNF = BN / 32;
    constexpr int BST = BN + 4;            // B row stride (uint2): 132 / 68
    __shared__ uint2 As[2][128][12];       // [stage][m][kp] pad to 12
    __shared__ uint2 Bs[2][8][BST];        // [stage][kp][n]

    const int tid  = threadIdx.x, lane = tid & 31, warp = tid >> 5;
    const int g    = lane >> 2,  tg   = lane & 3;
    const int wm0  = (warp >> 2) * 64, wn0 = (warp & 3) * (BN / 4);
    const int m0   = blockIdx.y * 128, n0 = blockIdx.x * BN;
    const int KH   = K >> 1;

    // chunk decompositions (16B = 2 uint2)
    const int am  = tid >> 2, aci = (tid & 3) * 2;          // A: 256 chunks x2
    const int bk1 = tid >> 6, bc1 = (tid & 63) * 2;         // BN=128: 512 chunks
    const int bk2 = tid >> 5, bc2 = (tid & 31) * 2;         // BN=64 : 256 chunks

    float acc[4][TNF][4];
    #pragma unroll
    for (int i = 0; i < 4; i++)
        #pragma unroll
        for (int j = 0; j < TNF; j++)
            #pragma unroll
            for (int l = 0; l < 4; l++) acc[i][j][l] = 0.f;

    const int T = K / 16;

    auto issue = [&](int t, int s) {
        int kh0 = t * 8;
        cpa16(&As[s][am][aci],        A + (size_t)(m0 + am)*KH       + kh0 + aci);
        cpa16(&As[s][am + 64][aci],   A + (size_t)(m0 + am + 64)*KH  + kh0 + aci);
        if (BN == 128) {
            cpa16(&Bs[s][bk1][bc1],       B + (size_t)(kh0 + bk1)*N     + n0 + bc1);
            cpa16(&Bs[s][bk1 + 4][bc1],   B + (size_t)(kh0 + bk1 + 4)*N + n0 + bc1);
        } else {
            cpa16(&Bs[s][bk2][bc2],       B + (size_t)(kh0 + bk2)*N     + n0 + bc2);
        }
        CP_COMMIT();
    };

    issue(0, 0);

    for (int t = 0; t < T; t++) {
        const int s = t & 1;
        CP_WAIT0();
        __syncthreads();
        if (t + 1 < T) issue(t + 1, s ^ 1);

        uint2 bf[TNF][2];
        #pragma unroll
        for (int tn = 0; tn < TNF; tn++) {
            int n = wn0 + tn*8 + g;
            bf[tn][0] = Bs[s][tg][n];
            bf[tn][1] = Bs[s][tg+4][n];
        }
        #pragma unroll
        for (int tm = 0; tm < 4; tm++) {
            int m = wm0 + tm*16 + g;
            uint2 a0 = As[s][m][tg],     a1 = As[s][m+8][tg];
            uint2 a2 = As[s][m][tg+4],   a3 = As[s][m+8][tg+4];
            #pragma unroll
            for (int tn = 0; tn < TNF; tn++) {
                mma16(acc[tm][tn], a0.x,a1.x,a2.x,a3.x, bf[tn][0].x, bf[tn][1].x);
                mma16(acc[tm][tn], a0.y,a1.y,a2.y,a3.y, bf[tn][0].x, bf[tn][1].x);
                mma16(acc[tm][tn], a0.x,a1.x,a2.x,a3.x, bf[tn][0].y, bf[tn][1].y);
            }
        }
        __syncthreads();
    }

    #pragma unroll
    for (int tm = 0; tm < 4; tm++) {
        #pragma unroll
        for (int tn = 0; tn < TNF; tn++) {
            int row = m0 + wm0 + tm*16 + g;
            int col = n0 + wn0 + tn*8 + tg*2;
            float b0v = bias[col], b1v = bias[col+1];
            float v00 = acc[tm][tn][0] + b0v, v01 = acc[tm][tn][1] + b1v;
            float v10 = acc[tm][tn][2] + b0v, v11 = acc[tm][tn][3] + b1v;
            if (ep == EP_BIAS_RES) {
                v00 += res[(size_t)row*N + col];     v01 += res[(size_t)row*N + col + 1];
                v10 += res[(size_t)(row+8)*N + col]; v11 += res[(size_t)(row+8)*N + col + 1];
                *(float2*)(C + (size_t)row*N + col)     = make_float2(v00, v01);
                *(float2*)(C + (size_t)(row+8)*N + col) = make_float2(v10, v11);
            } else if (ep == EP_BIAS) {
                *(float2*)(C + (size_t)row*N + col)     = make_float2(v00, v01);
                *(float2*)(C + (size_t)(row+8)*N + col) = make_float2(v10, v11);
            } else {
                if (ep == EP_GELU_SPLIT) {
                    v00 = 0.5f*v00*(1.0f + erff(v00*0.70710678118654752f));
                    v01 = 0.5f*v01*(1.0f + erff(v01*0.70710678118654752f));
                    v10 = 0.5f*v10*(1.0f + erff(v10*0.70710678118654752f));
                    v11 = 0.5f*v11*(1.0f + erff(v11*0.70710678118654752f));
                }
                Cs[(size_t)row*(N>>1)     + (col>>1)] = split2bf(v00, v01);
                Cs[(size_t)(row+8)*(N>>1) + (col>>1)] = split2bf(v10, v11);
            }
        }
    }
}

template<int BN>
__global__ __launch_bounds__(256) void tgemm_kernel(
    const uint2* __restrict__ A, const uint2* __restrict__ B,
    const float* __restrict__ bias, const float* __restrict__ res,
    float* __restrict__ C, uint2* __restrict__ Cs,
    int M, int N, int K, int ep)
{
    tgemm_body<BN>(A, B, bias, res, C, Cs, M, N, K, ep);
}

// fused QKV: blockIdx.z selects the projection (q,k -> split; v -> fp32)
__global__ __launch_bounds__(256) void qkv_kernel(
    const uint2* __restrict__ hs,
    const uint2* __restrict__ wq, const uint2* __restrict__ wk, const uint2* __restrict__ wv,
    const float* __restrict__ bq, const float* __restrict__ bk, const float* __restrict__ bv,
    uint2* __restrict__ qs, uint2* __restrict__ ks, float* __restrict__ v)
{
    if (blockIdx.z == 0)
        tgemm_body<128>(hs, wq, bq, nullptr, nullptr, qs, MROWS, HDIM, HDIM, EP_BIAS_SPLIT);
    else if (blockIdx.z == 1)
        tgemm_body<128>(hs, wk, bk, nullptr, nullptr, ks, MROWS, HDIM, HDIM, EP_BIAS_SPLIT);
    else
        tgemm_body<128>(hs, wv, bv, nullptr, v, nullptr, MROWS, HDIM, HDIM, EP_BIAS);
}

// ================= flash attention (split Q/K inputs, split ctx output) ========
#define FLASH_KPAD 132
#define FLASH_VPAD 68
#define FLASH_SMEM ((32*FLASH_KPAD + 64*FLASH_VPAD) * (int)sizeof(uint2))

__global__ __launch_bounds__(256) void flash_kernel(
    const uint2* __restrict__ q, const uint2* __restrict__ k,
    const float* __restrict__ v, uint2* __restrict__ ctxs)
{
    extern __shared__ uint2 dsmem[];
    uint2 (*Ks)[FLASH_KPAD] = reinterpret_cast<uint2(*)[FLASH_KPAD]>(dsmem);
    uint2 (*Vs)[FLASH_VPAD] = reinterpret_cast<uint2(*)[FLASH_VPAD]>(dsmem + 32*FLASH_KPAD);

    const int it = (int)(gridDim.x - 1 - blockIdx.x);
    const int bh = blockIdx.y, b = bh >> 3, h = bh & 7;
    const uint2* qb = q + (size_t)b*SS*HPH + h*32;
    const uint2* kb = k + (size_t)b*SS*HPH + h*32;
    const float* vb = v + (size_t)b*SS*HDIM + h*DH;
    uint2* cb       = ctxs + (size_t)b*SS*HPH + h*32;

    const int tid  = threadIdx.x, lane = tid & 31, warp = tid >> 5;
    const int g    = lane >> 2,  tg   = lane & 3;
    const int i0   = it * 128;
    const int rowg = i0 + warp*16 + g;

    // Q fragments straight from split gmem
    uint2 qf[4][4];
    {
        const uint2* qrg = qb + (size_t)rowg*HPH;
        const uint2* qr8 = qrg + 8*HPH;
        #pragma unroll
        for (int kk = 0; kk < 4; kk++) {
            qf[kk][0] = qrg[kk*8 + tg];
            qf[kk][1] = qr8[kk*8 + tg];
            qf[kk][2] = qrg[kk*8 + tg + 4];
            qf[kk][3] = qr8[kk*8 + tg + 4];
        }
    }

    float m0 = -1e30f, m1 = -1e30f, l0 = 0.f, l1 = 0.f;
    float o[8][4];
    #pragma unroll
    for (int nf = 0; nf < 8; nf++)
        #pragma unroll
        for (int l = 0; l < 4; l++) o[nf][l] = 0.f;

    const int kjr = tid >> 1, kcb = (tid & 1)*16;   // K loader: row, kp base
    const int vjp = tid >> 2, vcb = (tid & 3)*16;   // V loader: row pair, col base

    for (int jt = 0; jt <= it; jt++) {
        const int j0 = jt * 128;
        {   // K tile: copy split uint2, transpose to [kp][j]
            const uint2* krow = kb + (size_t)(j0 + kjr)*HPH + kcb;
            #pragma unroll
            for (int u = 0; u < 8; u++) {
                uint4 f = ((const uint4*)krow)[u];
                Ks[kcb + 2*u][kjr]     = make_uint2(f.x, f.y);
                Ks[kcb + 2*u + 1][kjr] = make_uint2(f.z, f.w);
            }
        }
        {   // V tile: fp32 -> (rowpair) split
            const float* vr0 = vb + (size_t)(j0 + 2*vjp)*HDIM + vcb;
            const float* vr1 = vr0 + HDIM;
            #pragma unroll
            for (int u = 0; u < 4; u++) {
                float4 f0 = *(const float4*)(vr0 + u*4);
                float4 f1 = *(const float4*)(vr1 + u*4);
                Vs[vjp][vcb + u*4 + 0] = split2bf(f0.x, f1.x);
                Vs[vjp][vcb + u*4 + 1] = split2bf(f0.y, f1.y);
                Vs[vjp][vcb + u*4 + 2] = split2bf(f0.z, f1.z);
                Vs[vjp][vcb + u*4 + 3] = split2bf(f0.w, f1.w);
            }
        }
        __syncthreads();

        float s[16][4];
        #pragma unroll
        for (int jf = 0; jf < 16; jf++)
            #pragma unroll
            for (int l = 0; l < 4; l++) s[jf][l] = 0.f;

        #pragma unroll
        for (int kk = 0; kk < 4; kk++) {
            uint2 a0 = qf[kk][0], a1 = qf[kk][1], a2 = qf[kk][2], a3 = qf[kk][3];
            #pragma unroll
            for (int jf = 0; jf < 16; jf++) {
                uint2 b0 = Ks[kk*8 + tg][jf*8 + g];
                uint2 b1 = Ks[kk*8 + tg + 4][jf*8 + g];
                mma16(s[jf], a0.x,a1.x,a2.x,a3.x, b0.x, b1.x);
                mma16(s[jf], a0.y,a1.y,a2.y,a3.y, b0.x, b1.x);
                mma16(s[jf], a0.x,a1.x,a2.x,a3.x, b0.y, b1.y);
            }
        }

        const float scale = 0.125f;
        if (jt == it) {
            const int r0 = warp*16 + g, r1 = r0 + 8;
            #pragma unroll
            for (int jf = 0; jf < 16; jf++) {
                int c0 = jf*8 + 2*tg;
                s[jf][0] = (c0     <= r0) ? s[jf][0]*scale : -1e30f;
                s[jf][1] = (c0 + 1 <= r0) ? s[jf][1]*scale : -1e30f;
                s[jf][2] = (c0     <= r1) ? s[jf][2]*scale : -1e30f;
                s[jf][3] = (c0 + 1 <= r1) ? s[jf][3]*scale : -1e30f;
            }
        } else {
            #pragma unroll
            for (int jf = 0; jf < 16; jf++) {
                s[jf][0] *= scale; s[jf][1] *= scale;
                s[jf][2] *= scale; s[jf][3] *= scale;
            }
        }

        float tm0 = -1e30f, tm1 = -1e30f;
        #pragma unroll
        for (int jf = 0; jf < 16; jf++) {
            tm0 = fmaxf(tm0, fmaxf(s[jf][0], s[jf][1]));
            tm1 = fmaxf(tm1, fmaxf(s[jf][2], s[jf][3]));
        }
        tm0 = fmaxf(tm0, __shfl_xor_sync(0xffffffffu, tm0, 1));
        tm0 = fmaxf(tm0, __shfl_xor_sync(0xffffffffu, tm0, 2));
        tm1 = fmaxf(tm1, __shfl_xor_sync(0xffffffffu, tm1, 1));
        tm1 = fmaxf(tm1, __shfl_xor_sync(0xffffffffu, tm1, 2));

        float nm0 = fmaxf(m0, tm0), nm1 = fmaxf(m1, tm1);
        float al0 = __expf(m0 - nm0), al1 = __expf(m1 - nm1);
        m0 = nm0; m1 = nm1;

        float rs0 = 0.f, rs1 = 0.f;
        #pragma unroll
        for (int jf = 0; jf < 16; jf++) {
            s[jf][0] = __expf(s[jf][0] - nm0);
            s[jf][1] = __expf(s[jf][1] - nm0);
            s[jf][2] = __expf(s[jf][2] - nm1);
            s[jf][3] = __expf(s[jf][3] - nm1);
            rs0 += s[jf][0] + s[jf][1];
            rs1 += s[jf][2] + s[jf][3];
        }
        rs0 += __shfl_xor_sync(0xffffffffu, rs0, 1);
        rs0 += __shfl_xor_sync(0xffffffffu, rs0, 2);
        rs1 += __shfl_xor_sync(0xffffffffu, rs1, 1);
        rs1 += __shfl_xor_sync(0xffffffffu, rs1, 2);
        l0 = l0*al0 + rs0;
        l1 = l1*al1 + rs1;

        #pragma unroll
        for (int nf = 0; nf < 8; nf++) {
            o[nf][0] *= al0; o[nf][1] *= al0;
            o[nf][2] *= al1; o[nf][3] *= al1;
        }

        #pragma unroll
        for (int kk = 0; kk < 8; kk++) {
            uint2 A0 = split2bf(s[2*kk][0],   s[2*kk][1]);
            uint2 A1 = split2bf(s[2*kk][2],   s[2*kk][3]);
            uint2 A2 = split2bf(s[2*kk+1][0], s[2*kk+1][1]);
            uint2 A3 = split2bf(s[2*kk+1][2], s[2*kk+1][3]);
            #pragma unroll
            for (int nf = 0; nf < 8; nf++) {
                uint2 b0 = Vs[kk*8 + tg][nf*8 + g];
                uint2 b1 = Vs[kk*8 + tg + 4][nf*8 + g];
                mma16(o[nf], A0.x,A1.x,A2.x,A3.x, b0.x, b1.x);
                mma16(o[nf], A0.y,A1.y,A2.y,A3.y, b0.x, b1.x);
                mma16(o[nf], A0.x,A1.x,A2.x,A3.x, b0.y, b1.y);
            }
        }
        __syncthreads();
    }

    float inv0 = 1.0f / l0, inv1 = 1.0f / l1;
    uint2* crow0 = cb + (size_t)rowg*HPH;
    uint2* crow1 = crow0 + 8*HPH;
    #pragma unroll
    for (int nf = 0; nf < 8; nf++) {
        crow0[nf*4 + tg] = split2bf(o[nf][0]*inv0, o[nf][1]*inv0);
        crow1[nf*4 + tg] = split2bf(o[nf][2]*inv1, o[nf][3]*inv1);
    }
}

// ---------------- layernorm over HDIM, fp32 + split outputs -------------------
__global__ __launch_bounds__(256) void ln_kernel(
    const float* __restrict__ x, const float* __restrict__ g,
    const float* __restrict__ b, float* __restrict__ out,
    uint2* __restrict__ outs)
{
    int row = blockIdx.x;
    __shared__ float red[32];
    int tid = threadIdx.x;
    int c0 = 2*tid;
    float2 xv = *(const float2*)(x + (size_t)row*HDIM + c0);
    float sum = blockReduceSum(xv.x + xv.y, red);
    float m = sum * (1.0f / HDIM);
    float d0 = xv.x - m, d1 = xv.y - m;
    float ssq = blockReduceSum(d0*d0 + d1*d1, red);
    float rstd = rsqrtf(ssq * (1.0f / HDIM) + 1e-5f);
    float o0 = d0 * rstd * g[c0]     + b[c0];
    float o1 = d1 * rstd * g[c0 + 1] + b[c0 + 1];
    *(float2*)(out + (size_t)row*HDIM + c0) = make_float2(o0, o1);
    outs[(size_t)row*HPH + tid] = split2bf(o0, o1);
}

// ---------------- final projection: out = h[:, :, 1] @ Wp + bp ----------------
__global__ __launch_bounds__(256) void final_kernel(
    const float* __restrict__ h, const float* __restrict__ Wp,
    const float* __restrict__ bp, float* __restrict__ out)
{
    int bt = blockIdx.x;
    int b = bt / TT, t = bt % TT;
    const float* row = h + ((size_t)b*SS + 3*t + 1) * HDIM;
    __shared__ float sRow[HDIM];
    __shared__ float part[8][ADIM];
    int tid = threadIdx.x;
    sRow[tid] = row[tid];
    sRow[tid + 256] = row[tid + 256];
    __syncthreads();
    int c = tid & 31, g = tid >> 5;
    float a = 0.f;
    for (int k = g*64; k < (g+1)*64; k++) a = fmaf(sRow[k], Wp[(size_t)k*ADIM + c], a);
    part[g][c] = a;
    __syncthreads();
    if (tid < ADIM) {
        float s = bp[tid];
        #pragma unroll
        for (int g2 = 0; g2 < 8; g2++) s += part[g2][tid];
        out[(size_t)bt*ADIM + tid] = s;
    }
}

// ---------------- driver ----------------
extern "C" void kernel_launch(void* const* d_in, const int* in_sizes, int n_in,
                              void* d_out, int out_size)
{
    const int*   timesteps = (const int*)  d_in[0];
    const float* state_0   = (const float*)d_in[1];
    const float* state_1   = (const float*)d_in[2];
    const float* actions   = (const float*)d_in[3];
    const float* time_emb  = (const float*)d_in[4];
    const float* Ws  = (const float*)d_in[5];
    const float* bs  = (const float*)d_in[6];
    const float* Wa  = (const float*)d_in[7];
    const float* ba  = (const float*)d_in[8];
    const float* Wq  = (const float*)d_in[9];
    const float* bq  = (const float*)d_in[10];
    const float* Wk  = (const float*)d_in[11];
    const float* bk  = (const float*)d_in[12];
    const float* Wv  = (const float*)d_in[13];
    const float* bv  = (const float*)d_in[14];
    const float* Wo  = (const float*)d_in[15];
    const float* bo  = (const float*)d_in[16];
    const float* W1  = (const float*)d_in[17];
    const float* b1  = (const float*)d_in[18];
    const float* W2  = (const float*)d_in[19];
    const float* b2  = (const float*)d_in[20];
    const float* ln1_g = (const float*)d_in[21];
    const float* ln1_b = (const float*)d_in[22];
    const float* ln2_g = (const float*)d_in[23];
    const float* ln2_b = (const float*)d_in[24];
    const float* eln_g = (const float*)d_in[25];
    const float* eln_b = (const float*)d_in[26];
    const float* Wp  = (const float*)d_in[27];
    const float* bp  = (const float*)d_in[28];

    float *h, *v, *xa, *ln1o, *pre2;
    uint2 *hs, *qs, *ks, *ctxs, *ln1s, *mlps, *ws;
    cudaGetSymbolAddress((void**)&h,    g_h);
    cudaGetSymbolAddress((void**)&v,    g_v);
    cudaGetSymbolAddress((void**)&xa,   g_xa);
    cudaGetSymbolAddress((void**)&ln1o, g_ln1);
    cudaGetSymbolAddress((void**)&pre2, g_pre2);
    cudaGetSymbolAddress((void**)&hs,   g_hs);
    cudaGetSymbolAddress((void**)&qs,   g_qs);
    cudaGetSymbolAddress((void**)&ks,   g_ks);
    cudaGetSymbolAddress((void**)&ctxs, g_ctxs);
    cudaGetSymbolAddress((void**)&ln1s, g_ln1s);
    cudaGetSymbolAddress((void**)&mlps, g_mlps);
    cudaGetSymbolAddress((void**)&ws,   g_ws);

    cudaFuncSetAttribute(flash_kernel,
                         cudaFuncAttributeMaxDynamicSharedMemorySize, FLASH_SMEM);

    // ---- pre-split all weights (once per launch) ----
    wsplit_kernel<<<dim3(HDIM/256, NBLK*HDIM/2), 256>>>(Wq, ws + WQ0, HDIM);
    wsplit_kernel<<<dim3(HDIM/256, NBLK*HDIM/2), 256>>>(Wk, ws + WK0, HDIM);
    wsplit_kernel<<<dim3(HDIM/256, NBLK*HDIM/2), 256>>>(Wv, ws + WV0, HDIM);
    wsplit_kernel<<<dim3(HDIM/256, NBLK*HDIM/2), 256>>>(Wo, ws + WO0, HDIM);
    wsplit_kernel<<<dim3(DFF/256,  NBLK*HDIM/2), 256>>>(W1, ws + W10, DFF);
    wsplit_kernel<<<dim3(HDIM/256, NBLK*DFF/2),  256>>>(W2, ws + W20, HDIM);

    embed_kernel<<<BB*SS, 256>>>(timesteps, state_0, state_1, actions, time_emb,
                                 Ws, bs, Wa, ba, eln_g, eln_b, h, hs);

    dim3 gQKV(HDIM/128, MROWS/128, 3);   // (4, 48, 3)
    dim3 gH64(HDIM/64,  MROWS/128);      // (8, 48)
    dim3 gF  (DFF /128, MROWS/128);      // (16, 48)
    dim3 gFl (SS/128, BB*NH);            // (12, 32)

    for (int blk = 0; blk < NBLK; blk++) {
        const uint2* wqs = ws + WQ0 + (size_t)blk*131072;
        const uint2* wks = ws + WK0 + (size_t)blk*131072;
        const uint2* wvs = ws + WV0 + (size_t)blk*131072;
        const uint2* wos = ws + WO0 + (size_t)blk*131072;
        const uint2* w1s = ws + W10 + (size_t)blk*524288;
        const uint2* w2s = ws + W20 + (size_t)blk*524288;
        const float* bq_ = bq + (size_t)blk*HDIM;
        const float* bk_ = bk + (size_t)blk*HDIM;
        const float* bv_ = bv + (size_t)blk*HDIM;
        const float* bo_ = bo + (size_t)blk*HDIM;
        const float* b1_ = b1 + (size_t)blk*DFF;
        const float* b2_ = b2 + (size_t)blk*HDIM;
        const float* g1_ = ln1_g + (size_t)blk*HDIM;
        const float* e1_ = ln1_b + (size_t)blk*HDIM;
        const float* g2_ = ln2_g + (size_t)blk*HDIM;
        const float* e2_ = ln2_b + (size_t)blk*HDIM;

        qkv_kernel<<<gQKV, 256>>>(hs, wqs, wks, wvs, bq_, bk_, bv_, qs, ks, v);

        flash_kernel<<<gFl, 256, FLASH_SMEM>>>(qs, ks, v, ctxs);

        tgemm_kernel<64> <<<gH64, 256>>>(ctxs, wos, bo_, h, xa, nullptr,
                                         MROWS, HDIM, HDIM, EP_BIAS_RES);
        ln_kernel<<<MROWS, 256>>>(xa, g1_, e1_, ln1o, ln1s);
        tgemm_kernel<128><<<gF, 256>>>(ln1s, w1s, b1_, nullptr, nullptr, mlps,
                                       MROWS, DFF, HDIM, EP_GELU_SPLIT);
        tgemm_kernel<64> <<<gH64, 256>>>(mlps, w2s, b2_, ln1o, pre2, nullptr,
                                         MROWS, HDIM, DFF, EP_BIAS_RES);
        ln_kernel<<<MROWS, 256>>>(pre2, g2_, e2_, h, hs);
    }

    final_kernel<<<BB*TT, 256>>>(h, Wp, bp, (float*)d_out);
}

// round 8
// speedup vs baseline: 2.4902x; 1.0030x over previous
#include <cuda_runtime.h>
#include <cuda_bf16.h>
#include <math.h>

#define BB 4
#define TT 512
#define SS 1536           // S = 3*T
#define SDIM 64
#define ADIM 32
#define HDIM 512
#define HPH 256           // HDIM/2 (uint2 per row)
#define NH 8
#define DH 64
#define NBLK 6
#define DFF 2048
#define DFFH 1024
#define MROWS (BB*SS)     // 6144

enum { EP_BIAS = 0, EP_BIAS_RES = 1, EP_GELU_SPLIT = 2, EP_BIAS_SPLIT = 3 };

// ---------------- scratch (static device globals; no runtime allocs) ----------
__device__ float g_h   [MROWS * HDIM];
__device__ float g_v   [MROWS * HDIM];
__device__ float g_xa  [MROWS * HDIM];
__device__ float g_ln1 [MROWS * HDIM];
__device__ float g_pre2[MROWS * HDIM];

__device__ uint2 g_hs  [MROWS * HPH];
__device__ uint2 g_qs  [MROWS * HPH];
__device__ uint2 g_ks  [MROWS * HPH];
__device__ uint2 g_ctxs[MROWS * HPH];
__device__ uint2 g_ln1s[MROWS * HPH];
__device__ uint2 g_mlps[MROWS * DFFH];

// split weights: Wq,Wk,Wv,Wo (6 x 256x512), W1 (6 x 256x2048), W2 (6 x 1024x512)
#define WQ0 0
#define WK0 786432
#define WV0 1572864
#define WO0 2359296
#define W10 3145728
#define W20 6291456
__device__ uint2 g_ws[9437184];

// ---------------- bf16 split helpers ----------------
__device__ __forceinline__ uint2 split2bf(float x0, float x1) {
    __nv_bfloat162 h = __floats2bfloat162_rn(x0, x1);
    float r0 = x0 - __bfloat162float(h.x);
    float r1 = x1 - __bfloat162float(h.y);
    __nv_bfloat162 l = __floats2bfloat162_rn(r0, r1);
    uint2 out;
    out.x = *reinterpret_cast<unsigned*>(&h);
    out.y = *reinterpret_cast<unsigned*>(&l);
    return out;
}

__device__ __forceinline__ void mma16(float c[4],
    unsigned a0, unsigned a1, unsigned a2, unsigned a3,
    unsigned b0, unsigned b1)
{
    asm volatile(
      "mma.sync.aligned.m16n8k16.row.col.f32.bf16.bf16.f32 "
      "{%0,%1,%2,%3},{%4,%5,%6,%7},{%8,%9},{%0,%1,%2,%3};"
      : "+f"(c[0]), "+f"(c[1]), "+f"(c[2]), "+f"(c[3])
      : "r"(a0), "r"(a1), "r"(a2), "r"(a3), "r"(b0), "r"(b1));
}

// ---------------- cp.async helpers ----------------
__device__ __forceinline__ void cpa16(void* smem, const void* gmem) {
    unsigned saddr = (unsigned)__cvta_generic_to_shared(smem);
    asm volatile("cp.async.cg.shared.global [%0], [%1], 16;" :: "r"(saddr), "l"(gmem));
}
#define CP_COMMIT() asm volatile("cp.async.commit_group;")
#define CP_WAIT0()  asm volatile("cp.async.wait_group 0;")

// ---------------- reductions ----------------
__device__ __forceinline__ float blockReduceSum(float v, float* sm) {
    int lane = threadIdx.x & 31, wid = threadIdx.x >> 5;
    #pragma unroll
    for (int o = 16; o; o >>= 1) v += __shfl_down_sync(0xffffffffu, v, o);
    if (lane == 0) sm[wid] = v;
    __syncthreads();
    float r = 0.f;
    if (wid == 0) {
        r = (lane < 8) ? sm[lane] : 0.f;
        #pragma unroll
        for (int o = 4; o; o >>= 1) r += __shfl_down_sync(0xffffffffu, r, o);
        if (lane == 0) sm[0] = r;
    }
    __syncthreads();
    r = sm[0];
    __syncthreads();
    return r;
}

// ---------------- weight split: W[k][n] -> Ws[k/2][n] ----------------
__global__ __launch_bounds__(256) void wsplit_kernel(
    const float* __restrict__ src, uint2* __restrict__ dst, int N)
{
    int n  = blockIdx.x * 256 + threadIdx.x;
    int kp = blockIdx.y;
    dst[(size_t)kp * N + n] =
        split2bf(src[(size_t)(2*kp) * N + n], src[(size_t)(2*kp + 1) * N + n]);
}

// ---------------- embedding + eLN ----------------
__global__ __launch_bounds__(256) void embed_kernel(
    const int* __restrict__ timesteps, const float* __restrict__ s0,
    const float* __restrict__ s1, const float* __restrict__ act,
    const float* __restrict__ temb,
    const float* __restrict__ Ws, const float* __restrict__ bs,
    const float* __restrict__ Wa, const float* __restrict__ ba,
    const float* __restrict__ eg, const float* __restrict__ eb,
    float* __restrict__ out, uint2* __restrict__ outs)
{
    int s = blockIdx.x;
    int b = s / SS, sr = s % SS;
    int t = sr / 3, r = sr % 3;

    __shared__ float sIn[SDIM];
    __shared__ float red[32];

    const float* inp; const float* W; const float* bias; int Kin;
    if (r == 0)      { inp = s0  + (size_t)(b*TT + t)*SDIM; W = Ws; bias = bs; Kin = SDIM; }
    else if (r == 1) { inp = s1  + (size_t)(b*TT + t)*SDIM; W = Ws; bias = bs; Kin = SDIM; }
    else             { inp = act + (size_t)(b*TT + t)*ADIM; W = Wa; bias = ba; Kin = ADIM; }

    int tid = threadIdx.x;
    if (tid < Kin) sIn[tid] = inp[tid];
    __syncthreads();

    int tsv = timesteps[b*TT + t];
    const float* te = temb + (size_t)tsv * HDIM;

    int c0 = 2*tid;
    float a0 = bias[c0] + te[c0], a1 = bias[c0+1] + te[c0+1];
    for (int k = 0; k < Kin; k++) {
        float x = sIn[k];
        a0 = fmaf(x, W[(size_t)k*HDIM + c0],     a0);
        a1 = fmaf(x, W[(size_t)k*HDIM + c0 + 1], a1);
    }
    float sum = blockReduceSum(a0 + a1, red);
    float m = sum * (1.0f / HDIM);
    float d0 = a0 - m, d1 = a1 - m;
    float ssq = blockReduceSum(d0*d0 + d1*d1, red);
    float rstd = rsqrtf(ssq * (1.0f / HDIM) + 1e-5f);
    float o0 = d0 * rstd * eg[c0]     + eb[c0];
    float o1 = d1 * rstd * eg[c0 + 1] + eb[c0 + 1];
    *(float2*)(out + (size_t)s*HDIM + c0) = make_float2(o0, o1);
    outs[(size_t)s*HPH + tid] = split2bf(o0, o1);
}

// ============ tensor-core GEMM (bf16x3, split operands, cp.async pipeline) =====
// A: [M][K/2] uint2 (hi,lo pairs along k). B: [K/2][N] uint2.
// 256 threads, tile 128xBN, BK=16 (8 kp), 2-stage smem double buffer.
template<int BN>
__device__ __forceinline__ void tgemm_body(
    const uint2* __restrict__ A, const uint2* __restrict__ B,
    const float* __restrict__ bias, const float* __restrict__ res,
    float* __restrict__ C, uint2* __restrict__ Cs,
    int M, int N, int K, int ep)
{
    constexpr int TNF = BN / 32;
    constexpr int BST = BN + 4;            // B row stride (uint2): 132 / 68
    __shared__ uint2 As[2][128][12];       // [stage][m][kp] pad to 12
    __shared__ uint2 Bs[2][8][BST];        // [stage][kp][n]

    const int tid  = threadIdx.x, lane = tid & 31, warp = tid >> 5;
    const int g    = lane >> 2,  tg   = lane & 3;
    const int wm0  = (warp >> 2) * 64, wn0 = (warp & 3) * (BN / 4);
    const int m0   = blockIdx.y * 128, n0 = blockIdx.x * BN;
    const int KH   = K >> 1;

    // chunk decompositions (16B = 2 uint2)
    const int am  = tid >> 2, aci = (tid & 3) * 2;          // A: 256 chunks x2
    const int bk1 = tid >> 6, bc1 = (tid & 63) * 2;         // BN=128: 512 chunks
    const int bk2 = tid >> 5, bc2 = (tid & 31) * 2;         // BN=64 : 256 chunks

    float acc[4][TNF][4];
    #pragma unroll
    for (int i = 0; i < 4; i++)
        #pragma unroll
        for (int j = 0; j < TNF; j++)
            #pragma unroll
            for (int l = 0; l < 4; l++) acc[i][j][l] = 0.f;

    const int T = K / 16;

    auto issue = [&](int t, int s) {
        int kh0 = t * 8;
        cpa16(&As[s][am][aci],        A + (size_t)(m0 + am)*KH       + kh0 + aci);
        cpa16(&As[s][am + 64][aci],   A + (size_t)(m0 + am + 64)*KH  + kh0 + aci);
        if (BN == 128) {
            cpa16(&Bs[s][bk1][bc1],       B + (size_t)(kh0 + bk1)*N     + n0 + bc1);
            cpa16(&Bs[s][bk1 + 4][bc1],   B + (size_t)(kh0 + bk1 + 4)*N + n0 + bc1);
        } else {
            cpa16(&Bs[s][bk2][bc2],       B + (size_t)(kh0 + bk2)*N     + n0 + bc2);
        }
        CP_COMMIT();
    };

    issue(0, 0);

    for (int t = 0; t < T; t++) {
        const int s = t & 1;
        CP_WAIT0();
        __syncthreads();
        if (t + 1 < T) issue(t + 1, s ^ 1);

        uint2 bf[TNF][2];
        #pragma unroll
        for (int tn = 0; tn < TNF; tn++) {
            int n = wn0 + tn*8 + g;
            bf[tn][0] = Bs[s][tg][n];
            bf[tn][1] = Bs[s][tg+4][n];
        }
        #pragma unroll
        for (int tm = 0; tm < 4; tm++) {
            int m = wm0 + tm*16 + g;
            uint2 a0 = As[s][m][tg],     a1 = As[s][m+8][tg];
            uint2 a2 = As[s][m][tg+4],   a3 = As[s][m+8][tg+4];
            #pragma unroll
            for (int tn = 0; tn < TNF; tn++) {
                mma16(acc[tm][tn], a0.x,a1.x,a2.x,a3.x, bf[tn][0].x, bf[tn][1].x);
                mma16(acc[tm][tn], a0.y,a1.y,a2.y,a3.y, bf[tn][0].x, bf[tn][1].x);
                mma16(acc[tm][tn], a0.x,a1.x,a2.x,a3.x, bf[tn][0].y, bf[tn][1].y);
            }
        }
        __syncthreads();
    }

    #pragma unroll
    for (int tm = 0; tm < 4; tm++) {
        #pragma unroll
        for (int tn = 0; tn < TNF; tn++) {
            int row = m0 + wm0 + tm*16 + g;
            int col = n0 + wn0 + tn*8 + tg*2;
            float b0v = bias[col], b1v = bias[col+1];
            float v00 = acc[tm][tn][0] + b0v, v01 = acc[tm][tn][1] + b1v;
            float v10 = acc[tm][tn][2] + b0v, v11 = acc[tm][tn][3] + b1v;
            if (ep == EP_BIAS_RES) {
                v00 += res[(size_t)row*N + col];     v01 += res[(size_t)row*N + col + 1];
                v10 += res[(size_t)(row+8)*N + col]; v11 += res[(size_t)(row+8)*N + col + 1];
                *(float2*)(C + (size_t)row*N + col)     = make_float2(v00, v01);
                *(float2*)(C + (size_t)(row+8)*N + col) = make_float2(v10, v11);
            } else if (ep == EP_BIAS) {
                *(float2*)(C + (size_t)row*N + col)     = make_float2(v00, v01);
                *(float2*)(C + (size_t)(row+8)*N + col) = make_float2(v10, v11);
            } else {
                if (ep == EP_GELU_SPLIT) {
                    v00 = 0.5f*v00*(1.0f + erff(v00*0.70710678118654752f));
                    v01 = 0.5f*v01*(1.0f + erff(v01*0.70710678118654752f));
                    v10 = 0.5f*v10*(1.0f + erff(v10*0.70710678118654752f));
                    v11 = 0.5f*v11*(1.0f + erff(v11*0.70710678118654752f));
                }
                Cs[(size_t)row*(N>>1)     + (col>>1)] = split2bf(v00, v01);
                Cs[(size_t)(row+8)*(N>>1) + (col>>1)] = split2bf(v10, v11);
            }
        }
    }
}

template<int BN>
__global__ __launch_bounds__(256) void tgemm_kernel(
    const uint2* __restrict__ A, const uint2* __restrict__ B,
    const float* __restrict__ bias, const float* __restrict__ res,
    float* __restrict__ C, uint2* __restrict__ Cs,
    int M, int N, int K, int ep)
{
    tgemm_body<BN>(A, B, bias, res, C, Cs, M, N, K, ep);
}

// fused QKV: blockIdx.z selects the projection (q,k -> split; v -> fp32)
__global__ __launch_bounds__(256) void qkv_kernel(
    const uint2* __restrict__ hs,
    const uint2* __restrict__ wq, const uint2* __restrict__ wk, const uint2* __restrict__ wv,
    const float* __restrict__ bq, const float* __restrict__ bk, const float* __restrict__ bv,
    uint2* __restrict__ qs, uint2* __restrict__ ks, float* __restrict__ v)
{
    if (blockIdx.z == 0)
        tgemm_body<128>(hs, wq, bq, nullptr, nullptr, qs, MROWS, HDIM, HDIM, EP_BIAS_SPLIT);
    else if (blockIdx.z == 1)
        tgemm_body<128>(hs, wk, bk, nullptr, nullptr, ks, MROWS, HDIM, HDIM, EP_BIAS_SPLIT);
    else
        tgemm_body<128>(hs, wv, bv, nullptr, v, nullptr, MROWS, HDIM, HDIM, EP_BIAS);
}

// ================= flash attention (split Q/K inputs, split ctx output) ========
#define FLASH_KPAD 132
#define FLASH_VPAD 68
#define FLASH_SMEM ((32*FLASH_KPAD + 64*FLASH_VPAD) * (int)sizeof(uint2))

__global__ __launch_bounds__(256) void flash_kernel(
    const uint2* __restrict__ q, const uint2* __restrict__ k,
    const float* __restrict__ v, uint2* __restrict__ ctxs)
{
    extern __shared__ uint2 dsmem[];
    uint2 (*Ks)[FLASH_KPAD] = reinterpret_cast<uint2(*)[FLASH_KPAD]>(dsmem);
    uint2 (*Vs)[FLASH_VPAD] = reinterpret_cast<uint2(*)[FLASH_VPAD]>(dsmem + 32*FLASH_KPAD);

    const int it = (int)(gridDim.x - 1 - blockIdx.x);
    const int bh = blockIdx.y, b = bh >> 3, h = bh & 7;
    const uint2* qb = q + (size_t)b*SS*HPH + h*32;
    const uint2* kb = k + (size_t)b*SS*HPH + h*32;
    const float* vb = v + (size_t)b*SS*HDIM + h*DH;
    uint2* cb       = ctxs + (size_t)b*SS*HPH + h*32;

    const int tid  = threadIdx.x, lane = tid & 31, warp = tid >> 5;
    const int g    = lane >> 2,  tg   = lane & 3;
    const int i0   = it * 128;
    const int rowg = i0 + warp*16 + g;

    // Q fragments straight from split gmem
    uint2 qf[4][4];
    {
        const uint2* qrg = qb + (size_t)rowg*HPH;
        const uint2* qr8 = qrg + 8*HPH;
        #pragma unroll
        for (int kk = 0; kk < 4; kk++) {
            qf[kk][0] = qrg[kk*8 + tg];
            qf[kk][1] = qr8[kk*8 + tg];
            qf[kk][2] = qrg[kk*8 + tg + 4];
            qf[kk][3] = qr8[kk*8 + tg + 4];
        }
    }

    float m0 = -1e30f, m1 = -1e30f, l0 = 0.f, l1 = 0.f;
    float o[8][4];
    #pragma unroll
    for (int nf = 0; nf < 8; nf++)
        #pragma unroll
        for (int l = 0; l < 4; l++) o[nf][l] = 0.f;

    const int kjr = tid >> 1, kcb = (tid & 1)*16;   // K loader: row, kp base
    const int vjp = tid >> 2, vcb = (tid & 3)*16;   // V loader: row pair, col base

    for (int jt = 0; jt <= it; jt++) {
        const int j0 = jt * 128;
        {   // K tile: copy split uint2, transpose to [kp][j]
            const uint2* krow = kb + (size_t)(j0 + kjr)*HPH + kcb;
            #pragma unroll
            for (int u = 0; u < 8; u++) {
                uint4 f = ((const uint4*)krow)[u];
                Ks[kcb + 2*u][kjr]     = make_uint2(f.x, f.y);
                Ks[kcb + 2*u + 1][kjr] = make_uint2(f.z, f.w);
            }
        }
        {   // V tile: fp32 -> (rowpair) split
            const float* vr0 = vb + (size_t)(j0 + 2*vjp)*HDIM + vcb;
            const float* vr1 = vr0 + HDIM;
            #pragma unroll
            for (int u = 0; u < 4; u++) {
                float4 f0 = *(const float4*)(vr0 + u*4);
                float4 f1 = *(const float4*)(vr1 + u*4);
                Vs[vjp][vcb + u*4 + 0] = split2bf(f0.x, f1.x);
                Vs[vjp][vcb + u*4 + 1] = split2bf(f0.y, f1.y);
                Vs[vjp][vcb + u*4 + 2] = split2bf(f0.z, f1.z);
                Vs[vjp][vcb + u*4 + 3] = split2bf(f0.w, f1.w);
            }
        }
        __syncthreads();

        float s[16][4];
        #pragma unroll
        for (int jf = 0; jf < 16; jf++)
            #pragma unroll
            for (int l = 0; l < 4; l++) s[jf][l] = 0.f;

        #pragma unroll
        for (int kk = 0; kk < 4; kk++) {
            uint2 a0 = qf[kk][0], a1 = qf[kk][1], a2 = qf[kk][2], a3 = qf[kk][3];
            #pragma unroll
            for (int jf = 0; jf < 16; jf++) {
                uint2 b0 = Ks[kk*8 + tg][jf*8 + g];
                uint2 b1 = Ks[kk*8 + tg + 4][jf*8 + g];
                mma16(s[jf], a0.x,a1.x,a2.x,a3.x, b0.x, b1.x);
                mma16(s[jf], a0.y,a1.y,a2.y,a3.y, b0.x, b1.x);
                mma16(s[jf], a0.x,a1.x,a2.x,a3.x, b0.y, b1.y);
            }
        }

        const float scale = 0.125f;
        if (jt == it) {
            const int r0 = warp*16 + g, r1 = r0 + 8;
            #pragma unroll
            for (int jf = 0; jf < 16; jf++) {
                int c0 = jf*8 + 2*tg;
                s[jf][0] = (c0     <= r0) ? s[jf][0]*scale : -1e30f;
                s[jf][1] = (c0 + 1 <= r0) ? s[jf][1]*scale : -1e30f;
                s[jf][2] = (c0     <= r1) ? s[jf][2]*scale : -1e30f;
                s[jf][3] = (c0 + 1 <= r1) ? s[jf][3]*scale : -1e30f;
            }
        } else {
            #pragma unroll
            for (int jf = 0; jf < 16; jf++) {
                s[jf][0] *= scale; s[jf][1] *= scale;
                s[jf][2] *= scale; s[jf][3] *= scale;
            }
        }

        float tm0 = -1e30f, tm1 = -1e30f;
        #pragma unroll
        for (int jf = 0; jf < 16; jf++) {
            tm0 = fmaxf(tm0, fmaxf(s[jf][0], s[jf][1]));
            tm1 = fmaxf(tm1, fmaxf(s[jf][2], s[jf][3]));
        }
        tm0 = fmaxf(tm0, __shfl_xor_sync(0xffffffffu, tm0, 1));
        tm0 = fmaxf(tm0, __shfl_xor_sync(0xffffffffu, tm0, 2));
        tm1 = fmaxf(tm1, __shfl_xor_sync(0xffffffffu, tm1, 1));
        tm1 = fmaxf(tm1, __shfl_xor_sync(0xffffffffu, tm1, 2));

        float nm0 = fmaxf(m0, tm0), nm1 = fmaxf(m1, tm1);
        float al0 = __expf(m0 - nm0), al1 = __expf(m1 - nm1);
        m0 = nm0; m1 = nm1;

        float rs0 = 0.f, rs1 = 0.f;
        #pragma unroll
        for (int jf = 0; jf < 16; jf++) {
            s[jf][0] = __expf(s[jf][0] - nm0);
            s[jf][1] = __expf(s[jf][1] - nm0);
            s[jf][2] = __expf(s[jf][2] - nm1);
            s[jf][3] = __expf(s[jf][3] - nm1);
            rs0 += s[jf][0] + s[jf][1];
            rs1 += s[jf][2] + s[jf][3];
        }
        rs0 += __shfl_xor_sync(0xffffffffu, rs0, 1);
        rs0 += __shfl_xor_sync(0xffffffffu, rs0, 2);
        rs1 += __shfl_xor_sync(0xffffffffu, rs1, 1);
        rs1 += __shfl_xor_sync(0xffffffffu, rs1, 2);
        l0 = l0*al0 + rs0;
        l1 = l1*al1 + rs1;

        #pragma unroll
        for (int nf = 0; nf < 8; nf++) {
            o[nf][0] *= al0; o[nf][1] *= al0;
            o[nf][2] *= al1; o[nf][3] *= al1;
        }

        #pragma unroll
        for (int kk = 0; kk < 8; kk++) {
            uint2 A0 = split2bf(s[2*kk][0],   s[2*kk][1]);
            uint2 A1 = split2bf(s[2*kk][2],   s[2*kk][3]);
            uint2 A2 = split2bf(s[2*kk+1][0], s[2*kk+1][1]);
            uint2 A3 = split2bf(s[2*kk+1][2], s[2*kk+1][3]);
            #pragma unroll
            for (int nf = 0; nf < 8; nf++) {
                uint2 b0 = Vs[kk*8 + tg][nf*8 + g];
                uint2 b1 = Vs[kk*8 + tg + 4][nf*8 + g];
                mma16(o[nf], A0.x,A1.x,A2.x,A3.x, b0.x, b1.x);
                mma16(o[nf], A0.y,A1.y,A2.y,A3.y, b0.x, b1.x);
                mma16(o[nf], A0.x,A1.x,A2.x,A3.x, b0.y, b1.y);
            }
        }
        __syncthreads();
    }

    float inv0 = 1.0f / l0, inv1 = 1.0f / l1;
    uint2* crow0 = cb + (size_t)rowg*HPH;
    uint2* crow1 = crow0 + 8*HPH;
    #pragma unroll
    for (int nf = 0; nf < 8; nf++) {
        crow0[nf*4 + tg] = split2bf(o[nf][0]*inv0, o[nf][1]*inv0);
        crow1[nf*4 + tg] = split2bf(o[nf][2]*inv1, o[nf][3]*inv1);
    }
}

// ---------------- layernorm over HDIM, fp32 + split outputs -------------------
__global__ __launch_bounds__(256) void ln_kernel(
    const float* __restrict__ x, const float* __restrict__ g,
    const float* __restrict__ b, float* __restrict__ out,
    uint2* __restrict__ outs)
{
    int row = blockIdx.x;
    __shared__ float red[32];
    int tid = threadIdx.x;
    int c0 = 2*tid;
    float2 xv = *(const float2*)(x + (size_t)row*HDIM + c0);
    float sum = blockReduceSum(xv.x + xv.y, red);
    float m = sum * (1.0f / HDIM);
    float d0 = xv.x - m, d1 = xv.y - m;
    float ssq = blockReduceSum(d0*d0 + d1*d1, red);
    float rstd = rsqrtf(ssq * (1.0f / HDIM) + 1e-5f);
    float o0 = d0 * rstd * g[c0]     + b[c0];
    float o1 = d1 * rstd * g[c0 + 1] + b[c0 + 1];
    *(float2*)(out + (size_t)row*HDIM + c0) = make_float2(o0, o1);
    outs[(size_t)row*HPH + tid] = split2bf(o0, o1);
}

// ---------------- final projection: out = h[:, :, 1] @ Wp + bp ----------------
__global__ __launch_bounds__(256) void final_kernel(
    const float* __restrict__ h, const float* __restrict__ Wp,
    const float* __restrict__ bp, float* __restrict__ out)
{
    int bt = blockIdx.x;
    int b = bt / TT, t = bt % TT;
    const float* row = h + ((size_t)b*SS + 3*t + 1) * HDIM;
    __shared__ float sRow[HDIM];
    __shared__ float part[8][ADIM];
    int tid = threadIdx.x;
    sRow[tid] = row[tid];
    sRow[tid + 256] = row[tid + 256];
    __syncthreads();
    int c = tid & 31, g = tid >> 5;
    float a = 0.f;
    for (int k = g*64; k < (g+1)*64; k++) a = fmaf(sRow[k], Wp[(size_t)k*ADIM + c], a);
    part[g][c] = a;
    __syncthreads();
    if (tid < ADIM) {
        float s = bp[tid];
        #pragma unroll
        for (int g2 = 0; g2 < 8; g2++) s += part[g2][tid];
        out[(size_t)bt*ADIM + tid] = s;
    }
}

// ---------------- driver ----------------
extern "C" void kernel_launch(void* const* d_in, const int* in_sizes, int n_in,
                              void* d_out, int out_size)
{
    const int*   timesteps = (const int*)  d_in[0];
    const float* state_0   = (const float*)d_in[1];
    const float* state_1   = (const float*)d_in[2];
    const float* actions   = (const float*)d_in[3];
    const float* time_emb  = (const float*)d_in[4];
    const float* Ws  = (const float*)d_in[5];
    const float* bs  = (const float*)d_in[6];
    const float* Wa  = (const float*)d_in[7];
    const float* ba  = (const float*)d_in[8];
    const float* Wq  = (const float*)d_in[9];
    const float* bq  = (const float*)d_in[10];
    const float* Wk  = (const float*)d_in[11];
    const float* bk  = (const float*)d_in[12];
    const float* Wv  = (const float*)d_in[13];
    const float* bv  = (const float*)d_in[14];
    const float* Wo  = (const float*)d_in[15];
    const float* bo  = (const float*)d_in[16];
    const float* W1  = (const float*)d_in[17];
    const float* b1  = (const float*)d_in[18];
    const float* W2  = (const float*)d_in[19];
    const float* b2  = (const float*)d_in[20];
    const float* ln1_g = (const float*)d_in[21];
    const float* ln1_b = (const float*)d_in[22];
    const float* ln2_g = (const float*)d_in[23];
    const float* ln2_b = (const float*)d_in[24];
    const float* eln_g = (const float*)d_in[25];
    const float* eln_b = (const float*)d_in[26];
    const float* Wp  = (const float*)d_in[27];
    const float* bp  = (const float*)d_in[28];

    float *h, *v, *xa, *ln1o, *pre2;
    uint2 *hs, *qs, *ks, *ctxs, *ln1s, *mlps, *ws;
    cudaGetSymbolAddress((void**)&h,    g_h);
    cudaGetSymbolAddress((void**)&v,    g_v);
    cudaGetSymbolAddress((void**)&xa,   g_xa);
    cudaGetSymbolAddress((void**)&ln1o, g_ln1);
    cudaGetSymbolAddress((void**)&pre2, g_pre2);
    cudaGetSymbolAddress((void**)&hs,   g_hs);
    cudaGetSymbolAddress((void**)&qs,   g_qs);
    cudaGetSymbolAddress((void**)&ks,   g_ks);
    cudaGetSymbolAddress((void**)&ctxs, g_ctxs);
    cudaGetSymbolAddress((void**)&ln1s, g_ln1s);
    cudaGetSymbolAddress((void**)&mlps, g_mlps);
    cudaGetSymbolAddress((void**)&ws,   g_ws);

    cudaFuncSetAttribute(flash_kernel,
                         cudaFuncAttributeMaxDynamicSharedMemorySize, FLASH_SMEM);

    // ---- pre-split all weights (once per launch) ----
    wsplit_kernel<<<dim3(HDIM/256, NBLK*HDIM/2), 256>>>(Wq, ws + WQ0, HDIM);
    wsplit_kernel<<<dim3(HDIM/256, NBLK*HDIM/2), 256>>>(Wk, ws + WK0, HDIM);
    wsplit_kernel<<<dim3(HDIM/256, NBLK*HDIM/2), 256>>>(Wv, ws + WV0, HDIM);
    wsplit_kernel<<<dim3(HDIM/256, NBLK*HDIM/2), 256>>>(Wo, ws + WO0, HDIM);
    wsplit_kernel<<<dim3(DFF/256,  NBLK*HDIM/2), 256>>>(W1, ws + W10, DFF);
    wsplit_kernel<<<dim3(HDIM/256, NBLK*DFF/2),  256>>>(W2, ws + W20, HDIM);

    embed_kernel<<<BB*SS, 256>>>(timesteps, state_0, state_1, actions, time_emb,
                                 Ws, bs, Wa, ba, eln_g, eln_b, h, hs);

    dim3 gQKV(HDIM/128, MROWS/128, 3);   // (4, 48, 3)
    dim3 gH64(HDIM/64,  MROWS/128);      // (8, 48)
    dim3 gF  (DFF /128, MROWS/128);      // (16, 48)
    dim3 gFl (SS/128, BB*NH);            // (12, 32)

    for (int blk = 0; blk < NBLK; blk++) {
        const uint2* wqs = ws + WQ0 + (size_t)blk*131072;
        const uint2* wks = ws + WK0 + (size_t)blk*131072;
        const uint2* wvs = ws + WV0 + (size_t)blk*131072;
        const uint2* wos = ws + WO0 + (size_t)blk*131072;
        const uint2* w1s = ws + W10 + (size_t)blk*524288;
        const uint2* w2s = ws + W20 + (size_t)blk*524288;
        const float* bq_ = bq + (size_t)blk*HDIM;
        const float* bk_ = bk + (size_t)blk*HDIM;
        const float* bv_ = bv + (size_t)blk*HDIM;
        const float* bo_ = bo + (size_t)blk*HDIM;
        const float* b1_ = b1 + (size_t)blk*DFF;
        const float* b2_ = b2 + (size_t)blk*HDIM;
        const float* g1_ = ln1_g + (size_t)blk*HDIM;
        const float* e1_ = ln1_b + (size_t)blk*HDIM;
        const float* g2_ = ln2_g + (size_t)blk*HDIM;
        const float* e2_ = ln2_b + (size_t)blk*HDIM;

        qkv_kernel<<<gQKV, 256>>>(hs, wqs, wks, wvs, bq_, bk_, bv_, qs, ks, v);

        flash_kernel<<<gFl, 256, FLASH_SMEM>>>(qs, ks, v, ctxs);

        tgemm_kernel<64> <<<gH64, 256>>>(ctxs, wos, bo_, h, xa, nullptr,
                                         MROWS, HDIM, HDIM, EP_BIAS_RES);
        ln_kernel<<<MROWS, 256>>>(xa, g1_, e1_, ln1o, ln1s);
        tgemm_kernel<128><<<gF, 256>>>(ln1s, w1s, b1_, nullptr, nullptr, mlps,
                                       MROWS, DFF, HDIM, EP_GELU_SPLIT);
        tgemm_kernel<64> <<<gH64, 256>>>(mlps, w2s, b2_, ln1o, pre2, nullptr,
                                         MROWS, HDIM, DFF, EP_BIAS_RES);
        ln_kernel<<<MROWS, 256>>>(pre2, g2_, e2_, h, hs);
    }

    final_kernel<<<BB*TT, 256>>>(h, Wp, bp, (float*)d_out);
}

// round 10
// speedup vs baseline: 2.5645x; 1.0298x over previous
#include <cuda_runtime.h>
#include <cuda_bf16.h>
#include <math.h>

#define BB 4
#define TT 512
#define SS 1536
#define SDIM 64
#define ADIM 32
#define HDIM 512
#define HPH 256
#define NH 8
#define DH 64
#define NBLK 6
#define DFFH 1024
#define DFF 2048
#define MROWS (BB*SS)

enum { EP_BIAS = 0, EP_BIAS_RES = 1, EP_GELU_SPLIT = 2, EP_BIAS_SPLIT = 3 };

// ---------------- scratch ----------------
__device__ float g_h   [MROWS * HDIM];
__device__ float g_v   [MROWS * HDIM];
__device__ float g_xa  [MROWS * HDIM];
__device__ float g_ln1 [MROWS * HDIM];
__device__ float g_pre2[MROWS * HDIM];

__device__ uint2 g_hs  [MROWS * HPH];
__device__ uint2 g_qs  [MROWS * HPH];
__device__ uint2 g_ks  [MROWS * HPH];
__device__ uint2 g_ctxs[MROWS * HPH];
__device__ uint2 g_ln1s[MROWS * HPH];
__device__ uint2 g_mlps[MROWS * DFFH];

#define WQ0 0
#define WK0 786432
#define WV0 1572864
#define WO0 2359296
#define W10 3145728
#define W20 6291456
__device__ uint2 g_ws[9437184];

// ---------------- bf16 split helpers ----------------
__device__ __forceinline__ uint2 split2bf(float x0, float x1) {
    __nv_bfloat162 h = __floats2bfloat162_rn(x0, x1);
    float r0 = x0 - __bfloat162float(h.x);
    float r1 = x1 - __bfloat162float(h.y);
    __nv_bfloat162 l = __floats2bfloat162_rn(r0, r1);
    uint2 out;
    out.x = *reinterpret_cast<unsigned*>(&h);
    out.y = *reinterpret_cast<unsigned*>(&l);
    return out;
}

__device__ __forceinline__ void mma16(float c[4],
    unsigned a0, unsigned a1, unsigned a2, unsigned a3,
    unsigned b0, unsigned b1)
{
    asm volatile(
      "mma.sync.aligned.m16n8k16.row.col.f32.bf16.bf16.f32 "
      "{%0,%1,%2,%3},{%4,%5,%6,%7},{%8,%9},{%0,%1,%2,%3};"
      : "+f"(c[0]), "+f"(c[1]), "+f"(c[2]), "+f"(c[3])
      : "r"(a0), "r"(a1), "r"(a2), "r"(a3), "r"(b0), "r"(b1));
}

__device__ __forceinline__ void cpa16(void* s, const void* g) {
    unsigned a = (unsigned)__cvta_generic_to_shared(s);
    asm volatile("cp.async.cg.shared.global [%0], [%1], 16;" :: "r"(a), "l"(g));
}
#define CP_COMMIT() asm volatile("cp.async.commit_group;")
#define CP_WAIT0()  asm volatile("cp.async.wait_group 0;")
#define CP_WAIT1()  asm volatile("cp.async.wait_group 1;")

// ---------------- reductions ----------------
__device__ __forceinline__ float blockReduceSum(float v, float* sm) {
    int lane = threadIdx.x & 31, wid = threadIdx.x >> 5;
    #pragma unroll
    for (int o = 16; o; o >>= 1) v += __shfl_down_sync(0xffffffffu, v, o);
    if (lane == 0) sm[wid] = v;
    __syncthreads();
    float r = 0.f;
    if (wid == 0) {
        r = (lane < 8) ? sm[lane] : 0.f;
        #pragma unroll
        for (int o = 4; o; o >>= 1) r += __shfl_down_sync(0xffffffffu, r, o);
        if (lane == 0) sm[0] = r;
    }
    __syncthreads();
    r = sm[0];
    __syncthreads();
    return r;
}

// ---------------- weight split: W[k][n] -> Ws[k/2][n] (hi,lo uint2) ----------
__global__ __launch_bounds__(256) void wsplit_kernel(
    const float* __restrict__ src, uint2* __restrict__ dst, int N)
{
    int n  = blockIdx.x * 256 + threadIdx.x;
    int kp = blockIdx.y;
    dst[(size_t)kp * N + n] =
        split2bf(src[(size_t)(2*kp) * N + n], src[(size_t)(2*kp + 1) * N + n]);
}

// ---------------- embedding + eLN ----------------
__global__ __launch_bounds__(256) void embed_kernel(
    const int* __restrict__ timesteps, const float* __restrict__ s0,
    const float* __restrict__ s1, const float* __restrict__ act,
    const float* __restrict__ temb,
    const float* __restrict__ Ws, const float* __restrict__ bs,
    const float* __restrict__ Wa, const float* __restrict__ ba,
    const float* __restrict__ eg, const float* __restrict__ eb,
    float* __restrict__ out, uint2* __restrict__ outs)
{
    int s = blockIdx.x;
    int b = s / SS, sr = s % SS;
    int t = sr / 3, r = sr % 3;

    __shared__ float sIn[SDIM];
    __shared__ float red[32];

    const float* inp; const float* W; const float* bias; int Kin;
    if (r == 0)      { inp = s0  + (size_t)(b*TT + t)*SDIM; W = Ws; bias = bs; Kin = SDIM; }
    else if (r == 1) { inp = s1  + (size_t)(b*TT + t)*SDIM; W = Ws; bias = bs; Kin = SDIM; }
    else             { inp = act + (size_t)(b*TT + t)*ADIM; W = Wa; bias = ba; Kin = ADIM; }

    int tid = threadIdx.x;
    if (tid < Kin) sIn[tid] = inp[tid];
    __syncthreads();

    int tsv = timesteps[b*TT + t];
    const float* te = temb + (size_t)tsv * HDIM;

    int c0 = 2*tid;
    float a0 = bias[c0] + te[c0], a1 = bias[c0+1] + te[c0+1];
    for (int k = 0; k < Kin; k++) {
        float x = sIn[k];
        a0 = fmaf(x, W[(size_t)k*HDIM + c0],     a0);
        a1 = fmaf(x, W[(size_t)k*HDIM + c0 + 1], a1);
    }
    float sum = blockReduceSum(a0 + a1, red);
    float m = sum * (1.0f / HDIM);
    float d0 = a0 - m, d1 = a1 - m;
    float ssq = blockReduceSum(d0*d0 + d1*d1, red);
    float rstd = rsqrtf(ssq * (1.0f / HDIM) + 1e-5f);
    float o0 = d0 * rstd * eg[c0]     + eb[c0];
    float o1 = d1 * rstd * eg[c0 + 1] + eb[c0 + 1];
    *(float2*)(out + (size_t)s*HDIM + c0) = make_float2(o0, o1);
    outs[(size_t)s*HPH + tid] = split2bf(o0, o1);
}

// ============ tensor-core GEMM (bf16x3, split operands) ========================
// A: [M][K/2] uint2. B: [K/2][N] uint2. Tile 128xBN, k-chunk 32 (16 kp),
// 3-stage cp.async pipeline, ONE syncthreads per iteration.
#define APAD 20
#define ASTG (128*APAD)

template<int BN>
__device__ __forceinline__ void tgemm_body(
    const uint2* __restrict__ A, const uint2* __restrict__ B,
    const float* __restrict__ bias, const float* __restrict__ res,
    float* __restrict__ C, uint2* __restrict__ Cs,
    int M, int N, int K, int ep, float scl, char* smraw)
{
    constexpr int TNF = BN / 32;
    constexpr int BST = BN + 4;
    constexpr int BSTG = 16 * BST;
    uint2* Asm = (uint2*)smraw;
    uint2* Bsm = Asm + 3*ASTG;

    const int tid  = threadIdx.x, lane = tid & 31, warp = tid >> 5;
    const int g    = lane >> 2,  tg   = lane & 3;
    const int wm0  = (warp >> 2) * 64, wn0 = (warp & 3) * (BN / 4);
    const int m0   = blockIdx.y * 128, n0 = blockIdx.x * BN;
    const int KW   = K >> 1;

    float acc[4][TNF][4];
    #pragma unroll
    for (int i = 0; i < 4; i++)
        #pragma unroll
        for (int j = 0; j < TNF; j++)
            #pragma unroll
            for (int l = 0; l < 4; l++) acc[i][j][l] = 0.f;

    const int T = K / 32;

    auto fill = [&](int t, int s) {
        uint2* Ad = Asm + s*ASTG;
        uint2* Bd = Bsm + s*BSTG;
        int kw0 = t * 16;
        #pragma unroll
        for (int i = 0; i < 4; i++) {
            int id = tid + 256*i, r = id >> 3, c = (id & 7) * 2;
            cpa16(Ad + r*APAD + c, A + (size_t)(m0 + r)*KW + kw0 + c);
        }
        if (BN == 128) {
            #pragma unroll
            for (int i = 0; i < 4; i++) {
                int id = tid + 256*i, kp = id >> 6, nc = (id & 63) * 2;
                cpa16(Bd + kp*BST + nc, B + (size_t)(kw0 + kp)*N + n0 + nc);
            }
        } else {
            #pragma unroll
            for (int i = 0; i < 2; i++) {
                int id = tid + 256*i, kp = id >> 5, nc = (id & 31) * 2;
                cpa16(Bd + kp*BST + nc, B + (size_t)(kw0 + kp)*N + n0 + nc);
            }
        }
        CP_COMMIT();
    };

    fill(0, 0);
    if (T > 1) fill(1, 1);

    for (int t = 0; t < T; t++) {
        const int s = t % 3;
        if (t + 1 < T) CP_WAIT1(); else CP_WAIT0();
        __syncthreads();
        if (t + 2 < T) fill(t + 2, (t + 2) % 3);

        const uint2* As_ = Asm + s*ASTG;
        const uint2* Bs_ = Bsm + s*BSTG;
        #pragma unroll
        for (int ks = 0; ks < 2; ks++) {
            const int kb = ks * 8;
            uint2 bf[TNF][2];
            #pragma unroll
            for (int tn = 0; tn < TNF; tn++) {
                int n = wn0 + tn*8 + g;
                bf[tn][0] = Bs_[(kb + tg)*BST + n];
                bf[tn][1] = Bs_[(kb + tg + 4)*BST + n];
            }
            #pragma unroll
            for (int tm = 0; tm < 4; tm++) {
                int m = wm0 + tm*16 + g;
                uint2 a0 = As_[m*APAD + kb + tg];
                uint2 a1 = As_[(m+8)*APAD + kb + tg];
                uint2 a2 = As_[m*APAD + kb + tg + 4];
                uint2 a3 = As_[(m+8)*APAD + kb + tg + 4];
                #pragma unroll
                for (int tn = 0; tn < TNF; tn++) {
                    mma16(acc[tm][tn], a0.x,a1.x,a2.x,a3.x, bf[tn][0].x, bf[tn][1].x);
                    mma16(acc[tm][tn], a0.y,a1.y,a2.y,a3.y, bf[tn][0].x, bf[tn][1].x);
                    mma16(acc[tm][tn], a0.x,a1.x,a2.x,a3.x, bf[tn][0].y, bf[tn][1].y);
                }
            }
        }
    }

    #pragma unroll
    for (int tm = 0; tm < 4; tm++) {
        #pragma unroll
        for (int tn = 0; tn < TNF; tn++) {
            int row = m0 + wm0 + tm*16 + g;
            int col = n0 + wn0 + tn*8 + tg*2;
            float b0v = bias[col], b1v = bias[col+1];
            float v00 = acc[tm][tn][0] + b0v, v01 = acc[tm][tn][1] + b1v;
            float v10 = acc[tm][tn][2] + b0v, v11 = acc[tm][tn][3] + b1v;
            if (ep == EP_BIAS_RES) {
                v00 += res[(size_t)row*N + col];     v01 += res[(size_t)row*N + col + 1];
                v10 += res[(size_t)(row+8)*N + col]; v11 += res[(size_t)(row+8)*N + col + 1];
                *(float2*)(C + (size_t)row*N + col)     = make_float2(v00, v01);
                *(float2*)(C + (size_t)(row+8)*N + col) = make_float2(v10, v11);
            } else if (ep == EP_BIAS) {
                *(float2*)(C + (size_t)row*N + col)     = make_float2(v00, v01);
                *(float2*)(C + (size_t)(row+8)*N + col) = make_float2(v10, v11);
            } else {
                if (ep == EP_GELU_SPLIT) {
                    v00 = 0.5f*v00*(1.0f + erff(v00*0.70710678118654752f));
                    v01 = 0.5f*v01*(1.0f + erff(v01*0.70710678118654752f));
                    v10 = 0.5f*v10*(1.0f + erff(v10*0.70710678118654752f));
                    v11 = 0.5f*v11*(1.0f + erff(v11*0.70710678118654752f));
                } else {
                    v00 *= scl; v01 *= scl; v10 *= scl; v11 *= scl;
                }
                Cs[(size_t)row*(N>>1)     + (col>>1)] = split2bf(v00, v01);
                Cs[(size_t)(row+8)*(N>>1) + (col>>1)] = split2bf(v10, v11);
            }
        }
    }
}

template<int BN>
__global__ __launch_bounds__(256) void tgemm_kernel(
    const uint2* __restrict__ A, const uint2* __restrict__ B,
    const float* __restrict__ bias, const float* __restrict__ res,
    float* __restrict__ C, uint2* __restrict__ Cs,
    int M, int N, int K, int ep)
{
    extern __shared__ char smraw[];
    tgemm_body<BN>(A, B, bias, res, C, Cs, M, N, K, ep, 1.0f, smraw);
}

// fused QKV (q scaled by 1/8 pre-split; v fp32)
__global__ __launch_bounds__(256) void qkv_kernel(
    const uint2* __restrict__ hs,
    const uint2* __restrict__ wq, const uint2* __restrict__ wk, const uint2* __restrict__ wv,
    const float* __restrict__ bq, const float* __restrict__ bk, const float* __restrict__ bv,
    uint2* __restrict__ qs, uint2* __restrict__ ks, float* __restrict__ v)
{
    extern __shared__ char smraw[];
    if (blockIdx.z == 0)
        tgemm_body<128>(hs, wq, bq, nullptr, nullptr, qs, MROWS, HDIM, HDIM, EP_BIAS_SPLIT, 0.125f, smraw);
    else if (blockIdx.z == 1)
        tgemm_body<128>(hs, wk, bk, nullptr, nullptr, ks, MROWS, HDIM, HDIM, EP_BIAS_SPLIT, 1.0f, smraw);
    else
        tgemm_body<128>(hs, wv, bv, nullptr, v, nullptr, MROWS, HDIM, HDIM, EP_BIAS, 1.0f, smraw);
}

#define SM128 (3*(ASTG + 16*132)*(int)sizeof(uint2))
#define SM64  (3*(ASTG + 16*68 )*(int)sizeof(uint2))

// ================= flash attention (split Q/K inputs, split ctx output) ========
// Q pre-scaled by 1/8; no scale multiply in the loop.
#define FLASH_KPAD 132
#define FLASH_VPAD 68
#define FLASH_SMEM ((32*FLASH_KPAD + 64*FLASH_VPAD) * (int)sizeof(uint2))

__global__ __launch_bounds__(256) void flash_kernel(
    const uint2* __restrict__ q, const uint2* __restrict__ k,
    const float* __restrict__ v, uint2* __restrict__ ctxs)
{
    extern __shared__ uint2 dsmem[];
    uint2 (*Ks)[FLASH_KPAD] = reinterpret_cast<uint2(*)[FLASH_KPAD]>(dsmem);
    uint2 (*Vs)[FLASH_VPAD] = reinterpret_cast<uint2(*)[FLASH_VPAD]>(dsmem + 32*FLASH_KPAD);

    const int it = (int)(gridDim.x - 1 - blockIdx.x);
    const int bh = blockIdx.y, b = bh >> 3, h = bh & 7;
    const uint2* qb = q + (size_t)b*SS*HPH + h*32;
    const uint2* kb = k + (size_t)b*SS*HPH + h*32;
    const float* vb = v + (size_t)b*SS*HDIM + h*DH;
    uint2* cb       = ctxs + (size_t)b*SS*HPH + h*32;

    const int tid  = threadIdx.x, lane = tid & 31, warp = tid >> 5;
    const int g    = lane >> 2,  tg   = lane & 3;
    const int i0   = it * 128;
    const int rowg = i0 + warp*16 + g;

    uint2 qf[4][4];
    {
        const uint2* qrg = qb + (size_t)rowg*HPH;
        const uint2* qr8 = qrg + 8*HPH;
        #pragma unroll
        for (int kk = 0; kk < 4; kk++) {
            qf[kk][0] = qrg[kk*8 + tg];
            qf[kk][1] = qr8[kk*8 + tg];
            qf[kk][2] = qrg[kk*8 + tg + 4];
            qf[kk][3] = qr8[kk*8 + tg + 4];
        }
    }

    float m0 = -1e30f, m1 = -1e30f, l0 = 0.f, l1 = 0.f;
    float o[8][4];
    #pragma unroll
    for (int nf = 0; nf < 8; nf++)
        #pragma unroll
        for (int l = 0; l < 4; l++) o[nf][l] = 0.f;

    const int kjr = tid >> 1, kcb = (tid & 1)*16;
    const int vjp = tid >> 2, vcb = (tid & 3)*16;

    for (int jt = 0; jt <= it; jt++) {
        const int j0 = jt * 128;
        {
            const uint2* krow = kb + (size_t)(j0 + kjr)*HPH + kcb;
            #pragma unroll
            for (int u = 0; u < 8; u++) {
                uint4 f = ((const uint4*)krow)[u];
                Ks[kcb + 2*u][kjr]     = make_uint2(f.x, f.y);
                Ks[kcb + 2*u + 1][kjr] = make_uint2(f.z, f.w);
            }
        }
        {
            const float* vr0 = vb + (size_t)(j0 + 2*vjp)*HDIM + vcb;
            const float* vr1 = vr0 + HDIM;
            #pragma unroll
            for (int u = 0; u < 4; u++) {
                float4 f0 = *(const float4*)(vr0 + u*4);
                float4 f1 = *(const float4*)(vr1 + u*4);
                Vs[vjp][vcb + u*4 + 0] = split2bf(f0.x, f1.x);
                Vs[vjp][vcb + u*4 + 1] = split2bf(f0.y, f1.y);
                Vs[vjp][vcb + u*4 + 2] = split2bf(f0.z, f1.z);
                Vs[vjp][vcb + u*4 + 3] = split2bf(f0.w, f1.w);
            }
        }
        __syncthreads();

        float s[16][4];
        #pragma unroll
        for (int jf = 0; jf < 16; jf++)
            #pragma unroll
            for (int l = 0; l < 4; l++) s[jf][l] = 0.f;

        #pragma unroll
        for (int kk = 0; kk < 4; kk++) {
            uint2 a0 = qf[kk][0], a1 = qf[kk][1], a2 = qf[kk][2], a3 = qf[kk][3];
            #pragma unroll
            for (int jf = 0; jf < 16; jf++) {
                uint2 b0 = Ks[kk*8 + tg][jf*8 + g];
                uint2 b1 = Ks[kk*8 + tg + 4][jf*8 + g];
                mma16(s[jf], a0.x,a1.x,a2.x,a3.x, b0.x, b1.x);
                mma16(s[jf], a0.y,a1.y,a2.y,a3.y, b0.x, b1.x);
                mma16(s[jf], a0.x,a1.x,a2.x,a3.x, b0.y, b1.y);
            }
        }

        if (jt == it) {   // causal mask on the diagonal tile (Q pre-scaled)
            const int r0 = warp*16 + g, r1 = r0 + 8;
            #pragma unroll
            for (int jf = 0; jf < 16; jf++) {
                int c0 = jf*8 + 2*tg;
                if (c0     > r0) s[jf][0] = -1e30f;
                if (c0 + 1 > r0) s[jf][1] = -1e30f;
                if (c0     > r1) s[jf][2] = -1e30f;
                if (c0 + 1 > r1) s[jf][3] = -1e30f;
            }
        }

        float tm0 = -1e30f, tm1 = -1e30f;
        #pragma unroll
        for (int jf = 0; jf < 16; jf++) {
            tm0 = fmaxf(tm0, fmaxf(s[jf][0], s[jf][1]));
            tm1 = fmaxf(tm1, fmaxf(s[jf][2], s[jf][3]));
        }
        tm0 = fmaxf(tm0, __shfl_xor_sync(0xffffffffu, tm0, 1));
        tm0 = fmaxf(tm0, __shfl_xor_sync(0xffffffffu, tm0, 2));
        tm1 = fmaxf(tm1, __shfl_xor_sync(0xffffffffu, tm1, 1));
        tm1 = fmaxf(tm1, __shfl_xor_sync(0xffffffffu, tm1, 2));

        float nm0 = fmaxf(m0, tm0), nm1 = fmaxf(m1, tm1);
        float al0 = __expf(m0 - nm0), al1 = __expf(m1 - nm1);
        m0 = nm0; m1 = nm1;

        float rs0 = 0.f, rs1 = 0.f;
        #pragma unroll
        for (int jf = 0; jf < 16; jf++) {
            s[jf][0] = __expf(s[jf][0] - nm0);
            s[jf][1] = __expf(s[jf][1] - nm0);
            s[jf][2] = __expf(s[jf][2] - nm1);
            s[jf][3] = __expf(s[jf][3] - nm1);
            rs0 += s[jf][0] + s[jf][1];
            rs1 += s[jf][2] + s[jf][3];
        }
        rs0 += __shfl_xor_sync(0xffffffffu, rs0, 1);
        rs0 += __shfl_xor_sync(0xffffffffu, rs0, 2);
        rs1 += __shfl_xor_sync(0xffffffffu, rs1, 1);
        rs1 += __shfl_xor_sync(0xffffffffu, rs1, 2);
        l0 = l0*al0 + rs0;
        l1 = l1*al1 + rs1;

        #pragma unroll
        for (int nf = 0; nf < 8; nf++) {
            o[nf][0] *= al0; o[nf][1] *= al0;
            o[nf][2] *= al1; o[nf][3] *= al1;
        }

        #pragma unroll
        for (int kk = 0; kk < 8; kk++) {
            uint2 A0 = split2bf(s[2*kk][0],   s[2*kk][1]);
            uint2 A1 = split2bf(s[2*kk][2],   s[2*kk][3]);
            uint2 A2 = split2bf(s[2*kk+1][0], s[2*kk+1][1]);
            uint2 A3 = split2bf(s[2*kk+1][2], s[2*kk+1][3]);
            #pragma unroll
            for (int nf = 0; nf < 8; nf++) {
                uint2 b0 = Vs[kk*8 + tg][nf*8 + g];
                uint2 b1 = Vs[kk*8 + tg + 4][nf*8 + g];
                mma16(o[nf], A0.x,A1.x,A2.x,A3.x, b0.x, b1.x);
                mma16(o[nf], A0.y,A1.y,A2.y,A3.y, b0.x, b1.x);
                mma16(o[nf], A0.x,A1.x,A2.x,A3.x, b0.y, b1.y);
            }
        }
        __syncthreads();
    }

    float inv0 = 1.0f / l0, inv1 = 1.0f / l1;
    uint2* crow0 = cb + (size_t)rowg*HPH;
    uint2* crow1 = crow0 + 8*HPH;
    #pragma unroll
    for (int nf = 0; nf < 8; nf++) {
        crow0[nf*4 + tg] = split2bf(o[nf][0]*inv0, o[nf][1]*inv0);
        crow1[nf*4 + tg] = split2bf(o[nf][2]*inv1, o[nf][3]*inv1);
    }
}

// ---------------- layernorm over HDIM ----------------
__global__ __launch_bounds__(256) void ln_kernel(
    const float* __restrict__ x, const float* __restrict__ g,
    const float* __restrict__ b, float* __restrict__ out,
    uint2* __restrict__ outs)
{
    int row = blockIdx.x;
    __shared__ float red[32];
    int tid = threadIdx.x;
    int c0 = 2*tid;
    float2 xv = *(const float2*)(x + (size_t)row*HDIM + c0);
    float sum = blockReduceSum(xv.x + xv.y, red);
    float m = sum * (1.0f / HDIM);
    float d0 = xv.x - m, d1 = xv.y - m;
    float ssq = blockReduceSum(d0*d0 + d1*d1, red);
    float rstd = rsqrtf(ssq * (1.0f / HDIM) + 1e-5f);
    float o0 = d0 * rstd * g[c0]     + b[c0];
    float o1 = d1 * rstd * g[c0 + 1] + b[c0 + 1];
    *(float2*)(out + (size_t)row*HDIM + c0) = make_float2(o0, o1);
    outs[(size_t)row*HPH + tid] = split2bf(o0, o1);
}

// ---------------- final projection ----------------
__global__ __launch_bounds__(256) void final_kernel(
    const float* __restrict__ h, const float* __restrict__ Wp,
    const float* __restrict__ bp, float* __restrict__ out)
{
    int bt = blockIdx.x;
    int b = bt / TT, t = bt % TT;
    const float* row = h + ((size_t)b*SS + 3*t + 1) * HDIM;
    __shared__ float sRow[HDIM];
    __shared__ float part[8][ADIM];
    int tid = threadIdx.x;
    sRow[tid] = row[tid];
    sRow[tid + 256] = row[tid + 256];
    __syncthreads();
    int c = tid & 31, g = tid >> 5;
    float a = 0.f;
    for (int k = g*64; k < (g+1)*64; k++) a = fmaf(sRow[k], Wp[(size_t)k*ADIM + c], a);
    part[g][c] = a;
    __syncthreads();
    if (tid < ADIM) {
        float s = bp[tid];
        #pragma unroll
        for (int g2 = 0; g2 < 8; g2++) s += part[g2][tid];
        out[(size_t)bt*ADIM + tid] = s;
    }
}

// ---------------- driver ----------------
extern "C" void kernel_launch(void* const* d_in, const int* in_sizes, int n_in,
                              void* d_out, int out_size)
{
    const int*   timesteps = (const int*)  d_in[0];
    const float* state_0   = (const float*)d_in[1];
    const float* state_1   = (const float*)d_in[2];
    const float* actions   = (const float*)d_in[3];
    const float* time_emb  = (const float*)d_in[4];
    const float* Ws  = (const float*)d_in[5];
    const float* bs  = (const float*)d_in[6];
    const float* Wa  = (const float*)d_in[7];
    const float* ba  = (const float*)d_in[8];
    const float* Wq  = (const float*)d_in[9];
    const float* bq  = (const float*)d_in[10];
    const float* Wk  = (const float*)d_in[11];
    const float* bk  = (const float*)d_in[12];
    const float* Wv  = (const float*)d_in[13];
    const float* bv  = (const float*)d_in[14];
    const float* Wo  = (const float*)d_in[15];
    const float* bo  = (const float*)d_in[16];
    const float* W1  = (const float*)d_in[17];
    const float* b1  = (const float*)d_in[18];
    const float* W2  = (const float*)d_in[19];
    const float* b2  = (const float*)d_in[20];
    const float* ln1_g = (const float*)d_in[21];
    const float* ln1_b = (const float*)d_in[22];
    const float* ln2_g = (const float*)d_in[23];
    const float* ln2_b = (const float*)d_in[24];
    const float* eln_g = (const float*)d_in[25];
    const float* eln_b = (const float*)d_in[26];
    const float* Wp  = (const float*)d_in[27];
    const float* bp  = (const float*)d_in[28];

    float *h, *v, *xa, *ln1o, *pre2;
    uint2 *hs, *qs, *ks, *ctxs, *ln1s, *mlps, *ws;
    cudaGetSymbolAddress((void**)&h,    g_h);
    cudaGetSymbolAddress((void**)&v,    g_v);
    cudaGetSymbolAddress((void**)&xa,   g_xa);
    cudaGetSymbolAddress((void**)&ln1o, g_ln1);
    cudaGetSymbolAddress((void**)&pre2, g_pre2);
    cudaGetSymbolAddress((void**)&hs,   g_hs);
    cudaGetSymbolAddress((void**)&qs,   g_qs);
    cudaGetSymbolAddress((void**)&ks,   g_ks);
    cudaGetSymbolAddress((void**)&ctxs, g_ctxs);
    cudaGetSymbolAddress((void**)&ln1s, g_ln1s);
    cudaGetSymbolAddress((void**)&mlps, g_mlps);
    cudaGetSymbolAddress((void**)&ws,   g_ws);

    cudaFuncSetAttribute(flash_kernel,
                         cudaFuncAttributeMaxDynamicSharedMemorySize, FLASH_SMEM);
    cudaFuncSetAttribute(tgemm_kernel<128>,
                         cudaFuncAttributeMaxDynamicSharedMemorySize, SM128);
    cudaFuncSetAttribute(tgemm_kernel<64>,
                         cudaFuncAttributeMaxDynamicSharedMemorySize, SM64);
    cudaFuncSetAttribute(qkv_kernel,
                         cudaFuncAttributeMaxDynamicSharedMemorySize, SM128);

    wsplit_kernel<<<dim3(HDIM/256, NBLK*HDIM/2), 256>>>(Wq, ws + WQ0, HDIM);
    wsplit_kernel<<<dim3(HDIM/256, NBLK*HDIM/2), 256>>>(Wk, ws + WK0, HDIM);
    wsplit_kernel<<<dim3(HDIM/256, NBLK*HDIM/2), 256>>>(Wv, ws + WV0, HDIM);
    wsplit_kernel<<<dim3(HDIM/256, NBLK*HDIM/2), 256>>>(Wo, ws + WO0, HDIM);
    wsplit_kernel<<<dim3(DFF/256,  NBLK*HDIM/2), 256>>>(W1, ws + W10, DFF);
    wsplit_kernel<<<dim3(HDIM/256, NBLK*DFF/2),  256>>>(W2, ws + W20, HDIM);

    embed_kernel<<<BB*SS, 256>>>(timesteps, state_0, state_1, actions, time_emb,
                                 Ws, bs, Wa, ba, eln_g, eln_b, h, hs);

    dim3 gQKV(HDIM/128, MROWS/128, 3);   // (4, 48, 3)
    dim3 gH64(HDIM/64,  MROWS/128);      // (8, 48)
    dim3 gF  (DFF /128, MROWS/128);      // (16, 48)
    dim3 gFl (SS/128, BB*NH);            // (12, 32)

    for (int blk = 0; blk < NBLK; blk++) {
        const uint2* wqs = ws + WQ0 + (size_t)blk*131072;
        const uint2* wks = ws + WK0 + (size_t)blk*131072;
        const uint2* wvs = ws + WV0 + (size_t)blk*131072;
        const uint2* wos = ws + WO0 + (size_t)blk*131072;
        const uint2* w1s = ws + W10 + (size_t)blk*524288;
        const uint2* w2s = ws + W20 + (size_t)blk*524288;
        const float* bq_ = bq + (size_t)blk*HDIM;
        const float* bk_ = bk + (size_t)blk*HDIM;
        const float* bv_ = bv + (size_t)blk*HDIM;
        const float* bo_ = bo + (size_t)blk*HDIM;
        const float* b1_ = b1 + (size_t)blk*DFF;
        const float* b2_ = b2 + (size_t)blk*HDIM;
        const float* g1_ = ln1_g + (size_t)blk*HDIM;
        const float* e1_ = ln1_b + (size_t)blk*HDIM;
        const float* g2_ = ln2_g + (size_t)blk*HDIM;
        const float* e2_ = ln2_b + (size_t)blk*HDIM;

        qkv_kernel<<<gQKV, 256, SM128>>>(hs, wqs, wks, wvs, bq_, bk_, bv_, qs, ks, v);

        flash_kernel<<<gFl, 256, FLASH_SMEM>>>(qs, ks, v, ctxs);

        tgemm_kernel<64> <<<gH64, 256, SM64>>>(ctxs, wos, bo_, h, xa, nullptr,
                                               MROWS, HDIM, HDIM, EP_BIAS_RES);
        ln_kernel<<<MROWS, 256>>>(xa, g1_, e1_, ln1o, ln1s);
        tgemm_kernel<128><<<gF, 256, SM128>>>(ln1s, w1s, b1_, nullptr, nullptr, mlps,
                                              MROWS, DFF, HDIM, EP_GELU_SPLIT);
        tgemm_kernel<64> <<<gH64, 256, SM64>>>(mlps, w2s, b2_, ln1o, pre2, nullptr,
                                               MROWS, HDIM, DFF, EP_BIAS_RES);
        ln_kernel<<<MROWS, 256>>>(pre2, g2_, e2_, h, hs);
    }

    final_kernel<<<BB*TT, 256>>>(h, Wp, bp, (float*)d_out);
}

// round 11
// speedup vs baseline: 2.6935x; 1.0503x over previous
#include <cuda_runtime.h>
#include <cuda_bf16.h>
#include <math.h>

#define BB 4
#define TT 512
#define SS 1536
#define SDIM 64
#define ADIM 32
#define HDIM 512
#define HPH 256
#define NH 8
#define DH 64
#define NBLK 6
#define DFFH 1024
#define DFF 2048
#define MROWS (BB*SS)

enum { EP_BIAS = 0, EP_BIAS_RES = 1, EP_GELU_SPLIT = 2, EP_BIAS_SPLIT = 3 };

// ---------------- scratch ----------------
__device__ float g_h   [MROWS * HDIM];
__device__ float g_v   [MROWS * HDIM];
__device__ float g_xa  [MROWS * HDIM];
__device__ float g_ln1 [MROWS * HDIM];
__device__ float g_pre2[MROWS * HDIM];

__device__ uint2 g_hs  [MROWS * HPH];
__device__ uint2 g_qs  [MROWS * HPH];
__device__ uint2 g_ks  [MROWS * HPH];
__device__ uint2 g_ctxs[MROWS * HPH];
__device__ uint2 g_ln1s[MROWS * HPH];
__device__ uint2 g_mlps[MROWS * DFFH];

#define WQ0 0
#define WK0 786432
#define WV0 1572864
#define WO0 2359296
#define W10 3145728
#define W20 6291456
__device__ uint2 g_ws[9437184];

// ---------------- bf16 split helpers ----------------
__device__ __forceinline__ uint2 split2bf(float x0, float x1) {
    __nv_bfloat162 h = __floats2bfloat162_rn(x0, x1);
    float r0 = x0 - __bfloat162float(h.x);
    float r1 = x1 - __bfloat162float(h.y);
    __nv_bfloat162 l = __floats2bfloat162_rn(r0, r1);
    uint2 out;
    out.x = *reinterpret_cast<unsigned*>(&h);
    out.y = *reinterpret_cast<unsigned*>(&l);
    return out;
}

__device__ __forceinline__ void mma16(float c[4],
    unsigned a0, unsigned a1, unsigned a2, unsigned a3,
    unsigned b0, unsigned b1)
{
    asm volatile(
      "mma.sync.aligned.m16n8k16.row.col.f32.bf16.bf16.f32 "
      "{%0,%1,%2,%3},{%4,%5,%6,%7},{%8,%9},{%0,%1,%2,%3};"
      : "+f"(c[0]), "+f"(c[1]), "+f"(c[2]), "+f"(c[3])
      : "r"(a0), "r"(a1), "r"(a2), "r"(a3), "r"(b0), "r"(b1));
}

__device__ __forceinline__ void cpa16(void* s, const void* g) {
    unsigned a = (unsigned)__cvta_generic_to_shared(s);
    asm volatile("cp.async.cg.shared.global [%0], [%1], 16;" :: "r"(a), "l"(g));
}
#define CP_COMMIT() asm volatile("cp.async.commit_group;")
#define CP_WAIT0()  asm volatile("cp.async.wait_group 0;")

// ---------------- reductions ----------------
__device__ __forceinline__ float blockReduceSum(float v, float* sm) {
    int lane = threadIdx.x & 31, wid = threadIdx.x >> 5;
    #pragma unroll
    for (int o = 16; o; o >>= 1) v += __shfl_down_sync(0xffffffffu, v, o);
    if (lane == 0) sm[wid] = v;
    __syncthreads();
    float r = 0.f;
    if (wid == 0) {
        r = (lane < 8) ? sm[lane] : 0.f;
        #pragma unroll
        for (int o = 4; o; o >>= 1) r += __shfl_down_sync(0xffffffffu, r, o);
        if (lane == 0) sm[0] = r;
    }
    __syncthreads();
    r = sm[0];
    __syncthreads();
    return r;
}

// ---------------- weight split: W[k][n] -> Ws[k/2][n] (hi,lo uint2) ----------
__global__ __launch_bounds__(256) void wsplit_kernel(
    const float* __restrict__ src, uint2* __restrict__ dst, int N)
{
    int n  = blockIdx.x * 256 + threadIdx.x;
    int kp = blockIdx.y;
    dst[(size_t)kp * N + n] =
        split2bf(src[(size_t)(2*kp) * N + n], src[(size_t)(2*kp + 1) * N + n]);
}

// ---------------- embedding + eLN ----------------
__global__ __launch_bounds__(256) void embed_kernel(
    const int* __restrict__ timesteps, const float* __restrict__ s0,
    const float* __restrict__ s1, const float* __restrict__ act,
    const float* __restrict__ temb,
    const float* __restrict__ Ws, const float* __restrict__ bs,
    const float* __restrict__ Wa, const float* __restrict__ ba,
    const float* __restrict__ eg, const float* __restrict__ eb,
    float* __restrict__ out, uint2* __restrict__ outs)
{
    int s = blockIdx.x;
    int b = s / SS, sr = s % SS;
    int t = sr / 3, r = sr % 3;

    __shared__ float sIn[SDIM];
    __shared__ float red[32];

    const float* inp; const float* W; const float* bias; int Kin;
    if (r == 0)      { inp = s0  + (size_t)(b*TT + t)*SDIM; W = Ws; bias = bs; Kin = SDIM; }
    else if (r == 1) { inp = s1  + (size_t)(b*TT + t)*SDIM; W = Ws; bias = bs; Kin = SDIM; }
    else             { inp = act + (size_t)(b*TT + t)*ADIM; W = Wa; bias = ba; Kin = ADIM; }

    int tid = threadIdx.x;
    if (tid < Kin) sIn[tid] = inp[tid];
    __syncthreads();

    int tsv = timesteps[b*TT + t];
    const float* te = temb + (size_t)tsv * HDIM;

    int c0 = 2*tid;
    float a0 = bias[c0] + te[c0], a1 = bias[c0+1] + te[c0+1];
    for (int k = 0; k < Kin; k++) {
        float x = sIn[k];
        a0 = fmaf(x, W[(size_t)k*HDIM + c0],     a0);
        a1 = fmaf(x, W[(size_t)k*HDIM + c0 + 1], a1);
    }
    float sum = blockReduceSum(a0 + a1, red);
    float m = sum * (1.0f / HDIM);
    float d0 = a0 - m, d1 = a1 - m;
    float ssq = blockReduceSum(d0*d0 + d1*d1, red);
    float rstd = rsqrtf(ssq * (1.0f / HDIM) + 1e-5f);
    float o0 = d0 * rstd * eg[c0]     + eb[c0];
    float o1 = d1 * rstd * eg[c0 + 1] + eb[c0 + 1];
    *(float2*)(out + (size_t)s*HDIM + c0) = make_float2(o0, o1);
    outs[(size_t)s*HPH + tid] = split2bf(o0, o1);
}

// ============ tensor-core GEMM (bf16x3, split operands) ========================
// A: [M][K/2] uint2. B: [K/2][N] uint2. Tile 128xBN, k-chunk 32 (16 kp),
// 2-stage cp.async pipeline, ONE syncthreads per iteration, 2 CTAs/SM.
#define APAD 20
#define ASTG (128*APAD)

template<int BN>
__device__ __forceinline__ void tgemm_body(
    const uint2* __restrict__ A, const uint2* __restrict__ B,
    const float* __restrict__ bias, const float* __restrict__ res,
    float* __restrict__ C, uint2* __restrict__ Cs,
    int M, int N, int K, int ep, float scl, char* smraw)
{
    constexpr int TNF = BN / 32;
    constexpr int BST = BN + 4;
    constexpr int BSTG = 16 * BST;
    uint2* Asm = (uint2*)smraw;
    uint2* Bsm = Asm + 2*ASTG;

    const int tid  = threadIdx.x, lane = tid & 31, warp = tid >> 5;
    const int g    = lane >> 2,  tg   = lane & 3;
    const int wm0  = (warp >> 2) * 64, wn0 = (warp & 3) * (BN / 4);
    const int m0   = blockIdx.y * 128, n0 = blockIdx.x * BN;
    const int KW   = K >> 1;

    float acc[4][TNF][4];
    #pragma unroll
    for (int i = 0; i < 4; i++)
        #pragma unroll
        for (int j = 0; j < TNF; j++)
            #pragma unroll
            for (int l = 0; l < 4; l++) acc[i][j][l] = 0.f;

    const int T = K / 32;

    auto fill = [&](int t, int s) {
        uint2* Ad = Asm + s*ASTG;
        uint2* Bd = Bsm + s*BSTG;
        int kw0 = t * 16;
        #pragma unroll
        for (int i = 0; i < 4; i++) {
            int id = tid + 256*i, r = id >> 3, c = (id & 7) * 2;
            cpa16(Ad + r*APAD + c, A + (size_t)(m0 + r)*KW + kw0 + c);
        }
        if (BN == 128) {
            #pragma unroll
            for (int i = 0; i < 4; i++) {
                int id = tid + 256*i, kp = id >> 6, nc = (id & 63) * 2;
                cpa16(Bd + kp*BST + nc, B + (size_t)(kw0 + kp)*N + n0 + nc);
            }
        } else {
            #pragma unroll
            for (int i = 0; i < 2; i++) {
                int id = tid + 256*i, kp = id >> 5, nc = (id & 31) * 2;
                cpa16(Bd + kp*BST + nc, B + (size_t)(kw0 + kp)*N + n0 + nc);
            }
        }
        CP_COMMIT();
    };

    fill(0, 0);

    for (int t = 0; t < T; t++) {
        const int s = t & 1;
        CP_WAIT0();
        __syncthreads();
        if (t + 1 < T) fill(t + 1, s ^ 1);

        const uint2* As_ = Asm + s*ASTG;
        const uint2* Bs_ = Bsm + s*BSTG;
        #pragma unroll
        for (int ks = 0; ks < 2; ks++) {
            const int kb = ks * 8;
            uint2 bf[TNF][2];
            #pragma unroll
            for (int tn = 0; tn < TNF; tn++) {
                int n = wn0 + tn*8 + g;
                bf[tn][0] = Bs_[(kb + tg)*BST + n];
                bf[tn][1] = Bs_[(kb + tg + 4)*BST + n];
            }
            #pragma unroll
            for (int tm = 0; tm < 4; tm++) {
                int m = wm0 + tm*16 + g;
                uint2 a0 = As_[m*APAD + kb + tg];
                uint2 a1 = As_[(m+8)*APAD + kb + tg];
                uint2 a2 = As_[m*APAD + kb + tg + 4];
                uint2 a3 = As_[(m+8)*APAD + kb + tg + 4];
                #pragma unroll
                for (int tn = 0; tn < TNF; tn++) {
                    mma16(acc[tm][tn], a0.x,a1.x,a2.x,a3.x, bf[tn][0].x, bf[tn][1].x);
                    mma16(acc[tm][tn], a0.y,a1.y,a2.y,a3.y, bf[tn][0].x, bf[tn][1].x);
                    mma16(acc[tm][tn], a0.x,a1.x,a2.x,a3.x, bf[tn][0].y, bf[tn][1].y);
                }
            }
        }
    }

    #pragma unroll
    for (int tm = 0; tm < 4; tm++) {
        #pragma unroll
        for (int tn = 0; tn < TNF; tn++) {
            int row = m0 + wm0 + tm*16 + g;
            int col = n0 + wn0 + tn*8 + tg*2;
            float b0v = bias[col], b1v = bias[col+1];
            float v00 = acc[tm][tn][0] + b0v, v01 = acc[tm][tn][1] + b1v;
            float v10 = acc[tm][tn][2] + b0v, v11 = acc[tm][tn][3] + b1v;
            if (ep == EP_BIAS_RES) {
                v00 += res[(size_t)row*N + col];     v01 += res[(size_t)row*N + col + 1];
                v10 += res[(size_t)(row+8)*N + col]; v11 += res[(size_t)(row+8)*N + col + 1];
                *(float2*)(C + (size_t)row*N + col)     = make_float2(v00, v01);
                *(float2*)(C + (size_t)(row+8)*N + col) = make_float2(v10, v11);
            } else if (ep == EP_BIAS) {
                *(float2*)(C + (size_t)row*N + col)     = make_float2(v00, v01);
                *(float2*)(C + (size_t)(row+8)*N + col) = make_float2(v10, v11);
            } else {
                if (ep == EP_GELU_SPLIT) {
                    v00 = 0.5f*v00*(1.0f + erff(v00*0.70710678118654752f));
                    v01 = 0.5f*v01*(1.0f + erff(v01*0.70710678118654752f));
                    v10 = 0.5f*v10*(1.0f + erff(v10*0.70710678118654752f));
                    v11 = 0.5f*v11*(1.0f + erff(v11*0.70710678118654752f));
                } else {
                    v00 *= scl; v01 *= scl; v10 *= scl; v11 *= scl;
                }
                Cs[(size_t)row*(N>>1)     + (col>>1)] = split2bf(v00, v01);
                Cs[(size_t)(row+8)*(N>>1) + (col>>1)] = split2bf(v10, v11);
            }
        }
    }
}

template<int BN>
__global__ __launch_bounds__(256, 2) void tgemm_kernel(
    const uint2* __restrict__ A, const uint2* __restrict__ B,
    const float* __restrict__ bias, const float* __restrict__ res,
    float* __restrict__ C, uint2* __restrict__ Cs,
    int M, int N, int K, int ep)
{
    extern __shared__ char smraw[];
    tgemm_body<BN>(A, B, bias, res, C, Cs, M, N, K, ep, 1.0f, smraw);
}

// fused QKV (q scaled by 1/8 pre-split; v fp32)
__global__ __launch_bounds__(256, 2) void qkv_kernel(
    const uint2* __restrict__ hs,
    const uint2* __restrict__ wq, const uint2* __restrict__ wk, const uint2* __restrict__ wv,
    const float* __restrict__ bq, const float* __restrict__ bk, const float* __restrict__ bv,
    uint2* __restrict__ qs, uint2* __restrict__ ks, float* __restrict__ v)
{
    extern __shared__ char smraw[];
    if (blockIdx.z == 0)
        tgemm_body<128>(hs, wq, bq, nullptr, nullptr, qs, MROWS, HDIM, HDIM, EP_BIAS_SPLIT, 0.125f, smraw);
    else if (blockIdx.z == 1)
        tgemm_body<128>(hs, wk, bk, nullptr, nullptr, ks, MROWS, HDIM, HDIM, EP_BIAS_SPLIT, 1.0f, smraw);
    else
        tgemm_body<128>(hs, wv, bv, nullptr, v, nullptr, MROWS, HDIM, HDIM, EP_BIAS, 1.0f, smraw);
}

#define SM128 (2*(ASTG + 16*132)*(int)sizeof(uint2))
#define SM64  (2*(ASTG + 16*68 )*(int)sizeof(uint2))

// ================= flash attention (split Q/K inputs, split ctx output) ========
#define FLASH_KPAD 132
#define FLASH_VPAD 68
#define FLASH_SMEM ((32*FLASH_KPAD + 64*FLASH_VPAD) * (int)sizeof(uint2))

__global__ __launch_bounds__(256) void flash_kernel(
    const uint2* __restrict__ q, const uint2* __restrict__ k,
    const float* __restrict__ v, uint2* __restrict__ ctxs)
{
    extern __shared__ uint2 dsmem[];
    uint2 (*Ks)[FLASH_KPAD] = reinterpret_cast<uint2(*)[FLASH_KPAD]>(dsmem);
    uint2 (*Vs)[FLASH_VPAD] = reinterpret_cast<uint2(*)[FLASH_VPAD]>(dsmem + 32*FLASH_KPAD);

    const int it = (int)(gridDim.x - 1 - blockIdx.x);
    const int bh = blockIdx.y, b = bh >> 3, h = bh & 7;
    const uint2* qb = q + (size_t)b*SS*HPH + h*32;
    const uint2* kb = k + (size_t)b*SS*HPH + h*32;
    const float* vb = v + (size_t)b*SS*HDIM + h*DH;
    uint2* cb       = ctxs + (size_t)b*SS*HPH + h*32;

    const int tid  = threadIdx.x, lane = tid & 31, warp = tid >> 5;
    const int g    = lane >> 2,  tg   = lane & 3;
    const int i0   = it * 128;
    const int rowg = i0 + warp*16 + g;

    uint2 qf[4][4];
    {
        const uint2* qrg = qb + (size_t)rowg*HPH;
        const uint2* qr8 = qrg + 8*HPH;
        #pragma unroll
        for (int kk = 0; kk < 4; kk++) {
            qf[kk][0] = qrg[kk*8 + tg];
            qf[kk][1] = qr8[kk*8 + tg];
            qf[kk][2] = qrg[kk*8 + tg + 4];
            qf[kk][3] = qr8[kk*8 + tg + 4];
        }
    }

    float m0 = -1e30f, m1 = -1e30f, l0 = 0.f, l1 = 0.f;
    float o[8][4];
    #pragma unroll
    for (int nf = 0; nf < 8; nf++)
        #pragma unroll
        for (int l = 0; l < 4; l++) o[nf][l] = 0.f;

    const int kjr = tid >> 1, kcb = (tid & 1)*16;
    const int vjp = tid >> 2, vcb = (tid & 3)*16;

    for (int jt = 0; jt <= it; jt++) {
        const int j0 = jt * 128;
        {
            const uint2* krow = kb + (size_t)(j0 + kjr)*HPH + kcb;
            #pragma unroll
            for (int u = 0; u < 8; u++) {
                uint4 f = ((const uint4*)krow)[u];
                Ks[kcb + 2*u][kjr]     = make_uint2(f.x, f.y);
                Ks[kcb + 2*u + 1][kjr] = make_uint2(f.z, f.w);
            }
        }
        {
            const float* vr0 = vb + (size_t)(j0 + 2*vjp)*HDIM + vcb;
            const float* vr1 = vr0 + HDIM;
            #pragma unroll
            for (int u = 0; u < 4; u++) {
                float4 f0 = *(const float4*)(vr0 + u*4);
                float4 f1 = *(const float4*)(vr1 + u*4);
                Vs[vjp][vcb + u*4 + 0] = split2bf(f0.x, f1.x);
                Vs[vjp][vcb + u*4 + 1] = split2bf(f0.y, f1.y);
                Vs[vjp][vcb + u*4 + 2] = split2bf(f0.z, f1.z);
                Vs[vjp][vcb + u*4 + 3] = split2bf(f0.w, f1.w);
            }
        }
        __syncthreads();

        float s[16][4];
        #pragma unroll
        for (int jf = 0; jf < 16; jf++)
            #pragma unroll
            for (int l = 0; l < 4; l++) s[jf][l] = 0.f;

        #pragma unroll
        for (int kk = 0; kk < 4; kk++) {
            uint2 a0 = qf[kk][0], a1 = qf[kk][1], a2 = qf[kk][2], a3 = qf[kk][3];
            #pragma unroll
            for (int jf = 0; jf < 16; jf++) {
                uint2 b0 = Ks[kk*8 + tg][jf*8 + g];
                uint2 b1 = Ks[kk*8 + tg + 4][jf*8 + g];
                mma16(s[jf], a0.x,a1.x,a2.x,a3.x, b0.x, b1.x);
                mma16(s[jf], a0.y,a1.y,a2.y,a3.y, b0.x, b1.x);
                mma16(s[jf], a0.x,a1.x,a2.x,a3.x, b0.y, b1.y);
            }
        }

        if (jt == it) {
            const int r0 = warp*16 + g, r1 = r0 + 8;
            #pragma unroll
            for (int jf = 0; jf < 16; jf++) {
                int c0 = jf*8 + 2*tg;
                if (c0     > r0) s[jf][0] = -1e30f;
                if (c0 + 1 > r0) s[jf][1] = -1e30f;
                if (c0     > r1) s[jf][2] = -1e30f;
                if (c0 + 1 > r1) s[jf][3] = -1e30f;
            }
        }

        float tm0 = -1e30f, tm1 = -1e30f;
        #pragma unroll
        for (int jf = 0; jf < 16; jf++) {
            tm0 = fmaxf(tm0, fmaxf(s[jf][0], s[jf][1]));
            tm1 = fmaxf(tm1, fmaxf(s[jf][2], s[jf][3]));
        }
        tm0 = fmaxf(tm0, __shfl_xor_sync(0xffffffffu, tm0, 1));
        tm0 = fmaxf(tm0, __shfl_xor_sync(0xffffffffu, tm0, 2));
        tm1 = fmaxf(tm1, __shfl_xor_sync(0xffffffffu, tm1, 1));
        tm1 = fmaxf(tm1, __shfl_xor_sync(0xffffffffu, tm1, 2));

        float nm0 = fmaxf(m0, tm0), nm1 = fmaxf(m1, tm1);
        float al0 = __expf(m0 - nm0), al1 = __expf(m1 - nm1);
        m0 = nm0; m1 = nm1;

        float rs0 = 0.f, rs1 = 0.f;
        #pragma unroll
        for (int jf = 0; jf < 16; jf++) {
            s[jf][0] = __expf(s[jf][0] - nm0);
            s[jf][1] = __expf(s[jf][1] - nm0);
            s[jf][2] = __expf(s[jf][2] - nm1);
            s[jf][3] = __expf(s[jf][3] - nm1);
            rs0 += s[jf][0] + s[jf][1];
            rs1 += s[jf][2] + s[jf][3];
        }
        rs0 += __shfl_xor_sync(0xffffffffu, rs0, 1);
        rs0 += __shfl_xor_sync(0xffffffffu, rs0, 2);
        rs1 += __shfl_xor_sync(0xffffffffu, rs1, 1);
        rs1 += __shfl_xor_sync(0xffffffffu, rs1, 2);
        l0 = l0*al0 + rs0;
        l1 = l1*al1 + rs1;

        #pragma unroll
        for (int nf = 0; nf < 8; nf++) {
            o[nf][0] *= al0; o[nf][1] *= al0;
            o[nf][2] *= al1; o[nf][3] *= al1;
        }

        #pragma unroll
        for (int kk = 0; kk < 8; kk++) {
            uint2 A0 = split2bf(s[2*kk][0],   s[2*kk][1]);
            uint2 A1 = split2bf(s[2*kk][2],   s[2*kk][3]);
            uint2 A2 = split2bf(s[2*kk+1][0], s[2*kk+1][1]);
            uint2 A3 = split2bf(s[2*kk+1][2], s[2*kk+1][3]);
            #pragma unroll
            for (int nf = 0; nf < 8; nf++) {
                uint2 b0 = Vs[kk*8 + tg][nf*8 + g];
                uint2 b1 = Vs[kk*8 + tg + 4][nf*8 + g];
                mma16(o[nf], A0.x,A1.x,A2.x,A3.x, b0.x, b1.x);
                mma16(o[nf], A0.y,A1.y,A2.y,A3.y, b0.x, b1.x);
                mma16(o[nf], A0.x,A1.x,A2.x,A3.x, b0.y, b1.y);
            }
        }
        __syncthreads();
    }

    float inv0 = 1.0f / l0, inv1 = 1.0f / l1;
    uint2* crow0 = cb + (size_t)rowg*HPH;
    uint2* crow1 = crow0 + 8*HPH;
    #pragma unroll
    for (int nf = 0; nf < 8; nf++) {
        crow0[nf*4 + tg] = split2bf(o[nf][0]*inv0, o[nf][1]*inv0);
        crow1[nf*4 + tg] = split2bf(o[nf][2]*inv1, o[nf][3]*inv1);
    }
}

// ---------------- layernorm: one warp per row, shfl-only reductions -----------
__global__ __launch_bounds__(256) void ln_kernel(
    const float* __restrict__ x, const float* __restrict__ g,
    const float* __restrict__ b, float* __restrict__ out,
    uint2* __restrict__ outs)
{
    int row  = blockIdx.x * 8 + (threadIdx.x >> 5);
    int lane = threadIdx.x & 31;
    const float* xr = x + (size_t)row * HDIM;

    float4 xv[4];
    float sum = 0.f;
    #pragma unroll
    for (int i = 0; i < 4; i++) {
        xv[i] = *(const float4*)(xr + lane*4 + i*128);
        sum += (xv[i].x + xv[i].y) + (xv[i].z + xv[i].w);
    }
    #pragma unroll
    for (int o = 16; o; o >>= 1) sum += __shfl_xor_sync(0xffffffffu, sum, o);
    float m = sum * (1.0f / HDIM);

    float ssq = 0.f;
    #pragma unroll
    for (int i = 0; i < 4; i++) {
        xv[i].x -= m; xv[i].y -= m; xv[i].z -= m; xv[i].w -= m;
        ssq += xv[i].x*xv[i].x + xv[i].y*xv[i].y + xv[i].z*xv[i].z + xv[i].w*xv[i].w;
    }
    #pragma unroll
    for (int o = 16; o; o >>= 1) ssq += __shfl_xor_sync(0xffffffffu, ssq, o);
    float rstd = rsqrtf(ssq * (1.0f / HDIM) + 1e-5f);

    float* outr = out + (size_t)row * HDIM;
    uint2* outsr = outs + (size_t)row * HPH;
    #pragma unroll
    for (int i = 0; i < 4; i++) {
        int c = lane*4 + i*128;
        float4 gv = *(const float4*)(g + c);
        float4 bv = *(const float4*)(b + c);
        float4 ov;
        ov.x = xv[i].x * rstd * gv.x + bv.x;
        ov.y = xv[i].y * rstd * gv.y + bv.y;
        ov.z = xv[i].z * rstd * gv.z + bv.z;
        ov.w = xv[i].w * rstd * gv.w + bv.w;
        *(float4*)(outr + c) = ov;
        outsr[(c >> 1)    ] = split2bf(ov.x, ov.y);
        outsr[(c >> 1) + 1] = split2bf(ov.z, ov.w);
    }
}

// ---------------- final projection ----------------
__global__ __launch_bounds__(256) void final_kernel(
    const float* __restrict__ h, const float* __restrict__ Wp,
    const float* __restrict__ bp, float* __restrict__ out)
{
    int bt = blockIdx.x;
    int b = bt / TT, t = bt % TT;
    const float* row = h + ((size_t)b*SS + 3*t + 1) * HDIM;
    __shared__ float sRow[HDIM];
    __shared__ float part[8][ADIM];
    int tid = threadIdx.x;
    sRow[tid] = row[tid];
    sRow[tid + 256] = row[tid + 256];
    __syncthreads();
    int c = tid & 31, g = tid >> 5;
    float a = 0.f;
    for (int k = g*64; k < (g+1)*64; k++) a = fmaf(sRow[k], Wp[(size_t)k*ADIM + c], a);
    part[g][c] = a;
    __syncthreads();
    if (tid < ADIM) {
        float s = bp[tid];
        #pragma unroll
        for (int g2 = 0; g2 < 8; g2++) s += part[g2][tid];
        out[(size_t)bt*ADIM + tid] = s;
    }
}

// ---------------- driver ----------------
extern "C" void kernel_launch(void* const* d_in, const int* in_sizes, int n_in,
                              void* d_out, int out_size)
{
    const int*   timesteps = (const int*)  d_in[0];
    const float* state_0   = (const float*)d_in[1];
    const float* state_1   = (const float*)d_in[2];
    const float* actions   = (const float*)d_in[3];
    const float* time_emb  = (const float*)d_in[4];
    const float* Ws  = (const float*)d_in[5];
    const float* bs  = (const float*)d_in[6];
    const float* Wa  = (const float*)d_in[7];
    const float* ba  = (const float*)d_in[8];
    const float* Wq  = (const float*)d_in[9];
    const float* bq  = (const float*)d_in[10];
    const float* Wk  = (const float*)d_in[11];
    const float* bk  = (const float*)d_in[12];
    const float* Wv  = (const float*)d_in[13];
    const float* bv  = (const float*)d_in[14];
    const float* Wo  = (const float*)d_in[15];
    const float* bo  = (const float*)d_in[16];
    const float* W1  = (const float*)d_in[17];
    const float* b1  = (const float*)d_in[18];
    const float* W2  = (const float*)d_in[19];
    const float* b2  = (const float*)d_in[20];
    const float* ln1_g = (const float*)d_in[21];
    const float* ln1_b = (const float*)d_in[22];
    const float* ln2_g = (const float*)d_in[23];
    const float* ln2_b = (const float*)d_in[24];
    const float* eln_g = (const float*)d_in[25];
    const float* eln_b = (const float*)d_in[26];
    const float* Wp  = (const float*)d_in[27];
    const float* bp  = (const float*)d_in[28];

    float *h, *v, *xa, *ln1o, *pre2;
    uint2 *hs, *qs, *ks, *ctxs, *ln1s, *mlps, *ws;
    cudaGetSymbolAddress((void**)&h,    g_h);
    cudaGetSymbolAddress((void**)&v,    g_v);
    cudaGetSymbolAddress((void**)&xa,   g_xa);
    cudaGetSymbolAddress((void**)&ln1o, g_ln1);
    cudaGetSymbolAddress((void**)&pre2, g_pre2);
    cudaGetSymbolAddress((void**)&hs,   g_hs);
    cudaGetSymbolAddress((void**)&qs,   g_qs);
    cudaGetSymbolAddress((void**)&ks,   g_ks);
    cudaGetSymbolAddress((void**)&ctxs, g_ctxs);
    cudaGetSymbolAddress((void**)&ln1s, g_ln1s);
    cudaGetSymbolAddress((void**)&mlps, g_mlps);
    cudaGetSymbolAddress((void**)&ws,   g_ws);

    cudaFuncSetAttribute(flash_kernel,
                         cudaFuncAttributeMaxDynamicSharedMemorySize, FLASH_SMEM);
    cudaFuncSetAttribute(tgemm_kernel<128>,
                         cudaFuncAttributeMaxDynamicSharedMemorySize, SM128);
    cudaFuncSetAttribute(tgemm_kernel<64>,
                         cudaFuncAttributeMaxDynamicSharedMemorySize, SM64);
    cudaFuncSetAttribute(qkv_kernel,
                         cudaFuncAttributeMaxDynamicSharedMemorySize, SM128);

    wsplit_kernel<<<dim3(HDIM/256, NBLK*HDIM/2), 256>>>(Wq, ws + WQ0, HDIM);
    wsplit_kernel<<<dim3(HDIM/256, NBLK*HDIM/2), 256>>>(Wk, ws + WK0, HDIM);
    wsplit_kernel<<<dim3(HDIM/256, NBLK*HDIM/2), 256>>>(Wv, ws + WV0, HDIM);
    wsplit_kernel<<<dim3(HDIM/256, NBLK*HDIM/2), 256>>>(Wo, ws + WO0, HDIM);
    wsplit_kernel<<<dim3(DFF/256,  NBLK*HDIM/2), 256>>>(W1, ws + W10, DFF);
    wsplit_kernel<<<dim3(HDIM/256, NBLK*DFF/2),  256>>>(W2, ws + W20, HDIM);

    embed_kernel<<<BB*SS, 256>>>(timesteps, state_0, state_1, actions, time_emb,
                                 Ws, bs, Wa, ba, eln_g, eln_b, h, hs);

    dim3 gQKV(HDIM/128, MROWS/128, 3);   // (4, 48, 3)
    dim3 gH64(HDIM/64,  MROWS/128);      // (8, 48)
    dim3 gF  (DFF /128, MROWS/128);      // (16, 48)
    dim3 gFl (SS/128, BB*NH);            // (12, 32)

    for (int blk = 0; blk < NBLK; blk++) {
        const uint2* wqs = ws + WQ0 + (size_t)blk*131072;
        const uint2* wks = ws + WK0 + (size_t)blk*131072;
        const uint2* wvs = ws + WV0 + (size_t)blk*131072;
        const uint2* wos = ws + WO0 + (size_t)blk*131072;
        const uint2* w1s = ws + W10 + (size_t)blk*524288;
        const uint2* w2s = ws + W20 + (size_t)blk*524288;
        const float* bq_ = bq + (size_t)blk*HDIM;
        const float* bk_ = bk + (size_t)blk*HDIM;
        const float* bv_ = bv + (size_t)blk*HDIM;
        const float* bo_ = bo + (size_t)blk*HDIM;
        const float* b1_ = b1 + (size_t)blk*DFF;
        const float* b2_ = b2 + (size_t)blk*HDIM;
        const float* g1_ = ln1_g + (size_t)blk*HDIM;
        const float* e1_ = ln1_b + (size_t)blk*HDIM;
        const float* g2_ = ln2_g + (size_t)blk*HDIM;
        const float* e2_ = ln2_b + (size_t)blk*HDIM;

        qkv_kernel<<<gQKV, 256, SM128>>>(hs, wqs, wks, wvs, bq_, bk_, bv_, qs, ks, v);

        flash_kernel<<<gFl, 256, FLASH_SMEM>>>(qs, ks, v, ctxs);

        tgemm_kernel<64> <<<gH64, 256, SM64>>>(ctxs, wos, bo_, h, xa, nullptr,
                                               MROWS, HDIM, HDIM, EP_BIAS_RES);
        ln_kernel<<<MROWS/8, 256>>>(xa, g1_, e1_, ln1o, ln1s);
        tgemm_kernel<128><<<gF, 256, SM128>>>(ln1s, w1s, b1_, nullptr, nullptr, mlps,
                                              MROWS, DFF, HDIM, EP_GELU_SPLIT);
        tgemm_kernel<64> <<<gH64, 256, SM64>>>(mlps, w2s, b2_, ln1o, pre2, nullptr,
                                               MROWS, HDIM, DFF, EP_BIAS_RES);
        ln_kernel<<<MROWS/8, 256>>>(pre2, g2_, e2_, h, hs);
    }

    final_kernel<<<BB*TT, 256>>>(h, Wp, bp, (float*)d_out);
}

// round 12
// speedup vs baseline: 2.7121x; 1.0069x over previous
#include <cuda_runtime.h>
#include <cuda_bf16.h>
#include <math.h>

#define BB 4
#define TT 512
#define SS 1536
#define SDIM 64
#define ADIM 32
#define HDIM 512
#define HPH 256
#define NH 8
#define DH 64
#define NBLK 6
#define DFFH 1024
#define DFF 2048
#define MROWS (BB*SS)

enum { EP_BIAS = 0, EP_BIAS_RES = 1, EP_GELU_SPLIT = 2, EP_BIAS_SPLIT = 3 };

// ---------------- scratch ----------------
__device__ float g_h  [MROWS * HDIM];
__device__ float g_v  [MROWS * HDIM];
__device__ float g_p0 [MROWS * HDIM];   // split-K partial 0
__device__ float g_p1 [MROWS * HDIM];   // split-K partial 1
__device__ float g_ln1[MROWS * HDIM];

__device__ uint2 g_hs  [MROWS * HPH];
__device__ uint2 g_qs  [MROWS * HPH];
__device__ uint2 g_ks  [MROWS * HPH];
__device__ uint2 g_ctxs[MROWS * HPH];
__device__ uint2 g_ln1s[MROWS * HPH];
__device__ uint2 g_mlps[MROWS * DFFH];

#define WQ0 0
#define WK0 786432
#define WV0 1572864
#define WO0 2359296
#define W10 3145728
#define W20 6291456
__device__ uint2 g_ws[9437184];

// ---------------- bf16 split helpers ----------------
__device__ __forceinline__ uint2 split2bf(float x0, float x1) {
    __nv_bfloat162 h = __floats2bfloat162_rn(x0, x1);
    float r0 = x0 - __bfloat162float(h.x);
    float r1 = x1 - __bfloat162float(h.y);
    __nv_bfloat162 l = __floats2bfloat162_rn(r0, r1);
    uint2 out;
    out.x = *reinterpret_cast<unsigned*>(&h);
    out.y = *reinterpret_cast<unsigned*>(&l);
    return out;
}

__device__ __forceinline__ void mma16(float c[4],
    unsigned a0, unsigned a1, unsigned a2, unsigned a3,
    unsigned b0, unsigned b1)
{
    asm volatile(
      "mma.sync.aligned.m16n8k16.row.col.f32.bf16.bf16.f32 "
      "{%0,%1,%2,%3},{%4,%5,%6,%7},{%8,%9},{%0,%1,%2,%3};"
      : "+f"(c[0]), "+f"(c[1]), "+f"(c[2]), "+f"(c[3])
      : "r"(a0), "r"(a1), "r"(a2), "r"(a3), "r"(b0), "r"(b1));
}

__device__ __forceinline__ void cpa16(void* s, const void* g) {
    unsigned a = (unsigned)__cvta_generic_to_shared(s);
    asm volatile("cp.async.cg.shared.global [%0], [%1], 16;" :: "r"(a), "l"(g));
}
#define CP_COMMIT() asm volatile("cp.async.commit_group;")
#define CP_WAIT0()  asm volatile("cp.async.wait_group 0;")

// ---------------- reductions ----------------
__device__ __forceinline__ float blockReduceSum(float v, float* sm) {
    int lane = threadIdx.x & 31, wid = threadIdx.x >> 5;
    #pragma unroll
    for (int o = 16; o; o >>= 1) v += __shfl_down_sync(0xffffffffu, v, o);
    if (lane == 0) sm[wid] = v;
    __syncthreads();
    float r = 0.f;
    if (wid == 0) {
        r = (lane < 8) ? sm[lane] : 0.f;
        #pragma unroll
        for (int o = 4; o; o >>= 1) r += __shfl_down_sync(0xffffffffu, r, o);
        if (lane == 0) sm[0] = r;
    }
    __syncthreads();
    r = sm[0];
    __syncthreads();
    return r;
}

// ---------------- weight split: W[k][n] -> Ws[k/2][n] (hi,lo uint2) ----------
__global__ __launch_bounds__(256) void wsplit_kernel(
    const float* __restrict__ src, uint2* __restrict__ dst, int N)
{
    int n  = blockIdx.x * 256 + threadIdx.x;
    int kp = blockIdx.y;
    dst[(size_t)kp * N + n] =
        split2bf(src[(size_t)(2*kp) * N + n], src[(size_t)(2*kp + 1) * N + n]);
}

// ---------------- embedding + eLN ----------------
__global__ __launch_bounds__(256) void embed_kernel(
    const int* __restrict__ timesteps, const float* __restrict__ s0,
    const float* __restrict__ s1, const float* __restrict__ act,
    const float* __restrict__ temb,
    const float* __restrict__ Ws, const float* __restrict__ bs,
    const float* __restrict__ Wa, const float* __restrict__ ba,
    const float* __restrict__ eg, const float* __restrict__ eb,
    float* __restrict__ out, uint2* __restrict__ outs)
{
    int s = blockIdx.x;
    int b = s / SS, sr = s % SS;
    int t = sr / 3, r = sr % 3;

    __shared__ float sIn[SDIM];
    __shared__ float red[32];

    const float* inp; const float* W; const float* bias; int Kin;
    if (r == 0)      { inp = s0  + (size_t)(b*TT + t)*SDIM; W = Ws; bias = bs; Kin = SDIM; }
    else if (r == 1) { inp = s1  + (size_t)(b*TT + t)*SDIM; W = Ws; bias = bs; Kin = SDIM; }
    else             { inp = act + (size_t)(b*TT + t)*ADIM; W = Wa; bias = ba; Kin = ADIM; }

    int tid = threadIdx.x;
    if (tid < Kin) sIn[tid] = inp[tid];
    __syncthreads();

    int tsv = timesteps[b*TT + t];
    const float* te = temb + (size_t)tsv * HDIM;

    int c0 = 2*tid;
    float a0 = bias[c0] + te[c0], a1 = bias[c0+1] + te[c0+1];
    for (int k = 0; k < Kin; k++) {
        float x = sIn[k];
        a0 = fmaf(x, W[(size_t)k*HDIM + c0],     a0);
        a1 = fmaf(x, W[(size_t)k*HDIM + c0 + 1], a1);
    }
    float sum = blockReduceSum(a0 + a1, red);
    float m = sum * (1.0f / HDIM);
    float d0 = a0 - m, d1 = a1 - m;
    float ssq = blockReduceSum(d0*d0 + d1*d1, red);
    float rstd = rsqrtf(ssq * (1.0f / HDIM) + 1e-5f);
    float o0 = d0 * rstd * eg[c0]     + eb[c0];
    float o1 = d1 * rstd * eg[c0 + 1] + eb[c0 + 1];
    *(float2*)(out + (size_t)s*HDIM + c0) = make_float2(o0, o1);
    outs[(size_t)s*HPH + tid] = split2bf(o0, o1);
}

// ============ tensor-core GEMM (bf16x3, split operands) ========================
#define APAD 20
#define ASTG (128*APAD)

// main-loop macro-free shared body for full-K kernels
template<int BN>
__device__ __forceinline__ void tgemm_body(
    const uint2* __restrict__ A, const uint2* __restrict__ B,
    const float* __restrict__ bias,
    float* __restrict__ C, uint2* __restrict__ Cs,
    int M, int N, int K, int ep, float scl, char* smraw)
{
    constexpr int TNF = BN / 32;
    constexpr int BST = BN + 4;
    constexpr int BSTG = 16 * BST;
    uint2* Asm = (uint2*)smraw;
    uint2* Bsm = Asm + 2*ASTG;

    const int tid  = threadIdx.x, lane = tid & 31, warp = tid >> 5;
    const int g    = lane >> 2,  tg   = lane & 3;
    const int wm0  = (warp >> 2) * 64, wn0 = (warp & 3) * (BN / 4);
    const int m0   = blockIdx.y * 128, n0 = blockIdx.x * BN;
    const int KW   = K >> 1;

    float acc[4][TNF][4];
    #pragma unroll
    for (int i = 0; i < 4; i++)
        #pragma unroll
        for (int j = 0; j < TNF; j++)
            #pragma unroll
            for (int l = 0; l < 4; l++) acc[i][j][l] = 0.f;

    const int T = K / 32;

    auto fill = [&](int t, int s) {
        uint2* Ad = Asm + s*ASTG;
        uint2* Bd = Bsm + s*BSTG;
        int kw0 = t * 16;
        #pragma unroll
        for (int i = 0; i < 4; i++) {
            int id = tid + 256*i, r = id >> 3, c = (id & 7) * 2;
            cpa16(Ad + r*APAD + c, A + (size_t)(m0 + r)*KW + kw0 + c);
        }
        if (BN == 128) {
            #pragma unroll
            for (int i = 0; i < 4; i++) {
                int id = tid + 256*i, kp = id >> 6, nc = (id & 63) * 2;
                cpa16(Bd + kp*BST + nc, B + (size_t)(kw0 + kp)*N + n0 + nc);
            }
        } else {
            #pragma unroll
            for (int i = 0; i < 2; i++) {
                int id = tid + 256*i, kp = id >> 5, nc = (id & 31) * 2;
                cpa16(Bd + kp*BST + nc, B + (size_t)(kw0 + kp)*N + n0 + nc);
            }
        }
        CP_COMMIT();
    };

    fill(0, 0);

    for (int t = 0; t < T; t++) {
        const int s = t & 1;
        CP_WAIT0();
        __syncthreads();
        if (t + 1 < T) fill(t + 1, s ^ 1);

        const uint2* As_ = Asm + s*ASTG;
        const uint2* Bs_ = Bsm + s*BSTG;
        #pragma unroll
        for (int ks = 0; ks < 2; ks++) {
            const int kb = ks * 8;
            uint2 bf[TNF][2];
            #pragma unroll
            for (int tn = 0; tn < TNF; tn++) {
                int n = wn0 + tn*8 + g;
                bf[tn][0] = Bs_[(kb + tg)*BST + n];
                bf[tn][1] = Bs_[(kb + tg + 4)*BST + n];
            }
            #pragma unroll
            for (int tm = 0; tm < 4; tm++) {
                int m = wm0 + tm*16 + g;
                uint2 a0 = As_[m*APAD + kb + tg];
                uint2 a1 = As_[(m+8)*APAD + kb + tg];
                uint2 a2 = As_[m*APAD + kb + tg + 4];
                uint2 a3 = As_[(m+8)*APAD + kb + tg + 4];
                #pragma unroll
                for (int tn = 0; tn < TNF; tn++) {
                    mma16(acc[tm][tn], a0.x,a1.x,a2.x,a3.x, bf[tn][0].x, bf[tn][1].x);
                    mma16(acc[tm][tn], a0.y,a1.y,a2.y,a3.y, bf[tn][0].x, bf[tn][1].x);
                    mma16(acc[tm][tn], a0.x,a1.x,a2.x,a3.x, bf[tn][0].y, bf[tn][1].y);
                }
            }
        }
    }

    #pragma unroll
    for (int tm = 0; tm < 4; tm++) {
        #pragma unroll
        for (int tn = 0; tn < TNF; tn++) {
            int row = m0 + wm0 + tm*16 + g;
            int col = n0 + wn0 + tn*8 + tg*2;
            float b0v = bias[col], b1v = bias[col+1];
            float v00 = acc[tm][tn][0] + b0v, v01 = acc[tm][tn][1] + b1v;
            float v10 = acc[tm][tn][2] + b0v, v11 = acc[tm][tn][3] + b1v;
            if (ep == EP_BIAS) {
                *(float2*)(C + (size_t)row*N + col)     = make_float2(v00, v01);
                *(float2*)(C + (size_t)(row+8)*N + col) = make_float2(v10, v11);
            } else {
                if (ep == EP_GELU_SPLIT) {
                    v00 = 0.5f*v00*(1.0f + erff(v00*0.70710678118654752f));
                    v01 = 0.5f*v01*(1.0f + erff(v01*0.70710678118654752f));
                    v10 = 0.5f*v10*(1.0f + erff(v10*0.70710678118654752f));
                    v11 = 0.5f*v11*(1.0f + erff(v11*0.70710678118654752f));
                } else {
                    v00 *= scl; v01 *= scl; v10 *= scl; v11 *= scl;
                }
                Cs[(size_t)row*(N>>1)     + (col>>1)] = split2bf(v00, v01);
                Cs[(size_t)(row+8)*(N>>1) + (col>>1)] = split2bf(v10, v11);
            }
        }
    }
}

template<int BN>
__global__ __launch_bounds__(256, 2) void tgemm_kernel(
    const uint2* __restrict__ A, const uint2* __restrict__ B,
    const float* __restrict__ bias,
    float* __restrict__ C, uint2* __restrict__ Cs,
    int M, int N, int K, int ep)
{
    extern __shared__ char smraw[];
    tgemm_body<BN>(A, B, bias, C, Cs, M, N, K, ep, 1.0f, smraw);
}

// ---------- split-K (2-way) GEMM: raw partials, BN=64, z selects K-half -------
__global__ __launch_bounds__(256, 2) void tgemm_splitk_kernel(
    const uint2* __restrict__ A, const uint2* __restrict__ B,
    float* __restrict__ P0, float* __restrict__ P1,
    int N, int K)      // K = full depth; each z does K/2
{
    constexpr int BN = 64, TNF = 2, BST = BN + 4, BSTG = 16 * BST;
    extern __shared__ char smraw[];
    uint2* Asm = (uint2*)smraw;
    uint2* Bsm = Asm + 2*ASTG;

    const int tid  = threadIdx.x, lane = tid & 31, warp = tid >> 5;
    const int g    = lane >> 2,  tg   = lane & 3;
    const int wm0  = (warp >> 2) * 64, wn0 = (warp & 3) * 16;
    const int m0   = blockIdx.y * 128, n0 = blockIdx.x * BN;
    const int z    = blockIdx.z;
    const int KW   = K >> 1;           // full row stride (uint2 words)
    const int KWS  = KW >> 1;          // words per K-slice
    const int kwb  = z * KWS;          // word offset of this slice
    float* P = z ? P1 : P0;

    float acc[4][TNF][4];
    #pragma unroll
    for (int i = 0; i < 4; i++)
        #pragma unroll
        for (int j = 0; j < TNF; j++)
            #pragma unroll
            for (int l = 0; l < 4; l++) acc[i][j][l] = 0.f;

    const int T = (K / 2) / 32;

    auto fill = [&](int t, int s) {
        uint2* Ad = Asm + s*ASTG;
        uint2* Bd = Bsm + s*BSTG;
        int kw0 = kwb + t * 16;
        #pragma unroll
        for (int i = 0; i < 4; i++) {
            int id = tid + 256*i, r = id >> 3, c = (id & 7) * 2;
            cpa16(Ad + r*APAD + c, A + (size_t)(m0 + r)*KW + kw0 + c);
        }
        #pragma unroll
        for (int i = 0; i < 2; i++) {
            int id = tid + 256*i, kp = id >> 5, nc = (id & 31) * 2;
            cpa16(Bd + kp*BST + nc, B + (size_t)(kw0 + kp)*N + n0 + nc);
        }
        CP_COMMIT();
    };

    fill(0, 0);

    for (int t = 0; t < T; t++) {
        const int s = t & 1;
        CP_WAIT0();
        __syncthreads();
        if (t + 1 < T) fill(t + 1, s ^ 1);

        const uint2* As_ = Asm + s*ASTG;
        const uint2* Bs_ = Bsm + s*BSTG;
        #pragma unroll
        for (int ks = 0; ks < 2; ks++) {
            const int kb = ks * 8;
            uint2 bf[TNF][2];
            #pragma unroll
            for (int tn = 0; tn < TNF; tn++) {
                int n = wn0 + tn*8 + g;
                bf[tn][0] = Bs_[(kb + tg)*BST + n];
                bf[tn][1] = Bs_[(kb + tg + 4)*BST + n];
            }
            #pragma unroll
            for (int tm = 0; tm < 4; tm++) {
                int m = wm0 + tm*16 + g;
                uint2 a0 = As_[m*APAD + kb + tg];
                uint2 a1 = As_[(m+8)*APAD + kb + tg];
                uint2 a2 = As_[m*APAD + kb + tg + 4];
                uint2 a3 = As_[(m+8)*APAD + kb + tg + 4];
                #pragma unroll
                for (int tn = 0; tn < TNF; tn++) {
                    mma16(acc[tm][tn], a0.x,a1.x,a2.x,a3.x, bf[tn][0].x, bf[tn][1].x);
                    mma16(acc[tm][tn], a0.y,a1.y,a2.y,a3.y, bf[tn][0].x, bf[tn][1].x);
                    mma16(acc[tm][tn], a0.x,a1.x,a2.x,a3.x, bf[tn][0].y, bf[tn][1].y);
                }
            }
        }
    }

    #pragma unroll
    for (int tm = 0; tm < 4; tm++)
        #pragma unroll
        for (int tn = 0; tn < TNF; tn++) {
            int row = m0 + wm0 + tm*16 + g;
            int col = n0 + wn0 + tn*8 + tg*2;
            *(float2*)(P + (size_t)row*N + col)     = make_float2(acc[tm][tn][0], acc[tm][tn][1]);
            *(float2*)(P + (size_t)(row+8)*N + col) = make_float2(acc[tm][tn][2], acc[tm][tn][3]);
        }
}

// fused QKV (q scaled by 1/8 pre-split; v fp32)
__global__ __launch_bounds__(256, 2) void qkv_kernel(
    const uint2* __restrict__ hs,
    const uint2* __restrict__ wq, const uint2* __restrict__ wk, const uint2* __restrict__ wv,
    const float* __restrict__ bq, const float* __restrict__ bk, const float* __restrict__ bv,
    uint2* __restrict__ qs, uint2* __restrict__ ks, float* __restrict__ v)
{
    extern __shared__ char smraw[];
    if (blockIdx.z == 0)
        tgemm_body<128>(hs, wq, bq, nullptr, qs, MROWS, HDIM, HDIM, EP_BIAS_SPLIT, 0.125f, smraw);
    else if (blockIdx.z == 1)
        tgemm_body<128>(hs, wk, bk, nullptr, ks, MROWS, HDIM, HDIM, EP_BIAS_SPLIT, 1.0f, smraw);
    else
        tgemm_body<128>(hs, wv, bv, v, nullptr, MROWS, HDIM, HDIM, EP_BIAS, 1.0f, smraw);
}

#define SM128 (2*(ASTG + 16*132)*(int)sizeof(uint2))
#define SM64  (2*(ASTG + 16*68 )*(int)sizeof(uint2))

// ================= flash attention =============================================
#define FLASH_KPAD 132
#define FLASH_VPAD 68
#define FLASH_SMEM ((32*FLASH_KPAD + 64*FLASH_VPAD) * (int)sizeof(uint2))

__global__ __launch_bounds__(256) void flash_kernel(
    const uint2* __restrict__ q, const uint2* __restrict__ k,
    const float* __restrict__ v, uint2* __restrict__ ctxs)
{
    extern __shared__ uint2 dsmem[];
    uint2 (*Ks)[FLASH_KPAD] = reinterpret_cast<uint2(*)[FLASH_KPAD]>(dsmem);
    uint2 (*Vs)[FLASH_VPAD] = reinterpret_cast<uint2(*)[FLASH_VPAD]>(dsmem + 32*FLASH_KPAD);

    const int it = (int)(gridDim.x - 1 - blockIdx.x);
    const int bh = blockIdx.y, b = bh >> 3, h = bh & 7;
    const uint2* qb = q + (size_t)b*SS*HPH + h*32;
    const uint2* kb = k + (size_t)b*SS*HPH + h*32;
    const float* vb = v + (size_t)b*SS*HDIM + h*DH;
    uint2* cb       = ctxs + (size_t)b*SS*HPH + h*32;

    const int tid  = threadIdx.x, lane = tid & 31, warp = tid >> 5;
    const int g    = lane >> 2,  tg   = lane & 3;
    const int i0   = it * 128;
    const int rowg = i0 + warp*16 + g;

    uint2 qf[4][4];
    {
        const uint2* qrg = qb + (size_t)rowg*HPH;
        const uint2* qr8 = qrg + 8*HPH;
        #pragma unroll
        for (int kk = 0; kk < 4; kk++) {
            qf[kk][0] = qrg[kk*8 + tg];
            qf[kk][1] = qr8[kk*8 + tg];
            qf[kk][2] = qrg[kk*8 + tg + 4];
            qf[kk][3] = qr8[kk*8 + tg + 4];
        }
    }

    float m0 = -1e30f, m1 = -1e30f, l0 = 0.f, l1 = 0.f;
    float o[8][4];
    #pragma unroll
    for (int nf = 0; nf < 8; nf++)
        #pragma unroll
        for (int l = 0; l < 4; l++) o[nf][l] = 0.f;

    const int kjr = tid >> 1, kcb = (tid & 1)*16;
    const int vjp = tid >> 2, vcb = (tid & 3)*16;

    for (int jt = 0; jt <= it; jt++) {
        const int j0 = jt * 128;
        {
            const uint2* krow = kb + (size_t)(j0 + kjr)*HPH + kcb;
            #pragma unroll
            for (int u = 0; u < 8; u++) {
                uint4 f = ((const uint4*)krow)[u];
                Ks[kcb + 2*u][kjr]     = make_uint2(f.x, f.y);
                Ks[kcb + 2*u + 1][kjr] = make_uint2(f.z, f.w);
            }
        }
        {
            const float* vr0 = vb + (size_t)(j0 + 2*vjp)*HDIM + vcb;
            const float* vr1 = vr0 + HDIM;
            #pragma unroll
            for (int u = 0; u < 4; u++) {
                float4 f0 = *(const float4*)(vr0 + u*4);
                float4 f1 = *(const float4*)(vr1 + u*4);
                Vs[vjp][vcb + u*4 + 0] = split2bf(f0.x, f1.x);
                Vs[vjp][vcb + u*4 + 1] = split2bf(f0.y, f1.y);
                Vs[vjp][vcb + u*4 + 2] = split2bf(f0.z, f1.z);
                Vs[vjp][vcb + u*4 + 3] = split2bf(f0.w, f1.w);
            }
        }
        __syncthreads();

        float s[16][4];
        #pragma unroll
        for (int jf = 0; jf < 16; jf++)
            #pragma unroll
            for (int l = 0; l < 4; l++) s[jf][l] = 0.f;

        #pragma unroll
        for (int kk = 0; kk < 4; kk++) {
            uint2 a0 = qf[kk][0], a1 = qf[kk][1], a2 = qf[kk][2], a3 = qf[kk][3];
            #pragma unroll
            for (int jf = 0; jf < 16; jf++) {
                uint2 b0 = Ks[kk*8 + tg][jf*8 + g];
                uint2 b1 = Ks[kk*8 + tg + 4][jf*8 + g];
                mma16(s[jf], a0.x,a1.x,a2.x,a3.x, b0.x, b1.x);
                mma16(s[jf], a0.y,a1.y,a2.y,a3.y, b0.x, b1.x);
                mma16(s[jf], a0.x,a1.x,a2.x,a3.x, b0.y, b1.y);
            }
        }

        if (jt == it) {
            const int r0 = warp*16 + g, r1 = r0 + 8;
            #pragma unroll
            for (int jf = 0; jf < 16; jf++) {
                int c0 = jf*8 + 2*tg;
                if (c0     > r0) s[jf][0] = -1e30f;
                if (c0 + 1 > r0) s[jf][1] = -1e30f;
                if (c0     > r1) s[jf][2] = -1e30f;
                if (c0 + 1 > r1) s[jf][3] = -1e30f;
            }
        }

        float tm0 = -1e30f, tm1 = -1e30f;
        #pragma unroll
        for (int jf = 0; jf < 16; jf++) {
            tm0 = fmaxf(tm0, fmaxf(s[jf][0], s[jf][1]));
            tm1 = fmaxf(tm1, fmaxf(s[jf][2], s[jf][3]));
        }
        tm0 = fmaxf(tm0, __shfl_xor_sync(0xffffffffu, tm0, 1));
        tm0 = fmaxf(tm0, __shfl_xor_sync(0xffffffffu, tm0, 2));
        tm1 = fmaxf(tm1, __shfl_xor_sync(0xffffffffu, tm1, 1));
        tm1 = fmaxf(tm1, __shfl_xor_sync(0xffffffffu, tm1, 2));

        float nm0 = fmaxf(m0, tm0), nm1 = fmaxf(m1, tm1);
        float al0 = __expf(m0 - nm0), al1 = __expf(m1 - nm1);
        m0 = nm0; m1 = nm1;

        float rs0 = 0.f, rs1 = 0.f;
        #pragma unroll
        for (int jf = 0; jf < 16; jf++) {
            s[jf][0] = __expf(s[jf][0] - nm0);
            s[jf][1] = __expf(s[jf][1] - nm0);
            s[jf][2] = __expf(s[jf][2] - nm1);
            s[jf][3] = __expf(s[jf][3] - nm1);
            rs0 += s[jf][0] + s[jf][1];
            rs1 += s[jf][2] + s[jf][3];
        }
        rs0 += __shfl_xor_sync(0xffffffffu, rs0, 1);
        rs0 += __shfl_xor_sync(0xffffffffu, rs0, 2);
        rs1 += __shfl_xor_sync(0xffffffffu, rs1, 1);
        rs1 += __shfl_xor_sync(0xffffffffu, rs1, 2);
        l0 = l0*al0 + rs0;
        l1 = l1*al1 + rs1;

        #pragma unroll
        for (int nf = 0; nf < 8; nf++) {
            o[nf][0] *= al0; o[nf][1] *= al0;
            o[nf][2] *= al1; o[nf][3] *= al1;
        }

        #pragma unroll
        for (int kk = 0; kk < 8; kk++) {
            uint2 A0 = split2bf(s[2*kk][0],   s[2*kk][1]);
            uint2 A1 = split2bf(s[2*kk][2],   s[2*kk][3]);
            uint2 A2 = split2bf(s[2*kk+1][0], s[2*kk+1][1]);
            uint2 A3 = split2bf(s[2*kk+1][2], s[2*kk+1][3]);
            #pragma unroll
            for (int nf = 0; nf < 8; nf++) {
                uint2 b0 = Vs[kk*8 + tg][nf*8 + g];
                uint2 b1 = Vs[kk*8 + tg + 4][nf*8 + g];
                mma16(o[nf], A0.x,A1.x,A2.x,A3.x, b0.x, b1.x);
                mma16(o[nf], A0.y,A1.y,A2.y,A3.y, b0.x, b1.x);
                mma16(o[nf], A0.x,A1.x,A2.x,A3.x, b0.y, b1.y);
            }
        }
        __syncthreads();
    }

    float inv0 = 1.0f / l0, inv1 = 1.0f / l1;
    uint2* crow0 = cb + (size_t)rowg*HPH;
    uint2* crow1 = crow0 + 8*HPH;
    #pragma unroll
    for (int nf = 0; nf < 8; nf++) {
        crow0[nf*4 + tg] = split2bf(o[nf][0]*inv0, o[nf][1]*inv0);
        crow1[nf*4 + tg] = split2bf(o[nf][2]*inv1, o[nf][3]*inv1);
    }
}

// ---------- layernorm over (p0 + p1 + bias + res): warp-per-row ---------------
__global__ __launch_bounds__(256) void ln_sum_kernel(
    const float* __restrict__ p0, const float* __restrict__ p1,
    const float* __restrict__ bias, const float* __restrict__ res,
    const float* __restrict__ g, const float* __restrict__ b,
    float* __restrict__ out, uint2* __restrict__ outs)
{
    int row  = blockIdx.x * 8 + (threadIdx.x >> 5);
    int lane = threadIdx.x & 31;
    const float* p0r = p0 + (size_t)row * HDIM;
    const float* p1r = p1 + (size_t)row * HDIM;
    const float* rr  = res + (size_t)row * HDIM;

    float4 xv[4];
    float sum = 0.f;
    #pragma unroll
    for (int i = 0; i < 4; i++) {
        int c = lane*4 + i*128;
        float4 a = *(const float4*)(p0r + c);
        float4 d = *(const float4*)(p1r + c);
        float4 e = *(const float4*)(bias + c);
        float4 f = *(const float4*)(rr + c);
        xv[i].x = a.x + d.x + e.x + f.x;
        xv[i].y = a.y + d.y + e.y + f.y;
        xv[i].z = a.z + d.z + e.z + f.z;
        xv[i].w = a.w + d.w + e.w + f.w;
        sum += (xv[i].x + xv[i].y) + (xv[i].z + xv[i].w);
    }
    #pragma unroll
    for (int o = 16; o; o >>= 1) sum += __shfl_xor_sync(0xffffffffu, sum, o);
    float m = sum * (1.0f / HDIM);

    float ssq = 0.f;
    #pragma unroll
    for (int i = 0; i < 4; i++) {
        xv[i].x -= m; xv[i].y -= m; xv[i].z -= m; xv[i].w -= m;
        ssq += xv[i].x*xv[i].x + xv[i].y*xv[i].y + xv[i].z*xv[i].z + xv[i].w*xv[i].w;
    }
    #pragma unroll
    for (int o = 16; o; o >>= 1) ssq += __shfl_xor_sync(0xffffffffu, ssq, o);
    float rstd = rsqrtf(ssq * (1.0f / HDIM) + 1e-5f);

    float* outr = out + (size_t)row * HDIM;
    uint2* outsr = outs + (size_t)row * HPH;
    #pragma unroll
    for (int i = 0; i < 4; i++) {
        int c = lane*4 + i*128;
        float4 gv = *(const float4*)(g + c);
        float4 bv = *(const float4*)(b + c);
        float4 ov;
        ov.x = xv[i].x * rstd * gv.x + bv.x;
        ov.y = xv[i].y * rstd * gv.y + bv.y;
        ov.z = xv[i].z * rstd * gv.z + bv.z;
        ov.w = xv[i].w * rstd * gv.w + bv.w;
        *(float4*)(outr + c) = ov;
        outsr[(c >> 1)    ] = split2bf(ov.x, ov.y);
        outsr[(c >> 1) + 1] = split2bf(ov.z, ov.w);
    }
}

// ---------------- final projection ----------------
__global__ __launch_bounds__(256) void final_kernel(
    const float* __restrict__ h, const float* __restrict__ Wp,
    const float* __restrict__ bp, float* __restrict__ out)
{
    int bt = blockIdx.x;
    int b = bt / TT, t = bt % TT;
    const float* row = h + ((size_t)b*SS + 3*t + 1) * HDIM;
    __shared__ float sRow[HDIM];
    __shared__ float part[8][ADIM];
    int tid = threadIdx.x;
    sRow[tid] = row[tid];
    sRow[tid + 256] = row[tid + 256];
    __syncthreads();
    int c = tid & 31, g = tid >> 5;
    float a = 0.f;
    for (int k = g*64; k < (g+1)*64; k++) a = fmaf(sRow[k], Wp[(size_t)k*ADIM + c], a);
    part[g][c] = a;
    __syncthreads();
    if (tid < ADIM) {
        float s = bp[tid];
        #pragma unroll
        for (int g2 = 0; g2 < 8; g2++) s += part[g2][tid];
        out[(size_t)bt*ADIM + tid] = s;
    }
}

// ---------------- driver ----------------
extern "C" void kernel_launch(void* const* d_in, const int* in_sizes, int n_in,
                              void* d_out, int out_size)
{
    const int*   timesteps = (const int*)  d_in[0];
    const float* state_0   = (const float*)d_in[1];
    const float* state_1   = (const float*)d_in[2];
    const float* actions   = (const float*)d_in[3];
    const float* time_emb  = (const float*)d_in[4];
    const float* Ws  = (const float*)d_in[5];
    const float* bs  = (const float*)d_in[6];
    const float* Wa  = (const float*)d_in[7];
    const float* ba  = (const float*)d_in[8];
    const float* Wq  = (const float*)d_in[9];
    const float* bq  = (const float*)d_in[10];
    const float* Wk  = (const float*)d_in[11];
    const float* bk  = (const float*)d_in[12];
    const float* Wv  = (const float*)d_in[13];
    const float* bv  = (const float*)d_in[14];
    const float* Wo  = (const float*)d_in[15];
    const float* bo  = (const float*)d_in[16];
    const float* W1  = (const float*)d_in[17];
    const float* b1  = (const float*)d_in[18];
    const float* W2  = (const float*)d_in[19];
    const float* b2  = (const float*)d_in[20];
    const float* ln1_g = (const float*)d_in[21];
    const float* ln1_b = (const float*)d_in[22];
    const float* ln2_g = (const float*)d_in[23];
    const float* ln2_b = (const float*)d_in[24];
    const float* eln_g = (const float*)d_in[25];
    const float* eln_b = (const float*)d_in[26];
    const float* Wp  = (const float*)d_in[27];
    const float* bp  = (const float*)d_in[28];

    float *h, *v, *p0, *p1, *ln1o;
    uint2 *hs, *qs, *ks, *ctxs, *ln1s, *mlps, *ws;
    cudaGetSymbolAddress((void**)&h,    g_h);
    cudaGetSymbolAddress((void**)&v,    g_v);
    cudaGetSymbolAddress((void**)&p0,   g_p0);
    cudaGetSymbolAddress((void**)&p1,   g_p1);
    cudaGetSymbolAddress((void**)&ln1o, g_ln1);
    cudaGetSymbolAddress((void**)&hs,   g_hs);
    cudaGetSymbolAddress((void**)&qs,   g_qs);
    cudaGetSymbolAddress((void**)&ks,   g_ks);
    cudaGetSymbolAddress((void**)&ctxs, g_ctxs);
    cudaGetSymbolAddress((void**)&ln1s, g_ln1s);
    cudaGetSymbolAddress((void**)&mlps, g_mlps);
    cudaGetSymbolAddress((void**)&ws,   g_ws);

    cudaFuncSetAttribute(flash_kernel,
                         cudaFuncAttributeMaxDynamicSharedMemorySize, FLASH_SMEM);
    cudaFuncSetAttribute(tgemm_kernel<128>,
                         cudaFuncAttributeMaxDynamicSharedMemorySize, SM128);
    cudaFuncSetAttribute(tgemm_splitk_kernel,
                         cudaFuncAttributeMaxDynamicSharedMemorySize, SM64);
    cudaFuncSetAttribute(qkv_kernel,
                         cudaFuncAttributeMaxDynamicSharedMemorySize, SM128);

    wsplit_kernel<<<dim3(HDIM/256, NBLK*HDIM/2), 256>>>(Wq, ws + WQ0, HDIM);
    wsplit_kernel<<<dim3(HDIM/256, NBLK*HDIM/2), 256>>>(Wk, ws + WK0, HDIM);
    wsplit_kernel<<<dim3(HDIM/256, NBLK*HDIM/2), 256>>>(Wv, ws + WV0, HDIM);
    wsplit_kernel<<<dim3(HDIM/256, NBLK*HDIM/2), 256>>>(Wo, ws + WO0, HDIM);
    wsplit_kernel<<<dim3(DFF/256,  NBLK*HDIM/2), 256>>>(W1, ws + W10, DFF);
    wsplit_kernel<<<dim3(HDIM/256, NBLK*DFF/2),  256>>>(W2, ws + W20, HDIM);

    embed_kernel<<<BB*SS, 256>>>(timesteps, state_0, state_1, actions, time_emb,
                                 Ws, bs, Wa, ba, eln_g, eln_b, h, hs);

    dim3 gQKV(HDIM/128, MROWS/128, 3);   // (4, 48, 3)
    dim3 gSK (HDIM/64,  MROWS/128, 2);   // (8, 48, 2)
    dim3 gF  (DFF /128, MROWS/128);      // (16, 48)
    dim3 gFl (SS/128, BB*NH);            // (12, 32)

    for (int blk = 0; blk < NBLK; blk++) {
        const uint2* wqs = ws + WQ0 + (size_t)blk*131072;
        const uint2* wks = ws + WK0 + (size_t)blk*131072;
        const uint2* wvs = ws + WV0 + (size_t)blk*131072;
        const uint2* wos = ws + WO0 + (size_t)blk*131072;
        const uint2* w1s = ws + W10 + (size_t)blk*524288;
        const uint2* w2s = ws + W20 + (size_t)blk*524288;
        const float* bq_ = bq + (size_t)blk*HDIM;
        const float* bk_ = bk + (size_t)blk*HDIM;
        const float* bv_ = bv + (size_t)blk*HDIM;
        const float* bo_ = bo + (size_t)blk*HDIM;
        const float* b1_ = b1 + (size_t)blk*DFF;
        const float* b2_ = b2 + (size_t)blk*HDIM;
        const float* g1_ = ln1_g + (size_t)blk*HDIM;
        const float* e1_ = ln1_b + (size_t)blk*HDIM;
        const float* g2_ = ln2_g + (size_t)blk*HDIM;
        const float* e2_ = ln2_b + (size_t)blk*HDIM;

        qkv_kernel<<<gQKV, 256, SM128>>>(hs, wqs, wks, wvs, bq_, bk_, bv_, qs, ks, v);

        flash_kernel<<<gFl, 256, FLASH_SMEM>>>(qs, ks, v, ctxs);

        tgemm_splitk_kernel<<<gSK, 256, SM64>>>(ctxs, wos, p0, p1, HDIM, HDIM);
        ln_sum_kernel<<<MROWS/8, 256>>>(p0, p1, bo_, h, g1_, e1_, ln1o, ln1s);
        tgemm_kernel<128><<<gF, 256, SM128>>>(ln1s, w1s, b1_, nullptr, mlps,
                                              MROWS, DFF, HDIM, EP_GELU_SPLIT);
        tgemm_splitk_kernel<<<gSK, 256, SM64>>>(mlps, w2s, p0, p1, HDIM, DFF);
        ln_sum_kernel<<<MROWS/8, 256>>>(p0, p1, b2_, ln1o, g2_, e2_, h, hs);
    }

    final_kernel<<<BB*TT, 256>>>(h, Wp, bp, (float*)d_out);
}